// round 6
// baseline (speedup 1.0000x reference)
#include <cuda_runtime.h>

#define NB      16384
#define OBS     64
#define HD      128
#define NNB     4
#define NNODE   5
#define NACT    8
#define SLOPE   0.2f
#define BT      16
#define NTHREADS 256
#define NROWS   (BT*NNODE)   // 80
#define ATS     84           // padded stride, mult of 4 -> 16B-aligned quad loads
#define FTS     18           // padded stride for final^T [256][16+pad]

typedef unsigned long long u64;

// ---- smem layout (float offsets) ----
#define OFF_B0  0
#define SZ_B0   (HD*ATS)          // 10752
#define OFF_B1  (OFF_B0 + SZ_B0)
#define SZ_B1   (HD*ATS)          // 10752
#define OFF_FT  (OFF_B1 + SZ_B1)
#define SZ_FT   (2*HD*FTS)        // 4608
#define OFF_SM  (OFF_FT + SZ_FT)
// 0 enc_b1[128], 128 enc_b2[128], 256 gat_a[512], 768 val_b1[128],
// 896 val_w2[128], 1024 pol_b1[128], 1152 pol_w2[1024], 2176 attn[80],
// 2256 val_b2, 2257..2264 pol_b2
#define SZ_SM   2272
#define OFF_ADJ (OFF_SM + SZ_SM)  // 80 ints
#define SMEM_FLOATS (OFF_ADJ + 80)
#define SMEM_BYTES  (SMEM_FLOATS*4)   // 113856 B -> 2 CTAs/SM

__device__ __forceinline__ u64 ffma2(u64 a, u64 b, u64 c) {
    u64 d;
    asm("fma.rn.f32x2 %0, %1, %2, %3;" : "=l"(d) : "l"(a), "l"(b), "l"(c));
    return d;
}
__device__ __forceinline__ u64 pack2(float x, float y) {
    u64 r; asm("mov.b64 %0, {%1, %2};" : "=l"(r) : "f"(x), "f"(y)); return r;
}
__device__ __forceinline__ float2 unpack2(u64 v) {
    float2 r; asm("mov.b64 {%0, %1}, %2;" : "=f"(r.x), "=f"(r.y) : "l"(v)); return r;
}

// Prefetch nfloats of gmem into L2.
__device__ __forceinline__ void pf_l2(const float* p, int tid, int nfloats) {
    for (int off = tid * 32; off < nfloats; off += NTHREADS * 32)
        asm volatile("prefetch.global.L2 [%0];" :: "l"(p + off));
}

// C^T[128][ATS]: C[r][c] = sum_k A[r][k]*W[k][c] (+bias)(relu).
// A^T in smem; W row-major [K][128] in GLOBAL (L2-resident).
// Warp ty owns rows {8ty..8ty+7} (two aligned quads) + {64+2ty, 65+2ty} (pair).
// Lane tx owns columns {tx, tx+32, tx+64, tx+96}. f32x2 lanes = (row, row+1).
template<int K, bool RELU>
__device__ __forceinline__ void gemmT(const float* __restrict__ AT,
                                      const float* __restrict__ Wg,
                                      float* __restrict__ CT,
                                      const float* bias,          // smem or nullptr
                                      const float* __restrict__ pf, int pfN,
                                      int tid)
{
    const int tx = tid & 31, ty = tid >> 5;
    const int rq = ty * 8;          // quad rows base
    const int rp = 64 + ty * 2;     // pair row

    if (pf) pf_l2(pf, tid, pfN);

    u64 acc[5][4];
    #pragma unroll
    for (int p = 0; p < 5; p++)
        #pragma unroll
        for (int j = 0; j < 4; j++) acc[p][j] = 0ull;

    #pragma unroll 4
    for (int k = 0; k < K; k++) {
        const float* wrow = Wg + k*HD + tx;
        const float ws0 = __ldg(wrow),      ws1 = __ldg(wrow + 32),
                    ws2 = __ldg(wrow + 64), ws3 = __ldg(wrow + 96);
        const u64 w0 = pack2(ws0, ws0), w1 = pack2(ws1, ws1),
                  w2 = pack2(ws2, ws2), w3 = pack2(ws3, ws3);
        const float* a = AT + k*ATS;
        const ulonglong2 q0 = *reinterpret_cast<const ulonglong2*>(a + rq);      // rows rq..rq+3
        const ulonglong2 q1 = *reinterpret_cast<const ulonglong2*>(a + rq + 4);  // rows rq+4..rq+7
        const u64        pr = *reinterpret_cast<const u64*>(a + rp);             // rows rp,rp+1
        const u64 a2[5] = {q0.x, q0.y, q1.x, q1.y, pr};
        #pragma unroll
        for (int p = 0; p < 5; p++) {
            acc[p][0] = ffma2(a2[p], w0, acc[p][0]);
            acc[p][1] = ffma2(a2[p], w1, acc[p][1]);
            acc[p][2] = ffma2(a2[p], w2, acc[p][2]);
            acc[p][3] = ffma2(a2[p], w3, acc[p][3]);
        }
    }
    #pragma unroll
    for (int j = 0; j < 4; j++) {
        const int c = tx + 32*j;
        const float b = bias ? bias[c] : 0.f;
        #pragma unroll
        for (int p = 0; p < 5; p++) {
            const int r = (p < 4) ? (rq + 2*p) : rp;
            float2 v = unpack2(acc[p][j]);
            v.x += b; v.y += b;
            if (RELU) { v.x = fmaxf(v.x, 0.f); v.y = fmaxf(v.y, 0.f); }
            *reinterpret_cast<float2*>(CT + c*ATS + r) = v;
        }
    }
}

extern "C" __global__ void __launch_bounds__(NTHREADS, 2)
colight(const float* __restrict__ obs, const float* __restrict__ nobs,
        const int* __restrict__ adj,
        const float* __restrict__ enc_w1, const float* __restrict__ enc_b1,
        const float* __restrict__ enc_w2, const float* __restrict__ enc_b2,
        const float* __restrict__ gat_w, const float* __restrict__ gat_a,
        const float* __restrict__ val_w1, const float* __restrict__ val_b1,
        const float* __restrict__ val_w2, const float* __restrict__ val_b2,
        const float* __restrict__ pol_w1, const float* __restrict__ pol_b1,
        const float* __restrict__ pol_w2, const float* __restrict__ pol_b2,
        float* __restrict__ out)
{
    extern __shared__ float sm[];
    float* B0  = sm + OFF_B0;
    float* B1  = sm + OFF_B1;
    float* FT  = sm + OFF_FT;
    float* sSm = sm + OFF_SM;
    int*   sAdj = reinterpret_cast<int*>(sm + OFF_ADJ);

    const int tid = threadIdx.x;
    const int b0  = blockIdx.x * BT;
    const int wid = tid >> 5, lane = tid & 31;

    // ---------- stage inputs (transposed) + small params ----------
    pf_l2(enc_w1, tid, OBS*HD);
    for (int idx = tid; idx < NROWS*OBS; idx += NTHREADS) {
        const int r = idx >> 6, k = idx & 63;
        const int lb = r / NNODE, n = r - lb*NNODE;
        const float v = (n == 0) ? obs[(size_t)(b0+lb)*OBS + k]
                                 : nobs[((size_t)(b0+lb)*NNB + (n-1))*OBS + k];
        B0[k*ATS + r] = v;
    }
    for (int idx = tid; idx < HD; idx += NTHREADS) {
        sSm[idx]        = enc_b1[idx];
        sSm[128 + idx]  = enc_b2[idx];
        sSm[768 + idx]  = val_b1[idx];
        sSm[896 + idx]  = val_w2[idx];
        sSm[1024 + idx] = pol_b1[idx];
    }
    for (int idx = tid; idx < 512;  idx += NTHREADS) sSm[256 + idx]  = gat_a[idx];
    for (int idx = tid; idx < 1024; idx += NTHREADS) sSm[1152 + idx] = pol_w2[idx];
    if (tid < NROWS) sAdj[tid] = adj[(size_t)b0*NNODE + tid];
    if (tid == 0) sSm[2256] = val_b2[0];
    if (tid < NACT) sSm[2257 + tid] = pol_b2[tid];
    __syncthreads();

    // ---------- encoder ----------
    gemmT<OBS, true >(B0, enc_w1, B1, sSm,        enc_w2, HD*HD, tid);  // hidden^T
    __syncthreads();
    gemmT<HD,  false>(B1, enc_w2, B0, sSm + 128,  gat_w,  HD*HD, tid);  // emb^T
    __syncthreads();

    // ---------- GAT heads ----------
    for (int h = 0; h < 2; h++) {
        const float* pfw = (h == 0) ? (gat_w + HD*HD) : val_w1;
        gemmT<HD, false>(B0, gat_w + h*HD*HD, B1, nullptr, pfw, HD*HD, tid);  // Wh^T
        __syncthreads();

        // attention: warp handles 2 batch elements
        #pragma unroll
        for (int q = 0; q < 2; q++) {
            const int lb = wid*2 + q;
            const float* a1 = sSm + 256 + h*256;
            const float* a2 = a1 + HD;
            float ei = 0.f, ej0 = 0.f, ej1 = 0.f, ej2 = 0.f, ej3 = 0.f, ej4 = 0.f;
            for (int kk = lane; kk < HD; kk += 32) {
                const float w1v = a1[kk], w2v = a2[kk];
                const float* whb = B1 + kk*ATS + lb*NNODE;
                const float v0 = whb[0], v1 = whb[1], v2 = whb[2],
                            v3 = whb[3], v4 = whb[4];
                ei  = fmaf(v0, w1v, ei);
                ej0 = fmaf(v0, w2v, ej0);
                ej1 = fmaf(v1, w2v, ej1);
                ej2 = fmaf(v2, w2v, ej2);
                ej3 = fmaf(v3, w2v, ej3);
                ej4 = fmaf(v4, w2v, ej4);
            }
            #pragma unroll
            for (int off = 16; off > 0; off >>= 1) {
                ei  += __shfl_xor_sync(0xffffffffu, ei,  off);
                ej0 += __shfl_xor_sync(0xffffffffu, ej0, off);
                ej1 += __shfl_xor_sync(0xffffffffu, ej1, off);
                ej2 += __shfl_xor_sync(0xffffffffu, ej2, off);
                ej3 += __shfl_xor_sync(0xffffffffu, ej3, off);
                ej4 += __shfl_xor_sync(0xffffffffu, ej4, off);
            }
            if (lane == 0) {
                float ej[5] = {ej0, ej1, ej2, ej3, ej4};
                float ev[5];
                float m = -1e30f;
                #pragma unroll
                for (int n = 0; n < NNODE; n++) {
                    if (sAdj[lb*NNODE + n] != 0) {
                        float e = ei + ej[n];
                        e = (e >= 0.f) ? e : SLOPE * e;
                        ev[n] = e;
                        m = fmaxf(m, e);
                    } else {
                        ev[n] = -1e30f;
                    }
                }
                float s = 0.f;
                #pragma unroll
                for (int n = 0; n < NNODE; n++) {
                    const float p = (ev[n] > -1e29f) ? __expf(ev[n] - m) : 0.f;
                    ev[n] = p; s += p;
                }
                const float inv = 1.f / s;
                #pragma unroll
                for (int n = 0; n < NNODE; n++) sSm[2176 + lb*NNODE + n] = ev[n] * inv;
            }
        }
        __syncthreads();

        // h_prime row 0 -> FT[(h*128+c)][lb]
        for (int idx = tid; idx < BT*HD; idx += NTHREADS) {
            const int lb = idx >> 7, c = idx & 127;
            const float* at  = sSm + 2176 + lb*NNODE;
            const float* whb = B1 + c*ATS + lb*NNODE;
            float s = at[0] * whb[0];
            s = fmaf(at[1], whb[1], s);
            s = fmaf(at[2], whb[2], s);
            s = fmaf(at[3], whb[3], s);
            s = fmaf(at[4], whb[4], s);
            FT[(h*HD + c)*FTS + lb] = s;
        }
        __syncthreads();
    }

    // ---------- fused value+policy first layers ----------
    // warps 0-3 -> value head, warps 4-7 -> policy head; 16 rows x 128 cols each.
    {
        const int head = wid >> 2;
        const float* Wg = head ? pol_w1 : val_w1;
        const float* bs = head ? (sSm + 1024) : (sSm + 768);
        float* H = head ? (B1 + BT*HD) : B1;   // hv=B1, hp=B1+2048
        const int rbase = (wid & 3) * 4 + (lane >> 4) * 2;  // even rows 0..14
        const int c0 = (lane & 15) * 8;

        u64 acc[2][4];
        #pragma unroll
        for (int r = 0; r < 2; r++)
            #pragma unroll
            for (int j = 0; j < 4; j++) acc[r][j] = 0ull;

        #pragma unroll 4
        for (int k = 0; k < 2*HD; k++) {
            const float2 a = *reinterpret_cast<const float2*>(FT + k*FTS + rbase);
            const u64 a0 = pack2(a.x, a.x), a1 = pack2(a.y, a.y);
            const ulonglong2 w0 = __ldg(reinterpret_cast<const ulonglong2*>(Wg + k*HD + c0));
            const ulonglong2 w1 = __ldg(reinterpret_cast<const ulonglong2*>(Wg + k*HD + c0 + 4));
            acc[0][0] = ffma2(a0, w0.x, acc[0][0]);
            acc[0][1] = ffma2(a0, w0.y, acc[0][1]);
            acc[0][2] = ffma2(a0, w1.x, acc[0][2]);
            acc[0][3] = ffma2(a0, w1.y, acc[0][3]);
            acc[1][0] = ffma2(a1, w0.x, acc[1][0]);
            acc[1][1] = ffma2(a1, w0.y, acc[1][1]);
            acc[1][2] = ffma2(a1, w1.x, acc[1][2]);
            acc[1][3] = ffma2(a1, w1.y, acc[1][3]);
        }
        #pragma unroll
        for (int r = 0; r < 2; r++)
            #pragma unroll
            for (int j = 0; j < 4; j++) {
                const int c = c0 + 2*j;
                float2 v = unpack2(acc[r][j]);
                v.x = fmaxf(v.x + bs[c],     0.f);
                v.y = fmaxf(v.y + bs[c + 1], 0.f);
                *reinterpret_cast<float2*>(H + (rbase + r)*HD + c) = v;
            }
    }
    __syncthreads();

    // ---------- value = hv @ val_w2 + b ----------
    #pragma unroll
    for (int q = 0; q < 2; q++) {
        const int lb = wid*2 + q;
        float s = 0.f;
        for (int kk = lane; kk < HD; kk += 32)
            s = fmaf(B1[lb*HD + kk], sSm[896 + kk], s);
        #pragma unroll
        for (int off = 16; off > 0; off >>= 1) s += __shfl_xor_sync(0xffffffffu, s, off);
        if (lane == 0) out[b0 + lb] = s + sSm[2256];
    }

    // ---------- logits = hp @ pol_w2 + b ----------
    if (tid < BT*NACT) {
        const int lb = tid >> 3, a = tid & 7;
        const float* hp = B1 + BT*HD + lb*HD;
        float s = 0.f;
        for (int kk = 0; kk < HD; kk++)
            s = fmaf(hp[kk], sSm[1152 + kk*NACT + a], s);
        out[NB + (size_t)(b0+lb)*NACT + a] = s + sSm[2257 + a];
    }
}

extern "C" void kernel_launch(void* const* d_in, const int* in_sizes, int n_in,
                              void* d_out, int out_size)
{
    (void)in_sizes; (void)n_in; (void)out_size;
    cudaFuncSetAttribute(colight, cudaFuncAttributeMaxDynamicSharedMemorySize, SMEM_BYTES);
    colight<<<NB/BT, NTHREADS, SMEM_BYTES>>>(
        (const float*)d_in[0],  (const float*)d_in[1],  (const int*)d_in[2],
        (const float*)d_in[3],  (const float*)d_in[4],  (const float*)d_in[5],
        (const float*)d_in[6],  (const float*)d_in[7],  (const float*)d_in[8],
        (const float*)d_in[9],  (const float*)d_in[10], (const float*)d_in[11],
        (const float*)d_in[12], (const float*)d_in[13], (const float*)d_in[14],
        (const float*)d_in[15], (const float*)d_in[16],
        (float*)d_out);
}

// round 7
// speedup vs baseline: 1.0568x; 1.0568x over previous
#include <cuda_runtime.h>

#define NB      16384
#define OBS     64
#define HD      128
#define NNB     4
#define NNODE   5
#define NACT    8
#define SLOPE   0.2f
#define BT      16
#define NTHREADS 256
#define NROWS   (BT*NNODE)   // 80
#define ATS     82           // padded stride for transposed activations
#define FTS     18           // padded stride for final^T [256][16+pad]

typedef unsigned long long u64;

// ---- smem layout (float offsets) ----
#define OFF_B0  0
#define SZ_B0   (HD*ATS)          // 10496
#define OFF_B1  (OFF_B0 + SZ_B0)
#define SZ_B1   (HD*ATS)          // 10496
#define OFF_FT  (OFF_B1 + SZ_B1)
#define SZ_FT   (2*HD*FTS)        // 4608
#define OFF_SM  (OFF_FT + SZ_FT)
// 0 enc_b1[128], 128 enc_b2[128], 256 gat_a[512], 768 val_b1[128],
// 896 val_w2[128], 1024 pol_b1[128], 1152 pol_w2[1024], 2176 attn[80],
// 2256 val_b2, 2257..2264 pol_b2
#define SZ_SM   2272
#define OFF_ADJ (OFF_SM + SZ_SM)  // 80 ints
#define SMEM_FLOATS (OFF_ADJ + 80)
#define SMEM_BYTES  (SMEM_FLOATS*4)   // 111808 B -> 2 CTAs/SM

__device__ __forceinline__ u64 ffma2(u64 a, u64 b, u64 c) {
    u64 d;
    asm("fma.rn.f32x2 %0, %1, %2, %3;" : "=l"(d) : "l"(a), "l"(b), "l"(c));
    return d;
}
__device__ __forceinline__ u64 pack2(float x, float y) {
    u64 r; asm("mov.b64 %0, {%1, %2};" : "=l"(r) : "f"(x), "f"(y)); return r;
}
__device__ __forceinline__ float2 unpack2(u64 v) {
    float2 r; asm("mov.b64 {%0, %1}, %2;" : "=f"(r.x), "=f"(r.y) : "l"(v)); return r;
}

// Prefetch nfloats of gmem into L2 (weights won't fit L1D at 2 CTAs/SM).
__device__ __forceinline__ void pf_l2(const float* p, int tid, int nfloats) {
    for (int off = tid * 32; off < nfloats; off += NTHREADS * 32)
        asm volatile("prefetch.global.L2 [%0];" :: "l"(p + off));
}

// C^T[128][ATS]: C[r][c] = sum_k A[r][k]*W[k][c] (+bias)(relu).
// A^T in smem; W row-major [K][128] in GLOBAL (L2-resident).
// Per-thread tile: 5 row-pairs x 4 cols, f32x2 lanes = (row, row+1).
// Unroll 8: 8 weight LDG.128 in flight per warp to cover L2 latency.
template<int K, bool RELU>
__device__ __forceinline__ void gemmT(const float* __restrict__ AT,
                                      const float* __restrict__ Wg,
                                      float* __restrict__ CT,
                                      const float* bias,          // smem or nullptr
                                      const float* __restrict__ pf, int pfN,
                                      int tid)
{
    const int tx = tid & 31, ty = tid >> 5;
    const int c0 = tx * 4, r0 = ty * 10;

    if (pf) pf_l2(pf, tid, pfN);

    u64 acc[5][4];
    #pragma unroll
    for (int p = 0; p < 5; p++)
        #pragma unroll
        for (int j = 0; j < 4; j++) acc[p][j] = 0ull;

    #pragma unroll 8
    for (int k = 0; k < K; k++) {
        const float4 w4 = __ldg(reinterpret_cast<const float4*>(Wg + k*HD + c0));
        const u64 w0 = pack2(w4.x, w4.x), w1 = pack2(w4.y, w4.y),
                  w2 = pack2(w4.z, w4.z), w3 = pack2(w4.w, w4.w);
        const float* a = AT + k*ATS + r0;
        u64 a2[5];
        #pragma unroll
        for (int p = 0; p < 5; p++)
            a2[p] = *reinterpret_cast<const u64*>(a + 2*p);
        #pragma unroll
        for (int p = 0; p < 5; p++) {
            acc[p][0] = ffma2(a2[p], w0, acc[p][0]);
            acc[p][1] = ffma2(a2[p], w1, acc[p][1]);
            acc[p][2] = ffma2(a2[p], w2, acc[p][2]);
            acc[p][3] = ffma2(a2[p], w3, acc[p][3]);
        }
    }
    #pragma unroll
    for (int j = 0; j < 4; j++) {
        const float b = bias ? bias[c0 + j] : 0.f;
        #pragma unroll
        for (int p = 0; p < 5; p++) {
            float2 v = unpack2(acc[p][j]);
            v.x += b; v.y += b;
            if (RELU) { v.x = fmaxf(v.x, 0.f); v.y = fmaxf(v.y, 0.f); }
            *reinterpret_cast<float2*>(CT + (c0 + j)*ATS + r0 + 2*p) = v;
        }
    }
}

extern "C" __global__ void __launch_bounds__(NTHREADS, 2)
colight(const float* __restrict__ obs, const float* __restrict__ nobs,
        const int* __restrict__ adj,
        const float* __restrict__ enc_w1, const float* __restrict__ enc_b1,
        const float* __restrict__ enc_w2, const float* __restrict__ enc_b2,
        const float* __restrict__ gat_w, const float* __restrict__ gat_a,
        const float* __restrict__ val_w1, const float* __restrict__ val_b1,
        const float* __restrict__ val_w2, const float* __restrict__ val_b2,
        const float* __restrict__ pol_w1, const float* __restrict__ pol_b1,
        const float* __restrict__ pol_w2, const float* __restrict__ pol_b2,
        float* __restrict__ out)
{
    extern __shared__ float sm[];
    float* B0  = sm + OFF_B0;
    float* B1  = sm + OFF_B1;
    float* FT  = sm + OFF_FT;
    float* sSm = sm + OFF_SM;
    int*   sAdj = reinterpret_cast<int*>(sm + OFF_ADJ);

    const int tid = threadIdx.x;
    const int b0  = blockIdx.x * BT;
    const int wid = tid >> 5, lane = tid & 31;

    // ---------- stage inputs (transposed) + small params ----------
    pf_l2(enc_w1, tid, OBS*HD);
    for (int idx = tid; idx < NROWS*OBS; idx += NTHREADS) {
        const int r = idx >> 6, k = idx & 63;
        const int lb = r / NNODE, n = r - lb*NNODE;
        const float v = (n == 0) ? obs[(size_t)(b0+lb)*OBS + k]
                                 : nobs[((size_t)(b0+lb)*NNB + (n-1))*OBS + k];
        B0[k*ATS + r] = v;
    }
    for (int idx = tid; idx < HD; idx += NTHREADS) {
        sSm[idx]        = enc_b1[idx];
        sSm[128 + idx]  = enc_b2[idx];
        sSm[768 + idx]  = val_b1[idx];
        sSm[896 + idx]  = val_w2[idx];
        sSm[1024 + idx] = pol_b1[idx];
    }
    for (int idx = tid; idx < 512;  idx += NTHREADS) sSm[256 + idx]  = gat_a[idx];
    for (int idx = tid; idx < 1024; idx += NTHREADS) sSm[1152 + idx] = pol_w2[idx];
    if (tid < NROWS) sAdj[tid] = adj[(size_t)b0*NNODE + tid];
    if (tid == 0) sSm[2256] = val_b2[0];
    if (tid < NACT) sSm[2257 + tid] = pol_b2[tid];
    __syncthreads();

    // ---------- encoder ----------
    gemmT<OBS, true >(B0, enc_w1, B1, sSm,        enc_w2, HD*HD, tid);  // hidden^T
    __syncthreads();
    gemmT<HD,  false>(B1, enc_w2, B0, sSm + 128,  gat_w,  HD*HD, tid);  // emb^T
    __syncthreads();

    // ---------- GAT heads ----------
    for (int h = 0; h < 2; h++) {
        const float* pfw = (h == 0) ? (gat_w + HD*HD) : val_w1;
        gemmT<HD, false>(B0, gat_w + h*HD*HD, B1, nullptr, pfw, HD*HD, tid);  // Wh^T
        __syncthreads();

        // attention: warp handles 2 batch elements
        #pragma unroll
        for (int q = 0; q < 2; q++) {
            const int lb = wid*2 + q;
            const float* a1 = sSm + 256 + h*256;
            const float* a2 = a1 + HD;
            float ei = 0.f, ej0 = 0.f, ej1 = 0.f, ej2 = 0.f, ej3 = 0.f, ej4 = 0.f;
            for (int kk = lane; kk < HD; kk += 32) {
                const float w1v = a1[kk], w2v = a2[kk];
                const float* whb = B1 + kk*ATS + lb*NNODE;
                const float v0 = whb[0], v1 = whb[1], v2 = whb[2],
                            v3 = whb[3], v4 = whb[4];
                ei  = fmaf(v0, w1v, ei);
                ej0 = fmaf(v0, w2v, ej0);
                ej1 = fmaf(v1, w2v, ej1);
                ej2 = fmaf(v2, w2v, ej2);
                ej3 = fmaf(v3, w2v, ej3);
                ej4 = fmaf(v4, w2v, ej4);
            }
            #pragma unroll
            for (int off = 16; off > 0; off >>= 1) {
                ei  += __shfl_xor_sync(0xffffffffu, ei,  off);
                ej0 += __shfl_xor_sync(0xffffffffu, ej0, off);
                ej1 += __shfl_xor_sync(0xffffffffu, ej1, off);
                ej2 += __shfl_xor_sync(0xffffffffu, ej2, off);
                ej3 += __shfl_xor_sync(0xffffffffu, ej3, off);
                ej4 += __shfl_xor_sync(0xffffffffu, ej4, off);
            }
            if (lane == 0) {
                float ej[5] = {ej0, ej1, ej2, ej3, ej4};
                float ev[5];
                float m = -1e30f;
                #pragma unroll
                for (int n = 0; n < NNODE; n++) {
                    if (sAdj[lb*NNODE + n] != 0) {
                        float e = ei + ej[n];
                        e = (e >= 0.f) ? e : SLOPE * e;
                        ev[n] = e;
                        m = fmaxf(m, e);
                    } else {
                        ev[n] = -1e30f;
                    }
                }
                float s = 0.f;
                #pragma unroll
                for (int n = 0; n < NNODE; n++) {
                    const float p = (ev[n] > -1e29f) ? __expf(ev[n] - m) : 0.f;
                    ev[n] = p; s += p;
                }
                const float inv = 1.f / s;
                #pragma unroll
                for (int n = 0; n < NNODE; n++) sSm[2176 + lb*NNODE + n] = ev[n] * inv;
            }
        }
        __syncthreads();

        // h_prime row 0 -> FT[(h*128+c)][lb]
        for (int idx = tid; idx < BT*HD; idx += NTHREADS) {
            const int lb = idx >> 7, c = idx & 127;
            const float* at  = sSm + 2176 + lb*NNODE;
            const float* whb = B1 + c*ATS + lb*NNODE;
            float s = at[0] * whb[0];
            s = fmaf(at[1], whb[1], s);
            s = fmaf(at[2], whb[2], s);
            s = fmaf(at[3], whb[3], s);
            s = fmaf(at[4], whb[4], s);
            FT[(h*HD + c)*FTS + lb] = s;
        }
        __syncthreads();
    }

    // ---------- fused value+policy first layers ----------
    // warps 0-3 -> value head, warps 4-7 -> policy head; 16 rows x 128 cols each.
    {
        const int head = wid >> 2;
        const float* Wg = head ? pol_w1 : val_w1;
        const float* bs = head ? (sSm + 1024) : (sSm + 768);
        float* H = head ? (B1 + BT*HD) : B1;   // hv=B1, hp=B1+2048
        const int rbase = (wid & 3) * 4 + (lane >> 4) * 2;  // even rows 0..14
        const int c0 = (lane & 15) * 8;

        u64 acc[2][4];
        #pragma unroll
        for (int r = 0; r < 2; r++)
            #pragma unroll
            for (int j = 0; j < 4; j++) acc[r][j] = 0ull;

        #pragma unroll 4
        for (int k = 0; k < 2*HD; k++) {
            const float2 a = *reinterpret_cast<const float2*>(FT + k*FTS + rbase);
            const u64 a0 = pack2(a.x, a.x), a1 = pack2(a.y, a.y);
            const ulonglong2 w0 = __ldg(reinterpret_cast<const ulonglong2*>(Wg + k*HD + c0));
            const ulonglong2 w1 = __ldg(reinterpret_cast<const ulonglong2*>(Wg + k*HD + c0 + 4));
            acc[0][0] = ffma2(a0, w0.x, acc[0][0]);
            acc[0][1] = ffma2(a0, w0.y, acc[0][1]);
            acc[0][2] = ffma2(a0, w1.x, acc[0][2]);
            acc[0][3] = ffma2(a0, w1.y, acc[0][3]);
            acc[1][0] = ffma2(a1, w0.x, acc[1][0]);
            acc[1][1] = ffma2(a1, w0.y, acc[1][1]);
            acc[1][2] = ffma2(a1, w1.x, acc[1][2]);
            acc[1][3] = ffma2(a1, w1.y, acc[1][3]);
        }
        #pragma unroll
        for (int r = 0; r < 2; r++)
            #pragma unroll
            for (int j = 0; j < 4; j++) {
                const int c = c0 + 2*j;
                float2 v = unpack2(acc[r][j]);
                v.x = fmaxf(v.x + bs[c],     0.f);
                v.y = fmaxf(v.y + bs[c + 1], 0.f);
                *reinterpret_cast<float2*>(H + (rbase + r)*HD + c) = v;
            }
    }
    __syncthreads();

    // ---------- value = hv @ val_w2 + b ----------
    #pragma unroll
    for (int q = 0; q < 2; q++) {
        const int lb = wid*2 + q;
        float s = 0.f;
        for (int kk = lane; kk < HD; kk += 32)
            s = fmaf(B1[lb*HD + kk], sSm[896 + kk], s);
        #pragma unroll
        for (int off = 16; off > 0; off >>= 1) s += __shfl_xor_sync(0xffffffffu, s, off);
        if (lane == 0) out[b0 + lb] = s + sSm[2256];
    }

    // ---------- logits = hp @ pol_w2 + b ----------
    if (tid < BT*NACT) {
        const int lb = tid >> 3, a = tid & 7;
        const float* hp = B1 + BT*HD + lb*HD;
        float s = 0.f;
        for (int kk = 0; kk < HD; kk++)
            s = fmaf(hp[kk], sSm[1152 + kk*NACT + a], s);
        out[NB + (size_t)(b0+lb)*NACT + a] = s + sSm[2257 + a];
    }
}

extern "C" void kernel_launch(void* const* d_in, const int* in_sizes, int n_in,
                              void* d_out, int out_size)
{
    (void)in_sizes; (void)n_in; (void)out_size;
    cudaFuncSetAttribute(colight, cudaFuncAttributeMaxDynamicSharedMemorySize, SMEM_BYTES);
    colight<<<NB/BT, NTHREADS, SMEM_BYTES>>>(
        (const float*)d_in[0],  (const float*)d_in[1],  (const int*)d_in[2],
        (const float*)d_in[3],  (const float*)d_in[4],  (const float*)d_in[5],
        (const float*)d_in[6],  (const float*)d_in[7],  (const float*)d_in[8],
        (const float*)d_in[9],  (const float*)d_in[10], (const float*)d_in[11],
        (const float*)d_in[12], (const float*)d_in[13], (const float*)d_in[14],
        (const float*)d_in[15], (const float*)d_in[16],
        (float*)d_out);
}

// round 8
// speedup vs baseline: 1.2759x; 1.2074x over previous
#include <cuda_runtime.h>

#define NB      16384
#define OBS     64
#define HD      128
#define NNB     4
#define NNODE   5
#define NACT    8
#define SLOPE   0.2f
#define BT      16
#define NTHREADS 256
#define NROWS   (BT*NNODE)   // 80
#define ATS     82           // padded stride for transposed activations
#define FTS     18           // padded stride for final^T [256][16+pad]

typedef unsigned long long u64;

// ---- smem layout (float offsets) ----
#define OFF_B0  0
#define SZ_B0   (HD*ATS)          // 10496
#define OFF_B1  (OFF_B0 + SZ_B0)
#define SZ_B1   (HD*ATS)          // 10496
#define OFF_FT  (OFF_B1 + SZ_B1)
#define SZ_FT   (2*HD*FTS)        // 4608
#define OFF_SM  (OFF_FT + SZ_FT)
// 0 enc_b1[128], 128 enc_b2[128], 256 gat_a[512], 768 val_b1[128],
// 896 val_w2[128], 1024 pol_b1[128], 1152 pol_w2[1024], 2176 attn[80],
// 2256 val_b2, 2257..2264 pol_b2
#define SZ_SM   2272
#define OFF_ADJ (OFF_SM + SZ_SM)  // 80 ints
#define SMEM_FLOATS (OFF_ADJ + 80)
#define SMEM_BYTES  (SMEM_FLOATS*4)   // 111808 B -> 2 CTAs/SM

__device__ __forceinline__ u64 ffma2(u64 a, u64 b, u64 c) {
    u64 d;
    asm("fma.rn.f32x2 %0, %1, %2, %3;" : "=l"(d) : "l"(a), "l"(b), "l"(c));
    return d;
}
__device__ __forceinline__ u64 pack2(float x, float y) {
    u64 r; asm("mov.b64 %0, {%1, %2};" : "=l"(r) : "f"(x), "f"(y)); return r;
}
__device__ __forceinline__ float2 unpack2(u64 v) {
    float2 r; asm("mov.b64 {%0, %1}, %2;" : "=f"(r.x), "=f"(r.y) : "l"(v)); return r;
}

// Prefetch nfloats of gmem into L2 (weights won't fit L1D at 2 CTAs/SM).
__device__ __forceinline__ void pf_l2(const float* p, int tid, int nfloats) {
    for (int off = tid * 32; off < nfloats; off += NTHREADS * 32)
        asm volatile("prefetch.global.L2 [%0];" :: "l"(p + off));
}

// C^T[128][ATS]: C[r][c] = sum_k A[r][k]*W[k][c] (+bias)(relu).
// A^T in smem; W row-major [K][128] in GLOBAL (L2-resident).
// Per-thread tile: 5 row-pairs x 4 cols, f32x2 lanes = (row, row+1).
// Unroll 8: 8 weight LDG.128 in flight per warp to cover L2 latency.
template<int K, bool RELU>
__device__ __forceinline__ void gemmT(const float* __restrict__ AT,
                                      const float* __restrict__ Wg,
                                      float* __restrict__ CT,
                                      const float* bias,          // smem or nullptr
                                      const float* __restrict__ pf, int pfN,
                                      int tid)
{
    const int tx = tid & 31, ty = tid >> 5;
    const int c0 = tx * 4, r0 = ty * 10;

    if (pf) pf_l2(pf, tid, pfN);

    u64 acc[5][4];
    #pragma unroll
    for (int p = 0; p < 5; p++)
        #pragma unroll
        for (int j = 0; j < 4; j++) acc[p][j] = 0ull;

    #pragma unroll 8
    for (int k = 0; k < K; k++) {
        const float4 w4 = __ldg(reinterpret_cast<const float4*>(Wg + k*HD + c0));
        const u64 w0 = pack2(w4.x, w4.x), w1 = pack2(w4.y, w4.y),
                  w2 = pack2(w4.z, w4.z), w3 = pack2(w4.w, w4.w);
        const float* a = AT + k*ATS + r0;
        u64 a2[5];
        #pragma unroll
        for (int p = 0; p < 5; p++)
            a2[p] = *reinterpret_cast<const u64*>(a + 2*p);
        #pragma unroll
        for (int p = 0; p < 5; p++) {
            acc[p][0] = ffma2(a2[p], w0, acc[p][0]);
            acc[p][1] = ffma2(a2[p], w1, acc[p][1]);
            acc[p][2] = ffma2(a2[p], w2, acc[p][2]);
            acc[p][3] = ffma2(a2[p], w3, acc[p][3]);
        }
    }
    #pragma unroll
    for (int j = 0; j < 4; j++) {
        const float b = bias ? bias[c0 + j] : 0.f;
        #pragma unroll
        for (int p = 0; p < 5; p++) {
            float2 v = unpack2(acc[p][j]);
            v.x += b; v.y += b;
            if (RELU) { v.x = fmaxf(v.x, 0.f); v.y = fmaxf(v.y, 0.f); }
            *reinterpret_cast<float2*>(CT + (c0 + j)*ATS + r0 + 2*p) = v;
        }
    }
}

extern "C" __global__ void __launch_bounds__(NTHREADS, 2)
colight(const float* __restrict__ obs, const float* __restrict__ nobs,
        const int* __restrict__ adj,
        const float* __restrict__ enc_w1, const float* __restrict__ enc_b1,
        const float* __restrict__ enc_w2, const float* __restrict__ enc_b2,
        const float* __restrict__ gat_w, const float* __restrict__ gat_a,
        const float* __restrict__ val_w1, const float* __restrict__ val_b1,
        const float* __restrict__ val_w2, const float* __restrict__ val_b2,
        const float* __restrict__ pol_w1, const float* __restrict__ pol_b1,
        const float* __restrict__ pol_w2, const float* __restrict__ pol_b2,
        float* __restrict__ out)
{
    extern __shared__ float sm[];
    float* B0  = sm + OFF_B0;
    float* B1  = sm + OFF_B1;
    float* FT  = sm + OFF_FT;
    float* sSm = sm + OFF_SM;
    int*   sAdj = reinterpret_cast<int*>(sm + OFF_ADJ);

    const int tid = threadIdx.x;
    const int b0  = blockIdx.x * BT;
    const int wid = tid >> 5, lane = tid & 31;

    // ---------- stage inputs (transposed) + small params ----------
    pf_l2(enc_w1, tid, OBS*HD);
    for (int idx = tid; idx < NROWS*OBS; idx += NTHREADS) {
        const int r = idx >> 6, k = idx & 63;
        const int lb = r / NNODE, n = r - lb*NNODE;
        const float v = (n == 0) ? obs[(size_t)(b0+lb)*OBS + k]
                                 : nobs[((size_t)(b0+lb)*NNB + (n-1))*OBS + k];
        B0[k*ATS + r] = v;
    }
    for (int idx = tid; idx < HD; idx += NTHREADS) {
        sSm[idx]        = enc_b1[idx];
        sSm[128 + idx]  = enc_b2[idx];
        sSm[768 + idx]  = val_b1[idx];
        sSm[896 + idx]  = val_w2[idx];
        sSm[1024 + idx] = pol_b1[idx];
    }
    for (int idx = tid; idx < 512;  idx += NTHREADS) sSm[256 + idx]  = gat_a[idx];
    for (int idx = tid; idx < 1024; idx += NTHREADS) sSm[1152 + idx] = pol_w2[idx];
    if (tid < NROWS) sAdj[tid] = adj[(size_t)b0*NNODE + tid];
    if (tid == 0) sSm[2256] = val_b2[0];
    if (tid < NACT) sSm[2257 + tid] = pol_b2[tid];
    __syncthreads();

    // ---------- encoder ----------
    gemmT<OBS, true >(B0, enc_w1, B1, sSm,        enc_w2, HD*HD, tid);  // hidden^T
    __syncthreads();
    gemmT<HD,  false>(B1, enc_w2, B0, sSm + 128,  gat_w,  HD*HD, tid);  // emb^T
    __syncthreads();

    // ---------- GAT heads ----------
    for (int h = 0; h < 2; h++) {
        const float* pfw = (h == 0) ? (gat_w + HD*HD) : val_w1;
        gemmT<HD, false>(B0, gat_w + h*HD*HD, B1, nullptr, pfw, HD*HD, tid);  // Wh^T
        __syncthreads();

        // attention: warp handles 2 batch elements
        #pragma unroll
        for (int q = 0; q < 2; q++) {
            const int lb = wid*2 + q;
            const float* a1 = sSm + 256 + h*256;
            const float* a2 = a1 + HD;
            float ei = 0.f, ej0 = 0.f, ej1 = 0.f, ej2 = 0.f, ej3 = 0.f, ej4 = 0.f;
            for (int kk = lane; kk < HD; kk += 32) {
                const float w1v = a1[kk], w2v = a2[kk];
                const float* whb = B1 + kk*ATS + lb*NNODE;
                const float v0 = whb[0], v1 = whb[1], v2 = whb[2],
                            v3 = whb[3], v4 = whb[4];
                ei  = fmaf(v0, w1v, ei);
                ej0 = fmaf(v0, w2v, ej0);
                ej1 = fmaf(v1, w2v, ej1);
                ej2 = fmaf(v2, w2v, ej2);
                ej3 = fmaf(v3, w2v, ej3);
                ej4 = fmaf(v4, w2v, ej4);
            }
            #pragma unroll
            for (int off = 16; off > 0; off >>= 1) {
                ei  += __shfl_xor_sync(0xffffffffu, ei,  off);
                ej0 += __shfl_xor_sync(0xffffffffu, ej0, off);
                ej1 += __shfl_xor_sync(0xffffffffu, ej1, off);
                ej2 += __shfl_xor_sync(0xffffffffu, ej2, off);
                ej3 += __shfl_xor_sync(0xffffffffu, ej3, off);
                ej4 += __shfl_xor_sync(0xffffffffu, ej4, off);
            }
            if (lane == 0) {
                float ej[5] = {ej0, ej1, ej2, ej3, ej4};
                float ev[5];
                float m = -1e30f;
                #pragma unroll
                for (int n = 0; n < NNODE; n++) {
                    if (sAdj[lb*NNODE + n] != 0) {
                        float e = ei + ej[n];
                        e = (e >= 0.f) ? e : SLOPE * e;
                        ev[n] = e;
                        m = fmaxf(m, e);
                    } else {
                        ev[n] = -1e30f;
                    }
                }
                float s = 0.f;
                #pragma unroll
                for (int n = 0; n < NNODE; n++) {
                    const float p = (ev[n] > -1e29f) ? __expf(ev[n] - m) : 0.f;
                    ev[n] = p; s += p;
                }
                const float inv = 1.f / s;
                #pragma unroll
                for (int n = 0; n < NNODE; n++) sSm[2176 + lb*NNODE + n] = ev[n] * inv;
            }
        }
        __syncthreads();

        // h_prime row 0 -> FT[(h*128+c)][lb]
        for (int idx = tid; idx < BT*HD; idx += NTHREADS) {
            const int lb = idx >> 7, c = idx & 127;
            const float* at  = sSm + 2176 + lb*NNODE;
            const float* whb = B1 + c*ATS + lb*NNODE;
            float s = at[0] * whb[0];
            s = fmaf(at[1], whb[1], s);
            s = fmaf(at[2], whb[2], s);
            s = fmaf(at[3], whb[3], s);
            s = fmaf(at[4], whb[4], s);
            FT[(h*HD + c)*FTS + lb] = s;
        }
        __syncthreads();
    }

    // ---------- fused value+policy first layers (restructured) ----------
    // head = wid>>2; each warp owns a DISTINCT 32-col slice of its head's W
    // (kills 4x W redundancy -> ~4x less unique L1 traffic in this phase).
    // Lane: colquad q = lane&7 -> cols cb+4q..+3; rowset s = lane>>3 ->
    // rowpairs (2s,2s+1) and (2s+8,2s+9). acc[2][4] u64 = 16 f32.
    {
        const int head = wid >> 2;
        const float* Wg = head ? pol_w1 : val_w1;
        const float* bs = head ? (sSm + 1024) : (sSm + 768);
        float* H = head ? (B1 + BT*HD) : B1;   // hv=B1, hp=B1+2048
        const int cb = (wid & 3) * 32;
        const int q  = lane & 7;
        const int s  = lane >> 3;
        const int c0 = cb + q * 4;

        u64 acc[2][4];
        #pragma unroll
        for (int r = 0; r < 2; r++)
            #pragma unroll
            for (int j = 0; j < 4; j++) acc[r][j] = 0ull;

        #pragma unroll 8
        for (int k = 0; k < 2*HD; k++) {
            const float4 w4 = __ldg(reinterpret_cast<const float4*>(Wg + k*HD + c0));
            const u64 w0 = pack2(w4.x, w4.x), w1 = pack2(w4.y, w4.y),
                      w2 = pack2(w4.z, w4.z), w3 = pack2(w4.w, w4.w);
            const float* f = FT + k*FTS;
            const u64 a0 = *reinterpret_cast<const u64*>(f + 2*s);      // rows 2s,2s+1
            const u64 a1 = *reinterpret_cast<const u64*>(f + 2*s + 8);  // rows 2s+8,2s+9
            acc[0][0] = ffma2(a0, w0, acc[0][0]);
            acc[0][1] = ffma2(a0, w1, acc[0][1]);
            acc[0][2] = ffma2(a0, w2, acc[0][2]);
            acc[0][3] = ffma2(a0, w3, acc[0][3]);
            acc[1][0] = ffma2(a1, w0, acc[1][0]);
            acc[1][1] = ffma2(a1, w1, acc[1][1]);
            acc[1][2] = ffma2(a1, w2, acc[1][2]);
            acc[1][3] = ffma2(a1, w3, acc[1][3]);
        }
        const float4 bb = *reinterpret_cast<const float4*>(bs + c0);
        #pragma unroll
        for (int p = 0; p < 2; p++) {
            const int r = 2*s + p*8;
            float2 v0 = unpack2(acc[p][0]);
            float2 v1 = unpack2(acc[p][1]);
            float2 v2 = unpack2(acc[p][2]);
            float2 v3 = unpack2(acc[p][3]);
            float4 lo, hi;
            lo.x = fmaxf(v0.x + bb.x, 0.f); hi.x = fmaxf(v0.y + bb.x, 0.f);
            lo.y = fmaxf(v1.x + bb.y, 0.f); hi.y = fmaxf(v1.y + bb.y, 0.f);
            lo.z = fmaxf(v2.x + bb.z, 0.f); hi.z = fmaxf(v2.y + bb.z, 0.f);
            lo.w = fmaxf(v3.x + bb.w, 0.f); hi.w = fmaxf(v3.y + bb.w, 0.f);
            *reinterpret_cast<float4*>(H + r*HD + c0)       = lo;  // row r
            *reinterpret_cast<float4*>(H + (r+1)*HD + c0)   = hi;  // row r+1
        }
    }
    __syncthreads();

    // ---------- value = hv @ val_w2 + b ----------
    #pragma unroll
    for (int q = 0; q < 2; q++) {
        const int lb = wid*2 + q;
        float s = 0.f;
        for (int kk = lane; kk < HD; kk += 32)
            s = fmaf(B1[lb*HD + kk], sSm[896 + kk], s);
        #pragma unroll
        for (int off = 16; off > 0; off >>= 1) s += __shfl_xor_sync(0xffffffffu, s, off);
        if (lane == 0) out[b0 + lb] = s + sSm[2256];
    }

    // ---------- logits = hp @ pol_w2 + b ----------
    if (tid < BT*NACT) {
        const int lb = tid >> 3, a = tid & 7;
        const float* hp = B1 + BT*HD + lb*HD;
        float s = 0.f;
        for (int kk = 0; kk < HD; kk++)
            s = fmaf(hp[kk], sSm[1152 + kk*NACT + a], s);
        out[NB + (size_t)(b0+lb)*NACT + a] = s + sSm[2257 + a];
    }
}

extern "C" void kernel_launch(void* const* d_in, const int* in_sizes, int n_in,
                              void* d_out, int out_size)
{
    (void)in_sizes; (void)n_in; (void)out_size;
    cudaFuncSetAttribute(colight, cudaFuncAttributeMaxDynamicSharedMemorySize, SMEM_BYTES);
    colight<<<NB/BT, NTHREADS, SMEM_BYTES>>>(
        (const float*)d_in[0],  (const float*)d_in[1],  (const int*)d_in[2],
        (const float*)d_in[3],  (const float*)d_in[4],  (const float*)d_in[5],
        (const float*)d_in[6],  (const float*)d_in[7],  (const float*)d_in[8],
        (const float*)d_in[9],  (const float*)d_in[10], (const float*)d_in[11],
        (const float*)d_in[12], (const float*)d_in[13], (const float*)d_in[14],
        (const float*)d_in[15], (const float*)d_in[16],
        (float*)d_out);
}

// round 9
// speedup vs baseline: 1.2876x; 1.0092x over previous
#include <cuda_runtime.h>

#define NB      16384
#define OBS     64
#define HD      128
#define NNB     4
#define NNODE   5
#define NACT    8
#define SLOPE   0.2f
#define BT      16
#define NTHREADS 256
#define NROWS   (BT*NNODE)   // 80
#define ATS     82           // padded stride for transposed activations
#define FTS     18           // padded stride for final^T [256][16+pad]

typedef unsigned long long u64;

// ---- smem layout (float offsets) ----
#define OFF_B0  0
#define SZ_B0   (HD*ATS)          // 10496
#define OFF_B1  (OFF_B0 + SZ_B0)
#define SZ_B1   (HD*ATS)          // 10496
#define OFF_FT  (OFF_B1 + SZ_B1)
#define SZ_FT   (2*HD*FTS)        // 4608
#define OFF_SM  (OFF_FT + SZ_FT)
// 0 enc_b1[128], 128 enc_b2[128], 256 gat_a[512], 768 val_b1[128],
// 896 val_w2[128], 1024 pol_b1[128], 1152 pol_w2[1024], 2176 attn[80],
// 2256 val_b2, 2257..2264 pol_b2
#define SZ_SM   2272
#define OFF_ADJ (OFF_SM + SZ_SM)  // 80 ints
#define SMEM_FLOATS (OFF_ADJ + 80)
#define SMEM_BYTES  (SMEM_FLOATS*4)   // 111808 B -> 2 CTAs/SM

__device__ __forceinline__ u64 ffma2(u64 a, u64 b, u64 c) {
    u64 d;
    asm("fma.rn.f32x2 %0, %1, %2, %3;" : "=l"(d) : "l"(a), "l"(b), "l"(c));
    return d;
}
__device__ __forceinline__ u64 pack2(float x, float y) {
    u64 r; asm("mov.b64 %0, {%1, %2};" : "=l"(r) : "f"(x), "f"(y)); return r;
}
__device__ __forceinline__ float2 unpack2(u64 v) {
    float2 r; asm("mov.b64 {%0, %1}, %2;" : "=f"(r.x), "=f"(r.y) : "l"(v)); return r;
}

// Prefetch nfloats of gmem into L2 (weights won't fit L1D at 2 CTAs/SM).
__device__ __forceinline__ void pf_l2(const float* p, int tid, int nfloats) {
    for (int off = tid * 32; off < nfloats; off += NTHREADS * 32)
        asm volatile("prefetch.global.L2 [%0];" :: "l"(p + off));
}

// C^T[128][ATS]: C[r][c] = sum_k A[r][k]*W[k][c] (+bias)(relu).
// A^T in smem; W row-major [K][128] in GLOBAL (L2-resident).
// Warp tile: 20 rows x 64 cols (4 row-groups x 2 col-halves = 8 warps).
// Lane (g = lane>>4, x = lane&15): 5 row-pairs (rows R0+10g+2p) x 4 cols
// (c0 = cb + 4x). Warp's W span = 256B = 2 L1 lines (vs 4 before).
template<int K, bool RELU>
__device__ __forceinline__ void gemmT(const float* __restrict__ AT,
                                      const float* __restrict__ Wg,
                                      float* __restrict__ CT,
                                      const float* bias,          // smem or nullptr
                                      const float* __restrict__ pf, int pfN,
                                      int tid)
{
    const int tx = tid & 31, ty = tid >> 5;
    const int g  = tx >> 4, x = tx & 15;
    const int cb = (ty & 1) * 64;        // column half
    const int R0 = (ty >> 1) * 20;       // row group
    const int c0 = cb + x * 4;
    const int r0 = R0 + 10 * g;          // 5 row-pairs: r0+2p

    if (pf) pf_l2(pf, tid, pfN);

    u64 acc[5][4];
    #pragma unroll
    for (int p = 0; p < 5; p++)
        #pragma unroll
        for (int j = 0; j < 4; j++) acc[p][j] = 0ull;

    #pragma unroll 8
    for (int k = 0; k < K; k++) {
        const float4 w4 = __ldg(reinterpret_cast<const float4*>(Wg + k*HD + c0));
        const u64 w0 = pack2(w4.x, w4.x), w1 = pack2(w4.y, w4.y),
                  w2 = pack2(w4.z, w4.z), w3 = pack2(w4.w, w4.w);
        const float* a = AT + k*ATS + r0;
        u64 a2[5];
        #pragma unroll
        for (int p = 0; p < 5; p++)
            a2[p] = *reinterpret_cast<const u64*>(a + 2*p);
        #pragma unroll
        for (int p = 0; p < 5; p++) {
            acc[p][0] = ffma2(a2[p], w0, acc[p][0]);
            acc[p][1] = ffma2(a2[p], w1, acc[p][1]);
            acc[p][2] = ffma2(a2[p], w2, acc[p][2]);
            acc[p][3] = ffma2(a2[p], w3, acc[p][3]);
        }
    }
    #pragma unroll
    for (int j = 0; j < 4; j++) {
        const float b = bias ? bias[c0 + j] : 0.f;
        #pragma unroll
        for (int p = 0; p < 5; p++) {
            float2 v = unpack2(acc[p][j]);
            v.x += b; v.y += b;
            if (RELU) { v.x = fmaxf(v.x, 0.f); v.y = fmaxf(v.y, 0.f); }
            *reinterpret_cast<float2*>(CT + (c0 + j)*ATS + r0 + 2*p) = v;
        }
    }
}

extern "C" __global__ void __launch_bounds__(NTHREADS, 2)
colight(const float* __restrict__ obs, const float* __restrict__ nobs,
        const int* __restrict__ adj,
        const float* __restrict__ enc_w1, const float* __restrict__ enc_b1,
        const float* __restrict__ enc_w2, const float* __restrict__ enc_b2,
        const float* __restrict__ gat_w, const float* __restrict__ gat_a,
        const float* __restrict__ val_w1, const float* __restrict__ val_b1,
        const float* __restrict__ val_w2, const float* __restrict__ val_b2,
        const float* __restrict__ pol_w1, const float* __restrict__ pol_b1,
        const float* __restrict__ pol_w2, const float* __restrict__ pol_b2,
        float* __restrict__ out)
{
    extern __shared__ float sm[];
    float* B0  = sm + OFF_B0;
    float* B1  = sm + OFF_B1;
    float* FT  = sm + OFF_FT;
    float* sSm = sm + OFF_SM;
    int*   sAdj = reinterpret_cast<int*>(sm + OFF_ADJ);

    const int tid = threadIdx.x;
    const int b0  = blockIdx.x * BT;
    const int wid = tid >> 5, lane = tid & 31;

    // ---------- stage inputs (transposed) + small params ----------
    pf_l2(enc_w1, tid, OBS*HD);
    for (int idx = tid; idx < NROWS*OBS; idx += NTHREADS) {
        const int r = idx >> 6, k = idx & 63;
        const int lb = r / NNODE, n = r - lb*NNODE;
        const float v = (n == 0) ? obs[(size_t)(b0+lb)*OBS + k]
                                 : nobs[((size_t)(b0+lb)*NNB + (n-1))*OBS + k];
        B0[k*ATS + r] = v;
    }
    for (int idx = tid; idx < HD; idx += NTHREADS) {
        sSm[idx]        = enc_b1[idx];
        sSm[128 + idx]  = enc_b2[idx];
        sSm[768 + idx]  = val_b1[idx];
        sSm[896 + idx]  = val_w2[idx];
        sSm[1024 + idx] = pol_b1[idx];
    }
    for (int idx = tid; idx < 512;  idx += NTHREADS) sSm[256 + idx]  = gat_a[idx];
    for (int idx = tid; idx < 1024; idx += NTHREADS) sSm[1152 + idx] = pol_w2[idx];
    if (tid < NROWS) sAdj[tid] = adj[(size_t)b0*NNODE + tid];
    if (tid == 0) sSm[2256] = val_b2[0];
    if (tid < NACT) sSm[2257 + tid] = pol_b2[tid];
    __syncthreads();

    // ---------- encoder ----------
    gemmT<OBS, true >(B0, enc_w1, B1, sSm,        enc_w2, HD*HD, tid);  // hidden^T
    __syncthreads();
    gemmT<HD,  false>(B1, enc_w2, B0, sSm + 128,  gat_w,  HD*HD, tid);  // emb^T
    __syncthreads();

    // ---------- GAT heads ----------
    for (int h = 0; h < 2; h++) {
        const float* pfw = (h == 0) ? (gat_w + HD*HD) : val_w1;
        gemmT<HD, false>(B0, gat_w + h*HD*HD, B1, nullptr, pfw, HD*HD, tid);  // Wh^T
        __syncthreads();

        // attention: warp handles 2 batch elements
        #pragma unroll
        for (int q = 0; q < 2; q++) {
            const int lb = wid*2 + q;
            const float* a1 = sSm + 256 + h*256;
            const float* a2 = a1 + HD;
            float ei = 0.f, ej0 = 0.f, ej1 = 0.f, ej2 = 0.f, ej3 = 0.f, ej4 = 0.f;
            for (int kk = lane; kk < HD; kk += 32) {
                const float w1v = a1[kk], w2v = a2[kk];
                const float* whb = B1 + kk*ATS + lb*NNODE;
                const float v0 = whb[0], v1 = whb[1], v2 = whb[2],
                            v3 = whb[3], v4 = whb[4];
                ei  = fmaf(v0, w1v, ei);
                ej0 = fmaf(v0, w2v, ej0);
                ej1 = fmaf(v1, w2v, ej1);
                ej2 = fmaf(v2, w2v, ej2);
                ej3 = fmaf(v3, w2v, ej3);
                ej4 = fmaf(v4, w2v, ej4);
            }
            #pragma unroll
            for (int off = 16; off > 0; off >>= 1) {
                ei  += __shfl_xor_sync(0xffffffffu, ei,  off);
                ej0 += __shfl_xor_sync(0xffffffffu, ej0, off);
                ej1 += __shfl_xor_sync(0xffffffffu, ej1, off);
                ej2 += __shfl_xor_sync(0xffffffffu, ej2, off);
                ej3 += __shfl_xor_sync(0xffffffffu, ej3, off);
                ej4 += __shfl_xor_sync(0xffffffffu, ej4, off);
            }
            if (lane == 0) {
                float ej[5] = {ej0, ej1, ej2, ej3, ej4};
                float ev[5];
                float m = -1e30f;
                #pragma unroll
                for (int n = 0; n < NNODE; n++) {
                    if (sAdj[lb*NNODE + n] != 0) {
                        float e = ei + ej[n];
                        e = (e >= 0.f) ? e : SLOPE * e;
                        ev[n] = e;
                        m = fmaxf(m, e);
                    } else {
                        ev[n] = -1e30f;
                    }
                }
                float s = 0.f;
                #pragma unroll
                for (int n = 0; n < NNODE; n++) {
                    const float p = (ev[n] > -1e29f) ? __expf(ev[n] - m) : 0.f;
                    ev[n] = p; s += p;
                }
                const float inv = 1.f / s;
                #pragma unroll
                for (int n = 0; n < NNODE; n++) sSm[2176 + lb*NNODE + n] = ev[n] * inv;
            }
        }
        __syncthreads();

        // h_prime row 0 -> FT[(h*128+c)][lb]
        for (int idx = tid; idx < BT*HD; idx += NTHREADS) {
            const int lb = idx >> 7, c = idx & 127;
            const float* at  = sSm + 2176 + lb*NNODE;
            const float* whb = B1 + c*ATS + lb*NNODE;
            float s = at[0] * whb[0];
            s = fmaf(at[1], whb[1], s);
            s = fmaf(at[2], whb[2], s);
            s = fmaf(at[3], whb[3], s);
            s = fmaf(at[4], whb[4], s);
            FT[(h*HD + c)*FTS + lb] = s;
        }
        __syncthreads();
    }

    // ---------- fused value+policy first layers ----------
    // head = wid>>2; each warp owns a DISTINCT 32-col slice of its head's W.
    {
        const int head = wid >> 2;
        const float* Wg = head ? pol_w1 : val_w1;
        const float* bs = head ? (sSm + 1024) : (sSm + 768);
        float* H = head ? (B1 + BT*HD) : B1;   // hv=B1, hp=B1+2048
        const int cb = (wid & 3) * 32;
        const int q  = lane & 7;
        const int s  = lane >> 3;
        const int c0 = cb + q * 4;

        u64 acc[2][4];
        #pragma unroll
        for (int r = 0; r < 2; r++)
            #pragma unroll
            for (int j = 0; j < 4; j++) acc[r][j] = 0ull;

        #pragma unroll 8
        for (int k = 0; k < 2*HD; k++) {
            const float4 w4 = __ldg(reinterpret_cast<const float4*>(Wg + k*HD + c0));
            const u64 w0 = pack2(w4.x, w4.x), w1 = pack2(w4.y, w4.y),
                      w2 = pack2(w4.z, w4.z), w3 = pack2(w4.w, w4.w);
            const float* f = FT + k*FTS;
            const u64 a0 = *reinterpret_cast<const u64*>(f + 2*s);      // rows 2s,2s+1
            const u64 a1 = *reinterpret_cast<const u64*>(f + 2*s + 8);  // rows 2s+8,2s+9
            acc[0][0] = ffma2(a0, w0, acc[0][0]);
            acc[0][1] = ffma2(a0, w1, acc[0][1]);
            acc[0][2] = ffma2(a0, w2, acc[0][2]);
            acc[0][3] = ffma2(a0, w3, acc[0][3]);
            acc[1][0] = ffma2(a1, w0, acc[1][0]);
            acc[1][1] = ffma2(a1, w1, acc[1][1]);
            acc[1][2] = ffma2(a1, w2, acc[1][2]);
            acc[1][3] = ffma2(a1, w3, acc[1][3]);
        }
        const float4 bb = *reinterpret_cast<const float4*>(bs + c0);
        #pragma unroll
        for (int p = 0; p < 2; p++) {
            const int r = 2*s + p*8;
            float2 v0 = unpack2(acc[p][0]);
            float2 v1 = unpack2(acc[p][1]);
            float2 v2 = unpack2(acc[p][2]);
            float2 v3 = unpack2(acc[p][3]);
            float4 lo, hi;
            lo.x = fmaxf(v0.x + bb.x, 0.f); hi.x = fmaxf(v0.y + bb.x, 0.f);
            lo.y = fmaxf(v1.x + bb.y, 0.f); hi.y = fmaxf(v1.y + bb.y, 0.f);
            lo.z = fmaxf(v2.x + bb.z, 0.f); hi.z = fmaxf(v2.y + bb.z, 0.f);
            lo.w = fmaxf(v3.x + bb.w, 0.f); hi.w = fmaxf(v3.y + bb.w, 0.f);
            *reinterpret_cast<float4*>(H + r*HD + c0)       = lo;  // row r
            *reinterpret_cast<float4*>(H + (r+1)*HD + c0)   = hi;  // row r+1
        }
    }
    __syncthreads();

    // ---------- value = hv @ val_w2 + b ----------
    #pragma unroll
    for (int q = 0; q < 2; q++) {
        const int lb = wid*2 + q;
        float s = 0.f;
        for (int kk = lane; kk < HD; kk += 32)
            s = fmaf(B1[lb*HD + kk], sSm[896 + kk], s);
        #pragma unroll
        for (int off = 16; off > 0; off >>= 1) s += __shfl_xor_sync(0xffffffffu, s, off);
        if (lane == 0) out[b0 + lb] = s + sSm[2256];
    }

    // ---------- logits = hp @ pol_w2 + b ----------
    if (tid < BT*NACT) {
        const int lb = tid >> 3, a = tid & 7;
        const float* hp = B1 + BT*HD + lb*HD;
        float s = 0.f;
        for (int kk = 0; kk < HD; kk++)
            s = fmaf(hp[kk], sSm[1152 + kk*NACT + a], s);
        out[NB + (size_t)(b0+lb)*NACT + a] = s + sSm[2257 + a];
    }
}

extern "C" void kernel_launch(void* const* d_in, const int* in_sizes, int n_in,
                              void* d_out, int out_size)
{
    (void)in_sizes; (void)n_in; (void)out_size;
    cudaFuncSetAttribute(colight, cudaFuncAttributeMaxDynamicSharedMemorySize, SMEM_BYTES);
    colight<<<NB/BT, NTHREADS, SMEM_BYTES>>>(
        (const float*)d_in[0],  (const float*)d_in[1],  (const int*)d_in[2],
        (const float*)d_in[3],  (const float*)d_in[4],  (const float*)d_in[5],
        (const float*)d_in[6],  (const float*)d_in[7],  (const float*)d_in[8],
        (const float*)d_in[9],  (const float*)d_in[10], (const float*)d_in[11],
        (const float*)d_in[12], (const float*)d_in[13], (const float*)d_in[14],
        (const float*)d_in[15], (const float*)d_in[16],
        (float*)d_out);
}

// round 11
// speedup vs baseline: 1.5612x; 1.2125x over previous
#include <cuda_runtime.h>

typedef unsigned int u32;
typedef unsigned long long u64;

#define NB 16384
#define OBS 64
#define HD 128
#define NNODE 5
#define NACT 8
#define SLOPE 0.2f
#define BT 16
#define NTHREADS 256

#define S_A 68      // u32 stride of A planes [80][S_A]; 68%32==4 -> conflict-free frags
#define FTS 18

// ---- smem layout (4-byte word offsets) ----
#define OFF_AH 0        // A hi plane, u32[80*68]
#define OFF_AL 5440     // A lo plane
#define OFF_FT 10880    // FT fp32 [256][FTS]
#define OFF_ST 15488    // sT fp32 [128][FTS]
#define OFF_SM 17792    // small params (2784 floats):
// 0 enc_b1[128],128 enc_b2[128],256 gat_a[512],768 val_b1[128],896 val_w2[128],
// 1024 pol_b1[128],1152 pol_w2[1024],2176 attn[80],2256 val_b2,2257 pol_b2[8],2272 g[512]
#define OFF_ADJ 20576   // 80 ints
#define SMEM_FLOATS 20656
#define SMEM_BYTES (SMEM_FLOATS*4)   // 82624 B -> 2 CTAs/SM

// pack two f32 -> bf16x2, first arg in LOW half
#define CVTP(r, a, b) asm("cvt.rn.bf16x2.f32 %0, %1, %2;" : "=r"(r) : "f"(b), "f"(a))

__device__ __forceinline__ void split2(float v0, float v1, u32& hi, u32& lo) {
    CVTP(hi, v0, v1);
    const float r0 = v0 - __uint_as_float(hi << 16);
    const float r1 = v1 - __uint_as_float(hi & 0xffff0000u);
    CVTP(lo, r0, r1);
}

#define MMA(d, a0, a1, a2, a3, b0, b1) \
    asm volatile("mma.sync.aligned.m16n8k16.row.col.f32.bf16.bf16.f32 " \
        "{%0,%1,%2,%3}, {%4,%5,%6,%7}, {%8,%9}, {%0,%1,%2,%3};" \
        : "+f"((d)[0]), "+f"((d)[1]), "+f"((d)[2]), "+f"((d)[3]) \
        : "r"(a0), "r"(a1), "r"(a2), "r"(a3), "r"(b0), "r"(b1))

// FFMA2 helpers (scalar gemm paths)
__device__ __forceinline__ u64 ffma2(u64 a, u64 b, u64 c) {
    u64 d; asm("fma.rn.f32x2 %0, %1, %2, %3;" : "=l"(d) : "l"(a), "l"(b), "l"(c)); return d;
}
__device__ __forceinline__ u64 pack2(float x, float y) {
    u64 r; asm("mov.b64 %0, {%1, %2};" : "=l"(r) : "f"(x), "f"(y)); return r;
}
__device__ __forceinline__ float2 unpack2(u64 v) {
    float2 r; asm("mov.b64 {%0, %1}, %2;" : "=f"(r.x), "=f"(r.y) : "l"(v)); return r;
}
__device__ __forceinline__ void pf_l2(const float* p, int tid, int nf) {
    for (int off = tid * 32; off < nf; off += NTHREADS * 32)
        asm volatile("prefetch.global.L2 [%0];" :: "l"(p + off));
}

// Split-bf16 MMA gemm: acc[5 m-tiles][2 n-tiles][4] += A(80xK) @ W(Kx128)
// A planes in smem; W fp32 in gmem, fragments built on the fly.
__device__ __forceinline__ void run_gemm(float acc[5][2][4],
                                         const u32* __restrict__ AH,
                                         const u32* __restrict__ AL,
                                         const float* __restrict__ Wg,
                                         int lane, int n0, int KS)
{
    const int ar = lane >> 2, ac = lane & 3;
    for (int s = 0; s < KS; s++) {
        const int kb = s * 16;
        u32 bh[2][2], bl[2][2];
        #pragma unroll
        for (int j = 0; j < 2; j++) {
            const int wn = n0 + 8 * j + ar;
            const int wk = kb + (ac << 1);
            const float* p = Wg + (size_t)wk * HD + wn;
            const float w00 = __ldg(p),          w01 = __ldg(p + HD);
            const float w10 = __ldg(p + 8 * HD), w11 = __ldg(p + 9 * HD);
            split2(w00, w01, bh[j][0], bl[j][0]);
            split2(w10, w11, bh[j][1], bl[j][1]);
        }
        #pragma unroll
        for (int i = 0; i < 5; i++) {
            const u32* pa = AH + (i * 16 + ar) * S_A + s * 8 + ac;
            const u32* pl = AL + (i * 16 + ar) * S_A + s * 8 + ac;
            const u32 a0 = pa[0], a1 = pa[8 * S_A], a2 = pa[4], a3 = pa[8 * S_A + 4];
            const u32 l0 = pl[0], l1 = pl[8 * S_A], l2 = pl[4], l3 = pl[8 * S_A + 4];
            #pragma unroll
            for (int j = 0; j < 2; j++) {
                MMA(acc[i][j], a0, a1, a2, a3, bh[j][0], bh[j][1]);
                MMA(acc[i][j], a0, a1, a2, a3, bl[j][0], bl[j][1]);
                MMA(acc[i][j], l0, l1, l2, l3, bh[j][0], bh[j][1]);
            }
        }
    }
}

// D-frags -> bf16 hi/lo A planes (+bias, optional relu)
__device__ __forceinline__ void store_split(const float acc[5][2][4],
                                            u32* __restrict__ AH, u32* __restrict__ AL,
                                            const float* __restrict__ bias, bool relu,
                                            int lane, int n0)
{
    const int ar = lane >> 2, ac2 = (lane & 3) << 1;
    #pragma unroll
    for (int i = 0; i < 5; i++)
        #pragma unroll
        for (int j = 0; j < 2; j++) {
            const int c = n0 + 8 * j + ac2;
            const float b0v = bias[c], b1v = bias[c + 1];
            float v0 = acc[i][j][0] + b0v, v1 = acc[i][j][1] + b1v;
            if (relu) { v0 = fmaxf(v0, 0.f); v1 = fmaxf(v1, 0.f); }
            u32 hi, lo; split2(v0, v1, hi, lo);
            const int r0 = i * 16 + ar;
            AH[r0 * S_A + (c >> 1)] = hi;
            AL[r0 * S_A + (c >> 1)] = lo;
            float v2 = acc[i][j][2] + b0v, v3 = acc[i][j][3] + b1v;
            if (relu) { v2 = fmaxf(v2, 0.f); v3 = fmaxf(v3, 0.f); }
            split2(v2, v3, hi, lo);
            AH[(r0 + 8) * S_A + (c >> 1)] = hi;
            AL[(r0 + 8) * S_A + (c >> 1)] = lo;
        }
}

// unpack emb element pair (k=2*k2, 2*k2+1) from planes
__device__ __forceinline__ void emb_pair(u32 h, u32 l, float& e0, float& e1) {
    e0 = __uint_as_float(h << 16) + __uint_as_float(l << 16);
    e1 = __uint_as_float(h & 0xffff0000u) + __uint_as_float(l & 0xffff0000u);
}

extern "C" __global__ void __launch_bounds__(NTHREADS, 2)
colight(const float* __restrict__ obs, const float* __restrict__ nobs,
        const int* __restrict__ adj,
        const float* __restrict__ enc_w1, const float* __restrict__ enc_b1,
        const float* __restrict__ enc_w2, const float* __restrict__ enc_b2,
        const float* __restrict__ gat_w, const float* __restrict__ gat_a,
        const float* __restrict__ val_w1, const float* __restrict__ val_b1,
        const float* __restrict__ val_w2, const float* __restrict__ val_b2,
        const float* __restrict__ pol_w1, const float* __restrict__ pol_b1,
        const float* __restrict__ pol_w2, const float* __restrict__ pol_b2,
        float* __restrict__ out)
{
    extern __shared__ float sm[];
    u32*   AH  = reinterpret_cast<u32*>(sm + OFF_AH);
    u32*   AL  = reinterpret_cast<u32*>(sm + OFF_AL);
    float* FT  = sm + OFF_FT;
    float* ST  = sm + OFF_ST;
    float* sSm = sm + OFF_SM;
    int*   sAdj = reinterpret_cast<int*>(sm + OFF_ADJ);
    float* H   = sm + OFF_AH;   // head-MLP scratch reuses A region (after emb dead)

    const int tid = threadIdx.x;
    const int b0  = blockIdx.x * BT;
    const int wid = tid >> 5, lane = tid & 31;
    const int n0  = wid * 16;   // each warp owns n-tiles {2w, 2w+1}

    // ---------- init: params, adj, obs -> A planes (k2 0..31) ----------
    pf_l2(enc_w1, tid, OBS * HD);
    for (int idx = tid; idx < HD; idx += NTHREADS) {
        sSm[idx]        = enc_b1[idx];
        sSm[128 + idx]  = enc_b2[idx];
        sSm[768 + idx]  = val_b1[idx];
        sSm[896 + idx]  = val_w2[idx];
        sSm[1024 + idx] = pol_b1[idx];
    }
    for (int idx = tid; idx < 512;  idx += NTHREADS) sSm[256 + idx]  = gat_a[idx];
    for (int idx = tid; idx < 1024; idx += NTHREADS) sSm[1152 + idx] = pol_w2[idx];
    if (tid < BT * NNODE) sAdj[tid] = adj[(size_t)b0 * NNODE + tid];
    if (tid == 0) sSm[2256] = val_b2[0];
    if (tid < NACT) sSm[2257 + tid] = pol_b2[tid];

    for (int p = tid; p < 80 * 32; p += NTHREADS) {
        const int r = p >> 5, k2 = p & 31;
        const int lb = r / NNODE, n = r - lb * NNODE;
        const float* src = (n == 0) ? obs + (size_t)(b0 + lb) * OBS + 2 * k2
                                    : nobs + ((size_t)(b0 + lb) * 4 + (n - 1)) * OBS + 2 * k2;
        const float2 v = __ldg(reinterpret_cast<const float2*>(src));
        u32 hi, lo; split2(v.x, v.y, hi, lo);
        AH[r * S_A + k2] = hi;
        AL[r * S_A + k2] = lo;
    }
    __syncthreads();

    // ---------- encoder layer 1: hidden = relu(A @ enc_w1 + b1) ----------
    {
        float acc[5][2][4];
        #pragma unroll
        for (int i = 0; i < 5; i++)
            #pragma unroll
            for (int j = 0; j < 2; j++)
                #pragma unroll
                for (int t = 0; t < 4; t++) acc[i][j][t] = 0.f;
        pf_l2(enc_w2, tid, HD * HD);
        run_gemm(acc, AH, AL, enc_w1, lane, n0, 4);
        __syncthreads();                       // all frag reads done
        store_split(acc, AH, AL, sSm, true, lane, n0);   // k2 0..63
    }
    __syncthreads();

    // ---------- encoder layer 2: emb = hidden @ enc_w2 + b2 ----------
    {
        float acc[5][2][4];
        #pragma unroll
        for (int i = 0; i < 5; i++)
            #pragma unroll
            for (int j = 0; j < 2; j++)
                #pragma unroll
                for (int t = 0; t < 4; t++) acc[i][j][t] = 0.f;
        pf_l2(gat_w, tid, 2 * HD * HD);
        run_gemm(acc, AH, AL, enc_w2, lane, n0, 8);
        __syncthreads();
        store_split(acc, AH, AL, sSm + 128, false, lane, n0);
    }
    __syncthreads();

    // ---------- g vectors: g[h][v] = gat_w[h] @ a_v  (warp-cooperative) ----------
    {
        const int h = (wid >> 1) & 1, v = wid & 1;
        const int dbase = (wid >> 2) * 64;
        const float* av = sSm + 256 + h * 256 + v * 128;
        float* gdst = sSm + 2272 + (h * 2 + v) * 128;
        for (int d = dbase; d < dbase + 64; d++) {
            const float* row = gat_w + (size_t)h * HD * HD + d * HD;
            float s = 0.f;
            #pragma unroll
            for (int o = 0; o < 4; o++)
                s = fmaf(__ldg(row + lane + 32 * o), av[lane + 32 * o], s);
            #pragma unroll
            for (int off = 16; off > 0; off >>= 1) s += __shfl_xor_sync(0xffffffffu, s, off);
            if (lane == 0) gdst[d] = s;
        }
    }
    __syncthreads();

    // ---------- GAT heads ----------
    for (int h = 0; h < 2; h++) {
        // attention: ei = emb[n=0]·g1, ej[n] = emb[n]·g2 (per warp: 2 batch elems)
        const float* g1 = sSm + 2272 + (h * 2) * 128;
        const float* g2 = g1 + 128;
        #pragma unroll
        for (int q = 0; q < 2; q++) {
            const int lb = wid * 2 + q;
            float ei = 0.f, ej[5] = {0.f, 0.f, 0.f, 0.f, 0.f};
            #pragma unroll
            for (int n = 0; n < NNODE; n++) {
                const int r = lb * NNODE + n;
                #pragma unroll
                for (int rep = 0; rep < 2; rep++) {
                    const int k2 = lane + 32 * rep;
                    float e0, e1;
                    emb_pair(AH[r * S_A + k2], AL[r * S_A + k2], e0, e1);
                    const int k = 2 * k2;
                    if (n == 0) { ei = fmaf(e0, g1[k], ei); ei = fmaf(e1, g1[k + 1], ei); }
                    ej[n] = fmaf(e0, g2[k], ej[n]);
                    ej[n] = fmaf(e1, g2[k + 1], ej[n]);
                }
            }
            #pragma unroll
            for (int off = 16; off > 0; off >>= 1) {
                ei += __shfl_xor_sync(0xffffffffu, ei, off);
                #pragma unroll
                for (int n = 0; n < NNODE; n++)
                    ej[n] += __shfl_xor_sync(0xffffffffu, ej[n], off);
            }
            if (lane == 0) {
                float ev[5], mx = -1e30f;
                #pragma unroll
                for (int n = 0; n < NNODE; n++) {
                    if (sAdj[lb * NNODE + n] != 0) {
                        float e = ei + ej[n];
                        e = (e >= 0.f) ? e : SLOPE * e;
                        ev[n] = e; mx = fmaxf(mx, e);
                    } else ev[n] = -1e30f;
                }
                float ssum = 0.f;
                #pragma unroll
                for (int n = 0; n < NNODE; n++) {
                    const float p = (ev[n] > -1e29f) ? __expf(ev[n] - mx) : 0.f;
                    ev[n] = p; ssum += p;
                }
                const float inv = 1.f / ssum;
                #pragma unroll
                for (int n = 0; n < NNODE; n++) sSm[2176 + lb * NNODE + n] = ev[n] * inv;
            }
        }
        __syncthreads();

        // s_b = sum_n attn[b,n] * emb[b,n,:]  -> ST[k][lb]
        for (int p = tid; p < 16 * 64; p += NTHREADS) {
            const int lb = p >> 6, k2 = p & 63;
            const float* at = sSm + 2176 + lb * NNODE;
            float s0 = 0.f, s1 = 0.f;
            #pragma unroll
            for (int n = 0; n < NNODE; n++) {
                const int r = lb * NNODE + n;
                float e0, e1;
                emb_pair(AH[r * S_A + k2], AL[r * S_A + k2], e0, e1);
                s0 = fmaf(at[n], e0, s0);
                s1 = fmaf(at[n], e1, s1);
            }
            ST[(2 * k2) * FTS + lb]     = s0;
            ST[(2 * k2 + 1) * FTS + lb] = s1;
        }
        __syncthreads();

        // h' = s @ gat_w[h]  (16x128x128 scalar FFMA2) -> FT
        {
            const float* Wg = gat_w + (size_t)h * HD * HD;
            const int qd = lane & 3, rs = lane >> 2;
            const int c0 = wid * 16 + qd * 4;
            u64 acc4[4] = {0ull, 0ull, 0ull, 0ull};
            #pragma unroll 8
            for (int k = 0; k < HD; k++) {
                const float4 w4 = __ldg(reinterpret_cast<const float4*>(Wg + (size_t)k * HD + c0));
                const u64 w0 = pack2(w4.x, w4.x), w1 = pack2(w4.y, w4.y),
                          w2 = pack2(w4.z, w4.z), w3 = pack2(w4.w, w4.w);
                const u64 a = *reinterpret_cast<const u64*>(ST + k * FTS + 2 * rs);
                acc4[0] = ffma2(a, w0, acc4[0]);
                acc4[1] = ffma2(a, w1, acc4[1]);
                acc4[2] = ffma2(a, w2, acc4[2]);
                acc4[3] = ffma2(a, w3, acc4[3]);
            }
            #pragma unroll
            for (int j = 0; j < 4; j++) {
                const float2 v = unpack2(acc4[j]);
                *reinterpret_cast<float2*>(FT + (h * HD + c0 + j) * FTS + 2 * rs) = v;
            }
        }
        __syncthreads();
    }

    // ---------- fused value+policy first layers (FFMA2, reads FT, writes H) ----------
    {
        const int head = wid >> 2;
        const float* Wg = head ? pol_w1 : val_w1;
        const float* bs = head ? (sSm + 1024) : (sSm + 768);
        float* Ho = head ? (H + BT * HD) : H;   // hv = H, hp = H + 2048
        const int cb = (wid & 3) * 32;
        const int q  = lane & 7;
        const int s  = lane >> 3;
        const int c0 = cb + q * 4;

        u64 acc[2][4];
        #pragma unroll
        for (int r = 0; r < 2; r++)
            #pragma unroll
            for (int j = 0; j < 4; j++) acc[r][j] = 0ull;

        #pragma unroll 8
        for (int k = 0; k < 2 * HD; k++) {
            const float4 w4 = __ldg(reinterpret_cast<const float4*>(Wg + (size_t)k * HD + c0));
            const u64 w0 = pack2(w4.x, w4.x), w1 = pack2(w4.y, w4.y),
                      w2 = pack2(w4.z, w4.z), w3 = pack2(w4.w, w4.w);
            const float* f = FT + k * FTS;
            const u64 a0 = *reinterpret_cast<const u64*>(f + 2 * s);
            const u64 a1 = *reinterpret_cast<const u64*>(f + 2 * s + 8);
            acc[0][0] = ffma2(a0, w0, acc[0][0]);
            acc[0][1] = ffma2(a0, w1, acc[0][1]);
            acc[0][2] = ffma2(a0, w2, acc[0][2]);
            acc[0][3] = ffma2(a0, w3, acc[0][3]);
            acc[1][0] = ffma2(a1, w0, acc[1][0]);
            acc[1][1] = ffma2(a1, w1, acc[1][1]);
            acc[1][2] = ffma2(a1, w2, acc[1][2]);
            acc[1][3] = ffma2(a1, w3, acc[1][3]);
        }
        const float4 bb = *reinterpret_cast<const float4*>(bs + c0);
        #pragma unroll
        for (int p = 0; p < 2; p++) {
            const int r = 2 * s + p * 8;
            const float2 v0 = unpack2(acc[p][0]);
            const float2 v1 = unpack2(acc[p][1]);
            const float2 v2 = unpack2(acc[p][2]);
            const float2 v3 = unpack2(acc[p][3]);
            float4 lo, hi;
            lo.x = fmaxf(v0.x + bb.x, 0.f); hi.x = fmaxf(v0.y + bb.x, 0.f);
            lo.y = fmaxf(v1.x + bb.y, 0.f); hi.y = fmaxf(v1.y + bb.y, 0.f);
            lo.z = fmaxf(v2.x + bb.z, 0.f); hi.z = fmaxf(v2.y + bb.z, 0.f);
            lo.w = fmaxf(v3.x + bb.w, 0.f); hi.w = fmaxf(v3.y + bb.w, 0.f);
            *reinterpret_cast<float4*>(Ho + r * HD + c0)       = lo;
            *reinterpret_cast<float4*>(Ho + (r + 1) * HD + c0) = hi;
        }
    }
    __syncthreads();

    // ---------- value = hv @ val_w2 + b ----------
    #pragma unroll
    for (int q = 0; q < 2; q++) {
        const int lb = wid * 2 + q;
        float s = 0.f;
        for (int kk = lane; kk < HD; kk += 32)
            s = fmaf(H[lb * HD + kk], sSm[896 + kk], s);
        #pragma unroll
        for (int off = 16; off > 0; off >>= 1) s += __shfl_xor_sync(0xffffffffu, s, off);
        if (lane == 0) out[b0 + lb] = s + sSm[2256];
    }

    // ---------- logits = hp @ pol_w2 + b ----------
    if (tid < BT * NACT) {
        const int lb = tid >> 3, a = tid & 7;
        const float* hp = H + BT * HD + lb * HD;
        float s = 0.f;
        for (int kk = 0; kk < HD; kk++)
            s = fmaf(hp[kk], sSm[1152 + kk * NACT + a], s);
        out[NB + (size_t)(b0 + lb) * NACT + a] = s + sSm[2257 + a];
    }
}

extern "C" void kernel_launch(void* const* d_in, const int* in_sizes, int n_in,
                              void* d_out, int out_size)
{
    (void)in_sizes; (void)n_in; (void)out_size;
    cudaFuncSetAttribute(colight, cudaFuncAttributeMaxDynamicSharedMemorySize, SMEM_BYTES);
    colight<<<NB/BT, NTHREADS, SMEM_BYTES>>>(
        (const float*)d_in[0],  (const float*)d_in[1],  (const int*)d_in[2],
        (const float*)d_in[3],  (const float*)d_in[4],  (const float*)d_in[5],
        (const float*)d_in[6],  (const float*)d_in[7],  (const float*)d_in[8],
        (const float*)d_in[9],  (const float*)d_in[10], (const float*)d_in[11],
        (const float*)d_in[12], (const float*)d_in[13], (const float*)d_in[14],
        (const float*)d_in[15], (const float*)d_in[16],
        (float*)d_out);
}

// round 12
// speedup vs baseline: 1.9726x; 1.2635x over previous
#include <cuda_runtime.h>

typedef unsigned int u32;
typedef unsigned long long u64;

#define NB 16384
#define OBS 64
#define HD 128
#define NNODE 5
#define NACT 8
#define SLOPE 0.2f
#define BT 16
#define NTHREADS 256

#define S_A 68      // u32 stride of 80-row A planes (68%32==4 -> conflict-free frags)
#define S_ST 68     // u32 stride of 16-row s planes
#define S_FT 132    // u32 stride of 16-row FT planes (132%32==4)

// ---- smem layout (4-byte word offsets) ----
#define OFF_AH  0        // A hi plane u32[80*68]
#define OFF_AL  5440
#define OFF_FTH 10880    // FT hi plane u32[16*132]
#define OFF_FTL 12992
#define OFF_STH 15104    // s hi plane u32[16*68]
#define OFF_STL 16192
#define OFF_SM  17280    // small params (2784 floats):
// 0 enc_b1[128],128 enc_b2[128],256 gat_a[512],768 val_b1[128],896 val_w2[128],
// 1024 pol_b1[128],1152 pol_w2[1024],2176 attn[80],2256 val_b2,2257 pol_b2[8],2272 g[512]
#define OFF_ADJ 20064    // 80 ints
#define SMEM_FLOATS 20144
#define SMEM_BYTES (SMEM_FLOATS*4)   // 80576 B -> 2 CTAs/SM

// pack two f32 -> bf16x2, first arg in LOW half
#define CVTP(r, a, b) asm("cvt.rn.bf16x2.f32 %0, %1, %2;" : "=r"(r) : "f"(b), "f"(a))

__device__ __forceinline__ void split2(float v0, float v1, u32& hi, u32& lo) {
    CVTP(hi, v0, v1);
    const float r0 = v0 - __uint_as_float(hi << 16);
    const float r1 = v1 - __uint_as_float(hi & 0xffff0000u);
    CVTP(lo, r0, r1);
}

#define MMA(d, a0, a1, a2, a3, b0, b1) \
    asm volatile("mma.sync.aligned.m16n8k16.row.col.f32.bf16.bf16.f32 " \
        "{%0,%1,%2,%3}, {%4,%5,%6,%7}, {%8,%9}, {%0,%1,%2,%3};" \
        : "+f"((d)[0]), "+f"((d)[1]), "+f"((d)[2]), "+f"((d)[3]) \
        : "r"(a0), "r"(a1), "r"(a2), "r"(a3), "r"(b0), "r"(b1))

__device__ __forceinline__ void pf_l2(const float* p, int tid, int nf) {
    for (int off = tid * 32; off < nf; off += NTHREADS * 32)
        asm volatile("prefetch.global.L2 [%0];" :: "l"(p + off));
}

// Split-bf16 MMA gemm: acc[5 m-tiles][2 n-tiles][4] += A(80xK) @ W(Kx128)
__device__ __forceinline__ void run_gemm(float acc[5][2][4],
                                         const u32* __restrict__ AH,
                                         const u32* __restrict__ AL,
                                         const float* __restrict__ Wg,
                                         int lane, int n0, int KS)
{
    const int ar = lane >> 2, ac = lane & 3;
    for (int s = 0; s < KS; s++) {
        const int kb = s * 16;
        u32 bh[2][2], bl[2][2];
        #pragma unroll
        for (int j = 0; j < 2; j++) {
            const int wn = n0 + 8 * j + ar;
            const float* p = Wg + (size_t)(kb + (ac << 1)) * HD + wn;
            split2(__ldg(p), __ldg(p + HD), bh[j][0], bl[j][0]);
            split2(__ldg(p + 8 * HD), __ldg(p + 9 * HD), bh[j][1], bl[j][1]);
        }
        #pragma unroll
        for (int i = 0; i < 5; i++) {
            const u32* pa = AH + (i * 16 + ar) * S_A + s * 8 + ac;
            const u32* pl = AL + (i * 16 + ar) * S_A + s * 8 + ac;
            const u32 a0 = pa[0], a1 = pa[8 * S_A], a2 = pa[4], a3 = pa[8 * S_A + 4];
            const u32 l0 = pl[0], l1 = pl[8 * S_A], l2 = pl[4], l3 = pl[8 * S_A + 4];
            #pragma unroll
            for (int j = 0; j < 2; j++) {
                MMA(acc[i][j], a0, a1, a2, a3, bh[j][0], bh[j][1]);
                MMA(acc[i][j], a0, a1, a2, a3, bl[j][0], bl[j][1]);
                MMA(acc[i][j], l0, l1, l2, l3, bh[j][0], bh[j][1]);
            }
        }
    }
}

// M=16 split-bf16 MMA gemm: acc[NT][4] += A(16xK, planes stride sa) @ W(Kx128)
template<int NT>
__device__ __forceinline__ void gemm16(float acc[NT][4],
                                       const u32* __restrict__ AHp,
                                       const u32* __restrict__ ALp, int sa,
                                       const float* __restrict__ Wg,
                                       int lane, int n0, int KS)
{
    const int ar = lane >> 2, ac = lane & 3;
    for (int s = 0; s < KS; s++) {
        const int kb = s * 16;
        u32 bh[NT][2], bl[NT][2];
        #pragma unroll
        for (int j = 0; j < NT; j++) {
            const int wn = n0 + 8 * j + ar;
            const float* p = Wg + (size_t)(kb + (ac << 1)) * HD + wn;
            split2(__ldg(p), __ldg(p + HD), bh[j][0], bl[j][0]);
            split2(__ldg(p + 8 * HD), __ldg(p + 9 * HD), bh[j][1], bl[j][1]);
        }
        const u32* pa = AHp + ar * sa + s * 8 + ac;
        const u32* pl = ALp + ar * sa + s * 8 + ac;
        const u32 a0 = pa[0], a1 = pa[8 * sa], a2 = pa[4], a3 = pa[8 * sa + 4];
        const u32 l0 = pl[0], l1 = pl[8 * sa], l2 = pl[4], l3 = pl[8 * sa + 4];
        #pragma unroll
        for (int j = 0; j < NT; j++) {
            MMA(acc[j], a0, a1, a2, a3, bh[j][0], bh[j][1]);
            MMA(acc[j], a0, a1, a2, a3, bl[j][0], bl[j][1]);
            MMA(acc[j], l0, l1, l2, l3, bh[j][0], bh[j][1]);
        }
    }
}

// D-frags -> bf16 hi/lo A planes (+bias, optional relu), 5 m-tiles
__device__ __forceinline__ void store_split(const float acc[5][2][4],
                                            u32* __restrict__ AH, u32* __restrict__ AL,
                                            const float* __restrict__ bias, bool relu,
                                            int lane, int n0)
{
    const int ar = lane >> 2, ac2 = (lane & 3) << 1;
    #pragma unroll
    for (int i = 0; i < 5; i++)
        #pragma unroll
        for (int j = 0; j < 2; j++) {
            const int c = n0 + 8 * j + ac2;
            const float b0v = bias[c], b1v = bias[c + 1];
            float v0 = acc[i][j][0] + b0v, v1 = acc[i][j][1] + b1v;
            if (relu) { v0 = fmaxf(v0, 0.f); v1 = fmaxf(v1, 0.f); }
            u32 hi, lo; split2(v0, v1, hi, lo);
            const int r0 = i * 16 + ar;
            AH[r0 * S_A + (c >> 1)] = hi;
            AL[r0 * S_A + (c >> 1)] = lo;
            float v2 = acc[i][j][2] + b0v, v3 = acc[i][j][3] + b1v;
            if (relu) { v2 = fmaxf(v2, 0.f); v3 = fmaxf(v3, 0.f); }
            split2(v2, v3, hi, lo);
            AH[(r0 + 8) * S_A + (c >> 1)] = hi;
            AL[(r0 + 8) * S_A + (c >> 1)] = lo;
        }
}

__device__ __forceinline__ void emb_pair(u32 h, u32 l, float& e0, float& e1) {
    e0 = __uint_as_float(h << 16) + __uint_as_float(l << 16);
    e1 = __uint_as_float(h & 0xffff0000u) + __uint_as_float(l & 0xffff0000u);
}

extern "C" __global__ void __launch_bounds__(NTHREADS, 2)
colight(const float* __restrict__ obs, const float* __restrict__ nobs,
        const int* __restrict__ adj,
        const float* __restrict__ enc_w1, const float* __restrict__ enc_b1,
        const float* __restrict__ enc_w2, const float* __restrict__ enc_b2,
        const float* __restrict__ gat_w, const float* __restrict__ gat_a,
        const float* __restrict__ val_w1, const float* __restrict__ val_b1,
        const float* __restrict__ val_w2, const float* __restrict__ val_b2,
        const float* __restrict__ pol_w1, const float* __restrict__ pol_b1,
        const float* __restrict__ pol_w2, const float* __restrict__ pol_b2,
        float* __restrict__ out)
{
    extern __shared__ float sm[];
    u32*   AH  = reinterpret_cast<u32*>(sm + OFF_AH);
    u32*   AL  = reinterpret_cast<u32*>(sm + OFF_AL);
    u32*   FTH = reinterpret_cast<u32*>(sm + OFF_FTH);
    u32*   FTL = reinterpret_cast<u32*>(sm + OFF_FTL);
    u32*   STH = reinterpret_cast<u32*>(sm + OFF_STH);
    u32*   STL = reinterpret_cast<u32*>(sm + OFF_STL);
    float* sSm = sm + OFF_SM;
    int*   sAdj = reinterpret_cast<int*>(sm + OFF_ADJ);
    float* Hf  = sm + OFF_AH;   // head-MLP output reuses A region (emb dead by then)

    const int tid = threadIdx.x;
    const int b0  = blockIdx.x * BT;
    const int wid = tid >> 5, lane = tid & 31;
    const int n0  = wid * 16;

    // ---------- init ----------
    pf_l2(enc_w1, tid, OBS * HD);
    for (int idx = tid; idx < HD; idx += NTHREADS) {
        sSm[idx]        = enc_b1[idx];
        sSm[128 + idx]  = enc_b2[idx];
        sSm[768 + idx]  = val_b1[idx];
        sSm[896 + idx]  = val_w2[idx];
        sSm[1024 + idx] = pol_b1[idx];
    }
    for (int idx = tid; idx < 512;  idx += NTHREADS) sSm[256 + idx]  = gat_a[idx];
    for (int idx = tid; idx < 1024; idx += NTHREADS) sSm[1152 + idx] = pol_w2[idx];
    if (tid < BT * NNODE) sAdj[tid] = adj[(size_t)b0 * NNODE + tid];
    if (tid == 0) sSm[2256] = val_b2[0];
    if (tid < NACT) sSm[2257 + tid] = pol_b2[tid];

    for (int p = tid; p < 80 * 32; p += NTHREADS) {
        const int r = p >> 5, k2 = p & 31;
        const int lb = r / NNODE, n = r - lb * NNODE;
        const float* src = (n == 0) ? obs + (size_t)(b0 + lb) * OBS + 2 * k2
                                    : nobs + ((size_t)(b0 + lb) * 4 + (n - 1)) * OBS + 2 * k2;
        const float2 v = __ldg(reinterpret_cast<const float2*>(src));
        u32 hi, lo; split2(v.x, v.y, hi, lo);
        AH[r * S_A + k2] = hi;
        AL[r * S_A + k2] = lo;
    }
    __syncthreads();

    // ---------- encoder layer 1 ----------
    {
        float acc[5][2][4];
        #pragma unroll
        for (int i = 0; i < 5; i++)
            #pragma unroll
            for (int j = 0; j < 2; j++)
                #pragma unroll
                for (int t = 0; t < 4; t++) acc[i][j][t] = 0.f;
        pf_l2(enc_w2, tid, HD * HD);
        run_gemm(acc, AH, AL, enc_w1, lane, n0, 4);
        __syncthreads();
        store_split(acc, AH, AL, sSm, true, lane, n0);
    }
    __syncthreads();

    // ---------- encoder layer 2 ----------
    {
        float acc[5][2][4];
        #pragma unroll
        for (int i = 0; i < 5; i++)
            #pragma unroll
            for (int j = 0; j < 2; j++)
                #pragma unroll
                for (int t = 0; t < 4; t++) acc[i][j][t] = 0.f;
        pf_l2(gat_w, tid, 2 * HD * HD);
        run_gemm(acc, AH, AL, enc_w2, lane, n0, 8);
        __syncthreads();
        store_split(acc, AH, AL, sSm + 128, false, lane, n0);
    }
    __syncthreads();

    // ---------- g vectors: g[h][v] = gat_w[h] @ a_v ----------
    {
        const int h = (wid >> 1) & 1, v = wid & 1;
        const int dbase = (wid >> 2) * 64;
        const float* av = sSm + 256 + h * 256 + v * 128;
        float* gdst = sSm + 2272 + (h * 2 + v) * 128;
        for (int d = dbase; d < dbase + 64; d++) {
            const float* row = gat_w + (size_t)h * HD * HD + d * HD;
            float s = 0.f;
            #pragma unroll
            for (int o = 0; o < 4; o++)
                s = fmaf(__ldg(row + lane + 32 * o), av[lane + 32 * o], s);
            #pragma unroll
            for (int off = 16; off > 0; off >>= 1) s += __shfl_xor_sync(0xffffffffu, s, off);
            if (lane == 0) gdst[d] = s;
        }
    }
    __syncthreads();

    // ---------- GAT heads ----------
    for (int h = 0; h < 2; h++) {
        const float* g1 = sSm + 2272 + (h * 2) * 128;
        const float* g2 = g1 + 128;
        #pragma unroll
        for (int q = 0; q < 2; q++) {
            const int lb = wid * 2 + q;
            float ei = 0.f, ej[5] = {0.f, 0.f, 0.f, 0.f, 0.f};
            #pragma unroll
            for (int n = 0; n < NNODE; n++) {
                const int r = lb * NNODE + n;
                #pragma unroll
                for (int rep = 0; rep < 2; rep++) {
                    const int k2 = lane + 32 * rep;
                    float e0, e1;
                    emb_pair(AH[r * S_A + k2], AL[r * S_A + k2], e0, e1);
                    const int k = 2 * k2;
                    if (n == 0) { ei = fmaf(e0, g1[k], ei); ei = fmaf(e1, g1[k + 1], ei); }
                    ej[n] = fmaf(e0, g2[k], ej[n]);
                    ej[n] = fmaf(e1, g2[k + 1], ej[n]);
                }
            }
            #pragma unroll
            for (int off = 16; off > 0; off >>= 1) {
                ei += __shfl_xor_sync(0xffffffffu, ei, off);
                #pragma unroll
                for (int n = 0; n < NNODE; n++)
                    ej[n] += __shfl_xor_sync(0xffffffffu, ej[n], off);
            }
            if (lane == 0) {
                float ev[5], mx = -1e30f;
                #pragma unroll
                for (int n = 0; n < NNODE; n++) {
                    if (sAdj[lb * NNODE + n] != 0) {
                        float e = ei + ej[n];
                        e = (e >= 0.f) ? e : SLOPE * e;
                        ev[n] = e; mx = fmaxf(mx, e);
                    } else ev[n] = -1e30f;
                }
                float ssum = 0.f;
                #pragma unroll
                for (int n = 0; n < NNODE; n++) {
                    const float p = (ev[n] > -1e29f) ? __expf(ev[n] - mx) : 0.f;
                    ev[n] = p; ssum += p;
                }
                const float inv = 1.f / ssum;
                #pragma unroll
                for (int n = 0; n < NNODE; n++) sSm[2176 + lb * NNODE + n] = ev[n] * inv;
            }
        }
        __syncthreads();

        // s_b = sum_n attn[b,n] * emb[b,n,:]  -> split planes STH/STL
        for (int p = tid; p < 16 * 64; p += NTHREADS) {
            const int lb = p >> 6, k2 = p & 63;
            const float* at = sSm + 2176 + lb * NNODE;
            float s0 = 0.f, s1 = 0.f;
            #pragma unroll
            for (int n = 0; n < NNODE; n++) {
                const int r = lb * NNODE + n;
                float e0, e1;
                emb_pair(AH[r * S_A + k2], AL[r * S_A + k2], e0, e1);
                s0 = fmaf(at[n], e0, s0);
                s1 = fmaf(at[n], e1, s1);
            }
            u32 hi, lo; split2(s0, s1, hi, lo);
            STH[lb * S_ST + k2] = hi;
            STL[lb * S_ST + k2] = lo;
        }
        __syncthreads();

        // h' = s @ gat_w[h]  (16x128x128 split-MMA) -> FT planes (k half h)
        {
            float acc[2][4];
            #pragma unroll
            for (int j = 0; j < 2; j++)
                #pragma unroll
                for (int t = 0; t < 4; t++) acc[j][t] = 0.f;
            gemm16<2>(acc, STH, STL, S_ST, gat_w + (size_t)h * HD * HD, lane, wid * 16, 8);
            const int ar = lane >> 2, ac2 = (lane & 3) << 1;
            #pragma unroll
            for (int j = 0; j < 2; j++) {
                const int c = wid * 16 + 8 * j + ac2;
                const int k2f = h * 64 + (c >> 1);
                u32 hi, lo;
                split2(acc[j][0], acc[j][1], hi, lo);
                FTH[ar * S_FT + k2f] = hi;
                FTL[ar * S_FT + k2f] = lo;
                split2(acc[j][2], acc[j][3], hi, lo);
                FTH[(ar + 8) * S_FT + k2f] = hi;
                FTL[(ar + 8) * S_FT + k2f] = lo;
            }
        }
        __syncthreads();
    }

    // ---------- fused value+policy first layers (16x256x128 split-MMA x2) ----------
    {
        const int head = wid >> 2;
        const float* Wg = head ? pol_w1 : val_w1;
        const float* bs = head ? (sSm + 1024) : (sSm + 768);
        float* Ho = Hf + head * BT * HD;
        float acc[4][4];
        #pragma unroll
        for (int j = 0; j < 4; j++)
            #pragma unroll
            for (int t = 0; t < 4; t++) acc[j][t] = 0.f;
        gemm16<4>(acc, FTH, FTL, S_FT, Wg, lane, (wid & 3) * 32, 16);
        const int ar = lane >> 2, ac2 = (lane & 3) << 1;
        #pragma unroll
        for (int j = 0; j < 4; j++) {
            const int c = (wid & 3) * 32 + 8 * j + ac2;
            const float b0v = bs[c], b1v = bs[c + 1];
            float2 v;
            v.x = fmaxf(acc[j][0] + b0v, 0.f);
            v.y = fmaxf(acc[j][1] + b1v, 0.f);
            *reinterpret_cast<float2*>(Ho + ar * HD + c) = v;
            v.x = fmaxf(acc[j][2] + b0v, 0.f);
            v.y = fmaxf(acc[j][3] + b1v, 0.f);
            *reinterpret_cast<float2*>(Ho + (ar + 8) * HD + c) = v;
        }
    }
    __syncthreads();

    // ---------- value = hv @ val_w2 + b ----------
    #pragma unroll
    for (int q = 0; q < 2; q++) {
        const int lb = wid * 2 + q;
        float s = 0.f;
        for (int kk = lane; kk < HD; kk += 32)
            s = fmaf(Hf[lb * HD + kk], sSm[896 + kk], s);
        #pragma unroll
        for (int off = 16; off > 0; off >>= 1) s += __shfl_xor_sync(0xffffffffu, s, off);
        if (lane == 0) out[b0 + lb] = s + sSm[2256];
    }

    // ---------- logits = hp @ pol_w2 + b ----------
    if (tid < BT * NACT) {
        const int lb = tid >> 3, a = tid & 7;
        const float* hp = Hf + BT * HD + lb * HD;
        float s = 0.f;
        for (int kk = 0; kk < HD; kk++)
            s = fmaf(hp[kk], sSm[1152 + kk * NACT + a], s);
        out[NB + (size_t)(b0 + lb) * NACT + a] = s + sSm[2257 + a];
    }
}

extern "C" void kernel_launch(void* const* d_in, const int* in_sizes, int n_in,
                              void* d_out, int out_size)
{
    (void)in_sizes; (void)n_in; (void)out_size;
    cudaFuncSetAttribute(colight, cudaFuncAttributeMaxDynamicSharedMemorySize, SMEM_BYTES);
    colight<<<NB/BT, NTHREADS, SMEM_BYTES>>>(
        (const float*)d_in[0],  (const float*)d_in[1],  (const int*)d_in[2],
        (const float*)d_in[3],  (const float*)d_in[4],  (const float*)d_in[5],
        (const float*)d_in[6],  (const float*)d_in[7],  (const float*)d_in[8],
        (const float*)d_in[9],  (const float*)d_in[10], (const float*)d_in[11],
        (const float*)d_in[12], (const float*)d_in[13], (const float*)d_in[14],
        (const float*)d_in[15], (const float*)d_in[16],
        (float*)d_out);
}

// round 13
// speedup vs baseline: 2.4377x; 1.2358x over previous
#include <cuda_runtime.h>

typedef unsigned int u32;
typedef unsigned long long u64;

#define NB 16384
#define OBS 64
#define HD 128
#define NNODE 5
#define NACT 8
#define SLOPE 0.2f
#define BT 16
#define NTHREADS 256

#define S_A 68      // u32 stride of 80-row A planes (68%32==4 -> conflict-free frags)
#define S_ST 68     // u32 stride of 16-row s planes
#define S_FT 132    // u32 stride of 16-row FT planes (132%32==4)

// ---- smem layout (4-byte word offsets) ----
#define OFF_AH  0        // A hi plane u32[80*68]
#define OFF_AL  5440
#define OFF_FTH 10880    // FT hi plane u32[16*132]
#define OFF_FTL 12992
#define OFF_STH 15104    // s hi plane u32[16*68]
#define OFF_STL 16192
#define OFF_SM  17280    // small params (2784 floats)
#define OFF_ADJ 20064    // 80 ints
#define SMEM_FLOATS 20144
#define SMEM_BYTES (SMEM_FLOATS*4)   // 80576 B -> 2 CTAs/SM

// ---- precomputed weight-fragment buffer (uint4 per (ntile,kstep,lane)) ----
// frag idx within a matrix: (s*16 + ntile)*32 + lane
#define WF_ENC1 0        // K=64:  4 ks * 16 nt * 32 = 2048
#define WF_ENC2 2048     // K=128: 4096
#define WF_GAT0 6144
#define WF_GAT1 10240
#define WF_VAL  14336    // K=256: 8192
#define WF_POL  22528
#define WF_TOTAL 30720
__device__ uint4 g_wf[WF_TOTAL];

// pack two f32 -> bf16x2, first arg in LOW half
#define CVTP(r, a, b) asm("cvt.rn.bf16x2.f32 %0, %1, %2;" : "=r"(r) : "f"(b), "f"(a))

__device__ __forceinline__ void split2(float v0, float v1, u32& hi, u32& lo) {
    CVTP(hi, v0, v1);
    const float r0 = v0 - __uint_as_float(hi << 16);
    const float r1 = v1 - __uint_as_float(hi & 0xffff0000u);
    CVTP(lo, r0, r1);
}

#define MMA(d, a0, a1, a2, a3, b0, b1) \
    asm volatile("mma.sync.aligned.m16n8k16.row.col.f32.bf16.bf16.f32 " \
        "{%0,%1,%2,%3}, {%4,%5,%6,%7}, {%8,%9}, {%0,%1,%2,%3};" \
        : "+f"((d)[0]), "+f"((d)[1]), "+f"((d)[2]), "+f"((d)[3]) \
        : "r"(a0), "r"(a1), "r"(a2), "r"(a3), "r"(b0), "r"(b1))

// ---- pre-pass: convert all weights to fragment layout (once per launch) ----
extern "C" __global__ void __launch_bounds__(256)
prep_wf(const float* __restrict__ enc_w1, const float* __restrict__ enc_w2,
        const float* __restrict__ gat_w,  const float* __restrict__ val_w1,
        const float* __restrict__ pol_w1)
{
    const int idx = blockIdx.x * 256 + threadIdx.x;
    if (idx >= WF_TOTAL) return;
    const float* W; int base;
    if      (idx < WF_ENC2) { W = enc_w1;           base = WF_ENC1; }
    else if (idx < WF_GAT0) { W = enc_w2;           base = WF_ENC2; }
    else if (idx < WF_GAT1) { W = gat_w;            base = WF_GAT0; }
    else if (idx < WF_VAL)  { W = gat_w + HD * HD;  base = WF_GAT1; }
    else if (idx < WF_POL)  { W = val_w1;           base = WF_VAL;  }
    else                    { W = pol_w1;           base = WF_POL;  }
    const int r = idx - base;
    const int lane = r & 31, t = (r >> 5) & 15, s = r >> 9;
    const int ar = lane >> 2, ac = lane & 3;
    const int wn = t * 8 + ar;
    const float* p = W + (size_t)(s * 16 + 2 * ac) * HD + wn;
    u32 h0, l0, h1, l1;
    split2(__ldg(p),          __ldg(p + HD),     h0, l0);
    split2(__ldg(p + 8 * HD), __ldg(p + 9 * HD), h1, l1);
    g_wf[idx] = make_uint4(h0, h1, l0, l1);
}

// Split-bf16 MMA gemm: acc[5 m-tiles][2 n-tiles][4] += A(80xK) @ W(Kx128)
// B-fragments from g_wf (one coalesced LDG.128 per (s,j)).
__device__ __forceinline__ void run_gemm(float acc[5][2][4],
                                         const u32* __restrict__ AH,
                                         const u32* __restrict__ AL,
                                         int wfbase, int lane, int wid, int KS)
{
    const int ar = lane >> 2, ac = lane & 3;
    for (int s = 0; s < KS; s++) {
        uint4 f[2];
        #pragma unroll
        for (int j = 0; j < 2; j++)
            f[j] = __ldg(&g_wf[wfbase + (s * 16 + 2 * wid + j) * 32 + lane]);
        #pragma unroll
        for (int i = 0; i < 5; i++) {
            const u32* pa = AH + (i * 16 + ar) * S_A + s * 8 + ac;
            const u32* pl = AL + (i * 16 + ar) * S_A + s * 8 + ac;
            const u32 a0 = pa[0], a1 = pa[8 * S_A], a2 = pa[4], a3 = pa[8 * S_A + 4];
            const u32 l0 = pl[0], l1 = pl[8 * S_A], l2 = pl[4], l3 = pl[8 * S_A + 4];
            #pragma unroll
            for (int j = 0; j < 2; j++) {
                MMA(acc[i][j], a0, a1, a2, a3, f[j].x, f[j].y);
                MMA(acc[i][j], a0, a1, a2, a3, f[j].z, f[j].w);
                MMA(acc[i][j], l0, l1, l2, l3, f[j].x, f[j].y);
            }
        }
    }
}

// M=16 split-bf16 MMA gemm: acc[NT][4] += A(16xK planes) @ W, frags from g_wf.
template<int NT>
__device__ __forceinline__ void gemm16(float acc[NT][4],
                                       const u32* __restrict__ AHp,
                                       const u32* __restrict__ ALp, int sa,
                                       int wfbase, int nt0, int lane, int KS)
{
    const int ar = lane >> 2, ac = lane & 3;
    for (int s = 0; s < KS; s++) {
        uint4 f[NT];
        #pragma unroll
        for (int j = 0; j < NT; j++)
            f[j] = __ldg(&g_wf[wfbase + (s * 16 + nt0 + j) * 32 + lane]);
        const u32* pa = AHp + ar * sa + s * 8 + ac;
        const u32* pl = ALp + ar * sa + s * 8 + ac;
        const u32 a0 = pa[0], a1 = pa[8 * sa], a2 = pa[4], a3 = pa[8 * sa + 4];
        const u32 l0 = pl[0], l1 = pl[8 * sa], l2 = pl[4], l3 = pl[8 * sa + 4];
        #pragma unroll
        for (int j = 0; j < NT; j++) {
            MMA(acc[j], a0, a1, a2, a3, f[j].x, f[j].y);
            MMA(acc[j], a0, a1, a2, a3, f[j].z, f[j].w);
            MMA(acc[j], l0, l1, l2, l3, f[j].x, f[j].y);
        }
    }
}

// D-frags -> bf16 hi/lo A planes (+bias, optional relu), 5 m-tiles
__device__ __forceinline__ void store_split(const float acc[5][2][4],
                                            u32* __restrict__ AH, u32* __restrict__ AL,
                                            const float* __restrict__ bias, bool relu,
                                            int lane, int n0)
{
    const int ar = lane >> 2, ac2 = (lane & 3) << 1;
    #pragma unroll
    for (int i = 0; i < 5; i++)
        #pragma unroll
        for (int j = 0; j < 2; j++) {
            const int c = n0 + 8 * j + ac2;
            const float b0v = bias[c], b1v = bias[c + 1];
            float v0 = acc[i][j][0] + b0v, v1 = acc[i][j][1] + b1v;
            if (relu) { v0 = fmaxf(v0, 0.f); v1 = fmaxf(v1, 0.f); }
            u32 hi, lo; split2(v0, v1, hi, lo);
            const int r0 = i * 16 + ar;
            AH[r0 * S_A + (c >> 1)] = hi;
            AL[r0 * S_A + (c >> 1)] = lo;
            float v2 = acc[i][j][2] + b0v, v3 = acc[i][j][3] + b1v;
            if (relu) { v2 = fmaxf(v2, 0.f); v3 = fmaxf(v3, 0.f); }
            split2(v2, v3, hi, lo);
            AH[(r0 + 8) * S_A + (c >> 1)] = hi;
            AL[(r0 + 8) * S_A + (c >> 1)] = lo;
        }
}

__device__ __forceinline__ void emb_pair(u32 h, u32 l, float& e0, float& e1) {
    e0 = __uint_as_float(h << 16) + __uint_as_float(l << 16);
    e1 = __uint_as_float(h & 0xffff0000u) + __uint_as_float(l & 0xffff0000u);
}

extern "C" __global__ void __launch_bounds__(NTHREADS, 2)
colight(const float* __restrict__ obs, const float* __restrict__ nobs,
        const int* __restrict__ adj,
        const float* __restrict__ enc_w1, const float* __restrict__ enc_b1,
        const float* __restrict__ enc_w2, const float* __restrict__ enc_b2,
        const float* __restrict__ gat_w, const float* __restrict__ gat_a,
        const float* __restrict__ val_w1, const float* __restrict__ val_b1,
        const float* __restrict__ val_w2, const float* __restrict__ val_b2,
        const float* __restrict__ pol_w1, const float* __restrict__ pol_b1,
        const float* __restrict__ pol_w2, const float* __restrict__ pol_b2,
        float* __restrict__ out)
{
    extern __shared__ float sm[];
    u32*   AH  = reinterpret_cast<u32*>(sm + OFF_AH);
    u32*   AL  = reinterpret_cast<u32*>(sm + OFF_AL);
    u32*   FTH = reinterpret_cast<u32*>(sm + OFF_FTH);
    u32*   FTL = reinterpret_cast<u32*>(sm + OFF_FTL);
    u32*   STH = reinterpret_cast<u32*>(sm + OFF_STH);
    u32*   STL = reinterpret_cast<u32*>(sm + OFF_STL);
    float* sSm = sm + OFF_SM;
    int*   sAdj = reinterpret_cast<int*>(sm + OFF_ADJ);
    float* Hf  = sm + OFF_AH;   // head-MLP output reuses A region

    const int tid = threadIdx.x;
    const int b0  = blockIdx.x * BT;
    const int wid = tid >> 5, lane = tid & 31;
    const int n0  = wid * 16;

    // ---------- init ----------
    for (int idx = tid; idx < HD; idx += NTHREADS) {
        sSm[idx]        = enc_b1[idx];
        sSm[128 + idx]  = enc_b2[idx];
        sSm[768 + idx]  = val_b1[idx];
        sSm[896 + idx]  = val_w2[idx];
        sSm[1024 + idx] = pol_b1[idx];
    }
    for (int idx = tid; idx < 512;  idx += NTHREADS) sSm[256 + idx]  = gat_a[idx];
    for (int idx = tid; idx < 1024; idx += NTHREADS) sSm[1152 + idx] = pol_w2[idx];
    if (tid < BT * NNODE) sAdj[tid] = adj[(size_t)b0 * NNODE + tid];
    if (tid == 0) sSm[2256] = val_b2[0];
    if (tid < NACT) sSm[2257 + tid] = pol_b2[tid];

    for (int p = tid; p < 80 * 32; p += NTHREADS) {
        const int r = p >> 5, k2 = p & 31;
        const int lb = r / NNODE, n = r - lb * NNODE;
        const float* src = (n == 0) ? obs + (size_t)(b0 + lb) * OBS + 2 * k2
                                    : nobs + ((size_t)(b0 + lb) * 4 + (n - 1)) * OBS + 2 * k2;
        const float2 v = __ldg(reinterpret_cast<const float2*>(src));
        u32 hi, lo; split2(v.x, v.y, hi, lo);
        AH[r * S_A + k2] = hi;
        AL[r * S_A + k2] = lo;
    }
    __syncthreads();

    // ---------- encoder layer 1 ----------
    {
        float acc[5][2][4];
        #pragma unroll
        for (int i = 0; i < 5; i++)
            #pragma unroll
            for (int j = 0; j < 2; j++)
                #pragma unroll
                for (int t = 0; t < 4; t++) acc[i][j][t] = 0.f;
        run_gemm(acc, AH, AL, WF_ENC1, lane, wid, 4);
        __syncthreads();
        store_split(acc, AH, AL, sSm, true, lane, n0);
    }
    __syncthreads();

    // ---------- encoder layer 2 ----------
    {
        float acc[5][2][4];
        #pragma unroll
        for (int i = 0; i < 5; i++)
            #pragma unroll
            for (int j = 0; j < 2; j++)
                #pragma unroll
                for (int t = 0; t < 4; t++) acc[i][j][t] = 0.f;
        run_gemm(acc, AH, AL, WF_ENC2, lane, wid, 8);
        __syncthreads();
        store_split(acc, AH, AL, sSm + 128, false, lane, n0);
    }
    __syncthreads();

    // ---------- g vectors: g[h][v] = gat_w[h] @ a_v ----------
    {
        const int h = (wid >> 1) & 1, v = wid & 1;
        const int dbase = (wid >> 2) * 64;
        const float* av = sSm + 256 + h * 256 + v * 128;
        float* gdst = sSm + 2272 + (h * 2 + v) * 128;
        for (int d = dbase; d < dbase + 64; d++) {
            const float* row = gat_w + (size_t)h * HD * HD + d * HD;
            float s = 0.f;
            #pragma unroll
            for (int o = 0; o < 4; o++)
                s = fmaf(__ldg(row + lane + 32 * o), av[lane + 32 * o], s);
            #pragma unroll
            for (int off = 16; off > 0; off >>= 1) s += __shfl_xor_sync(0xffffffffu, s, off);
            if (lane == 0) gdst[d] = s;
        }
    }
    __syncthreads();

    // ---------- GAT heads ----------
    for (int h = 0; h < 2; h++) {
        const float* g1 = sSm + 2272 + (h * 2) * 128;
        const float* g2 = g1 + 128;
        #pragma unroll
        for (int q = 0; q < 2; q++) {
            const int lb = wid * 2 + q;
            float ei = 0.f, ej[5] = {0.f, 0.f, 0.f, 0.f, 0.f};
            #pragma unroll
            for (int n = 0; n < NNODE; n++) {
                const int r = lb * NNODE + n;
                #pragma unroll
                for (int rep = 0; rep < 2; rep++) {
                    const int k2 = lane + 32 * rep;
                    float e0, e1;
                    emb_pair(AH[r * S_A + k2], AL[r * S_A + k2], e0, e1);
                    const int k = 2 * k2;
                    if (n == 0) { ei = fmaf(e0, g1[k], ei); ei = fmaf(e1, g1[k + 1], ei); }
                    ej[n] = fmaf(e0, g2[k], ej[n]);
                    ej[n] = fmaf(e1, g2[k + 1], ej[n]);
                }
            }
            #pragma unroll
            for (int off = 16; off > 0; off >>= 1) {
                ei += __shfl_xor_sync(0xffffffffu, ei, off);
                #pragma unroll
                for (int n = 0; n < NNODE; n++)
                    ej[n] += __shfl_xor_sync(0xffffffffu, ej[n], off);
            }
            if (lane == 0) {
                float ev[5], mx = -1e30f;
                #pragma unroll
                for (int n = 0; n < NNODE; n++) {
                    if (sAdj[lb * NNODE + n] != 0) {
                        float e = ei + ej[n];
                        e = (e >= 0.f) ? e : SLOPE * e;
                        ev[n] = e; mx = fmaxf(mx, e);
                    } else ev[n] = -1e30f;
                }
                float ssum = 0.f;
                #pragma unroll
                for (int n = 0; n < NNODE; n++) {
                    const float p = (ev[n] > -1e29f) ? __expf(ev[n] - mx) : 0.f;
                    ev[n] = p; ssum += p;
                }
                const float inv = 1.f / ssum;
                #pragma unroll
                for (int n = 0; n < NNODE; n++) sSm[2176 + lb * NNODE + n] = ev[n] * inv;
            }
        }
        __syncthreads();

        // s_b = sum_n attn[b,n] * emb[b,n,:]  -> split planes STH/STL
        for (int p = tid; p < 16 * 64; p += NTHREADS) {
            const int lb = p >> 6, k2 = p & 63;
            const float* at = sSm + 2176 + lb * NNODE;
            float s0 = 0.f, s1 = 0.f;
            #pragma unroll
            for (int n = 0; n < NNODE; n++) {
                const int r = lb * NNODE + n;
                float e0, e1;
                emb_pair(AH[r * S_A + k2], AL[r * S_A + k2], e0, e1);
                s0 = fmaf(at[n], e0, s0);
                s1 = fmaf(at[n], e1, s1);
            }
            u32 hi, lo; split2(s0, s1, hi, lo);
            STH[lb * S_ST + k2] = hi;
            STL[lb * S_ST + k2] = lo;
        }
        __syncthreads();

        // h' = s @ gat_w[h]  (16x128x128 split-MMA) -> FT planes (k half h)
        {
            float acc[2][4];
            #pragma unroll
            for (int j = 0; j < 2; j++)
                #pragma unroll
                for (int t = 0; t < 4; t++) acc[j][t] = 0.f;
            gemm16<2>(acc, STH, STL, S_ST, h ? WF_GAT1 : WF_GAT0, wid * 2, lane, 8);
            const int ar = lane >> 2, ac2 = (lane & 3) << 1;
            #pragma unroll
            for (int j = 0; j < 2; j++) {
                const int c = wid * 16 + 8 * j + ac2;
                const int k2f = h * 64 + (c >> 1);
                u32 hi, lo;
                split2(acc[j][0], acc[j][1], hi, lo);
                FTH[ar * S_FT + k2f] = hi;
                FTL[ar * S_FT + k2f] = lo;
                split2(acc[j][2], acc[j][3], hi, lo);
                FTH[(ar + 8) * S_FT + k2f] = hi;
                FTL[(ar + 8) * S_FT + k2f] = lo;
            }
        }
        __syncthreads();
    }

    // ---------- fused value+policy first layers (16x256x128 split-MMA x2) ----------
    {
        const int head = wid >> 2;
        const float* bs = head ? (sSm + 1024) : (sSm + 768);
        float* Ho = Hf + head * BT * HD;
        float acc[4][4];
        #pragma unroll
        for (int j = 0; j < 4; j++)
            #pragma unroll
            for (int t = 0; t < 4; t++) acc[j][t] = 0.f;
        gemm16<4>(acc, FTH, FTL, S_FT, head ? WF_POL : WF_VAL, (wid & 3) * 4, lane, 16);
        const int ar = lane >> 2, ac2 = (lane & 3) << 1;
        #pragma unroll
        for (int j = 0; j < 4; j++) {
            const int c = (wid & 3) * 32 + 8 * j + ac2;
            const float b0v = bs[c], b1v = bs[c + 1];
            float2 v;
            v.x = fmaxf(acc[j][0] + b0v, 0.f);
            v.y = fmaxf(acc[j][1] + b1v, 0.f);
            *reinterpret_cast<float2*>(Ho + ar * HD + c) = v;
            v.x = fmaxf(acc[j][2] + b0v, 0.f);
            v.y = fmaxf(acc[j][3] + b1v, 0.f);
            *reinterpret_cast<float2*>(Ho + (ar + 8) * HD + c) = v;
        }
    }
    __syncthreads();

    // ---------- value = hv @ val_w2 + b ----------
    #pragma unroll
    for (int q = 0; q < 2; q++) {
        const int lb = wid * 2 + q;
        float s = 0.f;
        for (int kk = lane; kk < HD; kk += 32)
            s = fmaf(Hf[lb * HD + kk], sSm[896 + kk], s);
        #pragma unroll
        for (int off = 16; off > 0; off >>= 1) s += __shfl_xor_sync(0xffffffffu, s, off);
        if (lane == 0) out[b0 + lb] = s + sSm[2256];
    }

    // ---------- logits = hp @ pol_w2 + b ----------
    if (tid < BT * NACT) {
        const int lb = tid >> 3, a = tid & 7;
        const float* hp = Hf + BT * HD + lb * HD;
        float s = 0.f;
        for (int kk = 0; kk < HD; kk++)
            s = fmaf(hp[kk], sSm[1152 + kk * NACT + a], s);
        out[NB + (size_t)(b0 + lb) * NACT + a] = s + sSm[2257 + a];
    }
}

extern "C" void kernel_launch(void* const* d_in, const int* in_sizes, int n_in,
                              void* d_out, int out_size)
{
    (void)in_sizes; (void)n_in; (void)out_size;
    cudaFuncSetAttribute(colight, cudaFuncAttributeMaxDynamicSharedMemorySize, SMEM_BYTES);
    prep_wf<<<(WF_TOTAL + 255) / 256, 256>>>(
        (const float*)d_in[3], (const float*)d_in[5], (const float*)d_in[7],
        (const float*)d_in[9], (const float*)d_in[13]);
    colight<<<NB/BT, NTHREADS, SMEM_BYTES>>>(
        (const float*)d_in[0],  (const float*)d_in[1],  (const int*)d_in[2],
        (const float*)d_in[3],  (const float*)d_in[4],  (const float*)d_in[5],
        (const float*)d_in[6],  (const float*)d_in[7],  (const float*)d_in[8],
        (const float*)d_in[9],  (const float*)d_in[10], (const float*)d_in[11],
        (const float*)d_in[12], (const float*)d_in[13], (const float*)d_in[14],
        (const float*)d_in[15], (const float*)d_in[16],
        (float*)d_out);
}

// round 14
// speedup vs baseline: 3.2629x; 1.3385x over previous
#include <cuda_runtime.h>

typedef unsigned int u32;
typedef unsigned long long u64;

#define NB 16384
#define OBS 64
#define HD 128
#define NNODE 5
#define NACT 8
#define SLOPE 0.2f
#define BT 16
#define NTHREADS 256

#define S_A 68      // u32 stride of 80-row A planes (68%32==4 -> conflict-free frags)
#define S_ST 68     // u32 stride of 16-row s planes (per head: 16*S_ST)
#define S_FT 132    // u32 stride of 16-row FT planes (132%32==4)

// ---- smem layout (4-byte word offsets) ----
#define OFF_AH  0        // A hi plane u32[80*68]
#define OFF_AL  5440
#define OFF_FTH 10880    // FT hi plane u32[16*132]
#define OFF_FTL 12992
#define OFF_STH 15104    // s hi planes u32[2][16*68]
#define OFF_STL 17280
#define OFF_SM  19456    // small params (2352 floats):
// 0 enc_b1[128],128 enc_b2[128],256 val_b1[128],384 val_w2[128],512 pol_b1[128],
// 640 pol_w2[1024],1664 attn[2][80],1824 val_b2,1825 pol_b2[8],1840 g[512]
#define OFF_ADJ 21808    // 80 ints
#define SMEM_FLOATS 21888
#define SMEM_BYTES (SMEM_FLOATS*4)   // 87552 B -> 2 CTAs/SM

// ---- precomputed weight-fragment buffer (uint4 per (ntile,kstep,lane)) ----
#define WF_ENC1 0        // K=64:  2048
#define WF_ENC2 2048     // K=128: 4096
#define WF_GAT0 6144
#define WF_GAT1 10240
#define WF_VAL  14336    // K=256: 8192
#define WF_POL  22528
#define WF_TOTAL 30720
__device__ uint4 g_wf[WF_TOTAL];
__device__ float g_g[512];   // g[h][v][d] = sum_k gat_w[h][d][k]*gat_a_v[h][k]

// pack two f32 -> bf16x2, first arg in LOW half
#define CVTP(r, a, b) asm("cvt.rn.bf16x2.f32 %0, %1, %2;" : "=r"(r) : "f"(b), "f"(a))

__device__ __forceinline__ void split2(float v0, float v1, u32& hi, u32& lo) {
    CVTP(hi, v0, v1);
    const float r0 = v0 - __uint_as_float(hi << 16);
    const float r1 = v1 - __uint_as_float(hi & 0xffff0000u);
    CVTP(lo, r0, r1);
}

#define MMA(d, a0, a1, a2, a3, b0, b1) \
    asm volatile("mma.sync.aligned.m16n8k16.row.col.f32.bf16.bf16.f32 " \
        "{%0,%1,%2,%3}, {%4,%5,%6,%7}, {%8,%9}, {%0,%1,%2,%3};" \
        : "+f"((d)[0]), "+f"((d)[1]), "+f"((d)[2]), "+f"((d)[3]) \
        : "r"(a0), "r"(a1), "r"(a2), "r"(a3), "r"(b0), "r"(b1))

// ---- pre-pass: weight fragments + batch-independent g vectors ----
extern "C" __global__ void __launch_bounds__(256)
prep_wf(const float* __restrict__ enc_w1, const float* __restrict__ enc_w2,
        const float* __restrict__ gat_w,  const float* __restrict__ val_w1,
        const float* __restrict__ pol_w1, const float* __restrict__ gat_a)
{
    const int idx = blockIdx.x * 256 + threadIdx.x;
    if (idx >= WF_TOTAL) {
        const int i2 = idx - WF_TOTAL;
        if (i2 < 512) {
            const int hv = i2 >> 7, d = i2 & 127;
            const int h = hv >> 1, v = hv & 1;
            const float* row = gat_w + (size_t)h * HD * HD + (size_t)d * HD;
            const float* av  = gat_a + h * 256 + v * 128;
            float s = 0.f;
            #pragma unroll 8
            for (int k = 0; k < HD; k++) s = fmaf(__ldg(row + k), __ldg(av + k), s);
            g_g[i2] = s;
        }
        return;
    }
    const float* W; int base;
    if      (idx < WF_ENC2) { W = enc_w1;           base = WF_ENC1; }
    else if (idx < WF_GAT0) { W = enc_w2;           base = WF_ENC2; }
    else if (idx < WF_GAT1) { W = gat_w;            base = WF_GAT0; }
    else if (idx < WF_VAL)  { W = gat_w + HD * HD;  base = WF_GAT1; }
    else if (idx < WF_POL)  { W = val_w1;           base = WF_VAL;  }
    else                    { W = pol_w1;           base = WF_POL;  }
    const int r = idx - base;
    const int lane = r & 31, t = (r >> 5) & 15, s = r >> 9;
    const int ar = lane >> 2, ac = lane & 3;
    const int wn = t * 8 + ar;
    const float* p = W + (size_t)(s * 16 + 2 * ac) * HD + wn;
    u32 h0, l0, h1, l1;
    split2(__ldg(p),          __ldg(p + HD),     h0, l0);
    split2(__ldg(p + 8 * HD), __ldg(p + 9 * HD), h1, l1);
    g_wf[idx] = make_uint4(h0, h1, l0, l1);
}

// Split-bf16 MMA gemm: acc[5 m-tiles][2 n-tiles][4] += A(80xK) @ W(Kx128)
__device__ __forceinline__ void run_gemm(float acc[5][2][4],
                                         const u32* __restrict__ AH,
                                         const u32* __restrict__ AL,
                                         int wfbase, int lane, int wid, int KS)
{
    const int ar = lane >> 2, ac = lane & 3;
    for (int s = 0; s < KS; s++) {
        uint4 f[2];
        #pragma unroll
        for (int j = 0; j < 2; j++)
            f[j] = __ldg(&g_wf[wfbase + (s * 16 + 2 * wid + j) * 32 + lane]);
        #pragma unroll
        for (int i = 0; i < 5; i++) {
            const u32* pa = AH + (i * 16 + ar) * S_A + s * 8 + ac;
            const u32* pl = AL + (i * 16 + ar) * S_A + s * 8 + ac;
            const u32 a0 = pa[0], a1 = pa[8 * S_A], a2 = pa[4], a3 = pa[8 * S_A + 4];
            const u32 l0 = pl[0], l1 = pl[8 * S_A], l2 = pl[4], l3 = pl[8 * S_A + 4];
            #pragma unroll
            for (int j = 0; j < 2; j++) {
                MMA(acc[i][j], a0, a1, a2, a3, f[j].x, f[j].y);
                MMA(acc[i][j], a0, a1, a2, a3, f[j].z, f[j].w);
                MMA(acc[i][j], l0, l1, l2, l3, f[j].x, f[j].y);
            }
        }
    }
}

// M=16 split-bf16 MMA gemm: acc[NT][4] += A(16xK planes) @ W, frags from g_wf.
template<int NT>
__device__ __forceinline__ void gemm16(float acc[NT][4],
                                       const u32* __restrict__ AHp,
                                       const u32* __restrict__ ALp, int sa,
                                       int wfbase, int nt0, int lane, int KS)
{
    const int ar = lane >> 2, ac = lane & 3;
    for (int s = 0; s < KS; s++) {
        uint4 f[NT];
        #pragma unroll
        for (int j = 0; j < NT; j++)
            f[j] = __ldg(&g_wf[wfbase + (s * 16 + nt0 + j) * 32 + lane]);
        const u32* pa = AHp + ar * sa + s * 8 + ac;
        const u32* pl = ALp + ar * sa + s * 8 + ac;
        const u32 a0 = pa[0], a1 = pa[8 * sa], a2 = pa[4], a3 = pa[8 * sa + 4];
        const u32 l0 = pl[0], l1 = pl[8 * sa], l2 = pl[4], l3 = pl[8 * sa + 4];
        #pragma unroll
        for (int j = 0; j < NT; j++) {
            MMA(acc[j], a0, a1, a2, a3, f[j].x, f[j].y);
            MMA(acc[j], a0, a1, a2, a3, f[j].z, f[j].w);
            MMA(acc[j], l0, l1, l2, l3, f[j].x, f[j].y);
        }
    }
}

// D-frags -> bf16 hi/lo A planes (+bias, optional relu), 5 m-tiles
__device__ __forceinline__ void store_split(const float acc[5][2][4],
                                            u32* __restrict__ AH, u32* __restrict__ AL,
                                            const float* __restrict__ bias, bool relu,
                                            int lane, int n0)
{
    const int ar = lane >> 2, ac2 = (lane & 3) << 1;
    #pragma unroll
    for (int i = 0; i < 5; i++)
        #pragma unroll
        for (int j = 0; j < 2; j++) {
            const int c = n0 + 8 * j + ac2;
            const float b0v = bias[c], b1v = bias[c + 1];
            float v0 = acc[i][j][0] + b0v, v1 = acc[i][j][1] + b1v;
            if (relu) { v0 = fmaxf(v0, 0.f); v1 = fmaxf(v1, 0.f); }
            u32 hi, lo; split2(v0, v1, hi, lo);
            const int r0 = i * 16 + ar;
            AH[r0 * S_A + (c >> 1)] = hi;
            AL[r0 * S_A + (c >> 1)] = lo;
            float v2 = acc[i][j][2] + b0v, v3 = acc[i][j][3] + b1v;
            if (relu) { v2 = fmaxf(v2, 0.f); v3 = fmaxf(v3, 0.f); }
            split2(v2, v3, hi, lo);
            AH[(r0 + 8) * S_A + (c >> 1)] = hi;
            AL[(r0 + 8) * S_A + (c >> 1)] = lo;
        }
}

__device__ __forceinline__ void emb_pair(u32 h, u32 l, float& e0, float& e1) {
    e0 = __uint_as_float(h << 16) + __uint_as_float(l << 16);
    e1 = __uint_as_float(h & 0xffff0000u) + __uint_as_float(l & 0xffff0000u);
}

extern "C" __global__ void __launch_bounds__(NTHREADS, 2)
colight(const float* __restrict__ obs, const float* __restrict__ nobs,
        const int* __restrict__ adj,
        const float* __restrict__ enc_w1, const float* __restrict__ enc_b1,
        const float* __restrict__ enc_w2, const float* __restrict__ enc_b2,
        const float* __restrict__ gat_w, const float* __restrict__ gat_a,
        const float* __restrict__ val_w1, const float* __restrict__ val_b1,
        const float* __restrict__ val_w2, const float* __restrict__ val_b2,
        const float* __restrict__ pol_w1, const float* __restrict__ pol_b1,
        const float* __restrict__ pol_w2, const float* __restrict__ pol_b2,
        float* __restrict__ out)
{
    extern __shared__ float sm[];
    u32*   AH  = reinterpret_cast<u32*>(sm + OFF_AH);
    u32*   AL  = reinterpret_cast<u32*>(sm + OFF_AL);
    u32*   FTH = reinterpret_cast<u32*>(sm + OFF_FTH);
    u32*   FTL = reinterpret_cast<u32*>(sm + OFF_FTL);
    u32*   STH = reinterpret_cast<u32*>(sm + OFF_STH);
    u32*   STL = reinterpret_cast<u32*>(sm + OFF_STL);
    float* sSm = sm + OFF_SM;
    int*   sAdj = reinterpret_cast<int*>(sm + OFF_ADJ);
    float* Hf  = sm + OFF_AH;   // head-MLP output reuses A region (emb dead by then)

    const int tid = threadIdx.x;
    const int b0  = blockIdx.x * BT;
    const int wid = tid >> 5, lane = tid & 31;
    const int n0  = wid * 16;

    // ---------- init ----------
    for (int idx = tid; idx < HD; idx += NTHREADS) {
        sSm[idx]        = enc_b1[idx];
        sSm[128 + idx]  = enc_b2[idx];
        sSm[256 + idx]  = val_b1[idx];
        sSm[384 + idx]  = val_w2[idx];
        sSm[512 + idx]  = pol_b1[idx];
    }
    for (int idx = tid; idx < 1024; idx += NTHREADS) sSm[640 + idx]  = pol_w2[idx];
    for (int idx = tid; idx < 512;  idx += NTHREADS) sSm[1840 + idx] = g_g[idx];
    if (tid < BT * NNODE) sAdj[tid] = adj[(size_t)b0 * NNODE + tid];
    if (tid == 0) sSm[1824] = val_b2[0];
    if (tid < NACT) sSm[1825 + tid] = pol_b2[tid];

    for (int p = tid; p < 80 * 32; p += NTHREADS) {
        const int r = p >> 5, k2 = p & 31;
        const int lb = r / NNODE, n = r - lb * NNODE;
        const float* src = (n == 0) ? obs + (size_t)(b0 + lb) * OBS + 2 * k2
                                    : nobs + ((size_t)(b0 + lb) * 4 + (n - 1)) * OBS + 2 * k2;
        const float2 v = __ldg(reinterpret_cast<const float2*>(src));
        u32 hi, lo; split2(v.x, v.y, hi, lo);
        AH[r * S_A + k2] = hi;
        AL[r * S_A + k2] = lo;
    }
    __syncthreads();

    // ---------- encoder layer 1 ----------
    {
        float acc[5][2][4];
        #pragma unroll
        for (int i = 0; i < 5; i++)
            #pragma unroll
            for (int j = 0; j < 2; j++)
                #pragma unroll
                for (int t = 0; t < 4; t++) acc[i][j][t] = 0.f;
        run_gemm(acc, AH, AL, WF_ENC1, lane, wid, 4);
        __syncthreads();
        store_split(acc, AH, AL, sSm, true, lane, n0);
    }
    __syncthreads();

    // ---------- encoder layer 2 ----------
    {
        float acc[5][2][4];
        #pragma unroll
        for (int i = 0; i < 5; i++)
            #pragma unroll
            for (int j = 0; j < 2; j++)
                #pragma unroll
                for (int t = 0; t < 4; t++) acc[i][j][t] = 0.f;
        run_gemm(acc, AH, AL, WF_ENC2, lane, wid, 8);
        __syncthreads();
        store_split(acc, AH, AL, sSm + 128, false, lane, n0);
    }
    __syncthreads();

    // ---------- GAT: both heads in parallel (warps 0-3 head0, 4-7 head1) ----------
    {
        const int head = wid >> 2;
        const float* g1 = sSm + 1840 + head * 256;
        const float* g2 = g1 + 128;
        #pragma unroll
        for (int q = 0; q < 4; q++) {
            const int lb = (wid & 3) * 4 + q;
            float ei = 0.f, ej[5] = {0.f, 0.f, 0.f, 0.f, 0.f};
            #pragma unroll
            for (int n = 0; n < NNODE; n++) {
                const int r = lb * NNODE + n;
                #pragma unroll
                for (int rep = 0; rep < 2; rep++) {
                    const int k2 = lane + 32 * rep;
                    float e0, e1;
                    emb_pair(AH[r * S_A + k2], AL[r * S_A + k2], e0, e1);
                    const int k = 2 * k2;
                    if (n == 0) { ei = fmaf(e0, g1[k], ei); ei = fmaf(e1, g1[k + 1], ei); }
                    ej[n] = fmaf(e0, g2[k], ej[n]);
                    ej[n] = fmaf(e1, g2[k + 1], ej[n]);
                }
            }
            #pragma unroll
            for (int off = 16; off > 0; off >>= 1) {
                ei += __shfl_xor_sync(0xffffffffu, ei, off);
                #pragma unroll
                for (int n = 0; n < NNODE; n++)
                    ej[n] += __shfl_xor_sync(0xffffffffu, ej[n], off);
            }
            if (lane == 0) {
                float ev[5], mx = -1e30f;
                #pragma unroll
                for (int n = 0; n < NNODE; n++) {
                    if (sAdj[lb * NNODE + n] != 0) {
                        float e = ei + ej[n];
                        e = (e >= 0.f) ? e : SLOPE * e;
                        ev[n] = e; mx = fmaxf(mx, e);
                    } else ev[n] = -1e30f;
                }
                float ssum = 0.f;
                #pragma unroll
                for (int n = 0; n < NNODE; n++) {
                    const float p = (ev[n] > -1e29f) ? __expf(ev[n] - mx) : 0.f;
                    ev[n] = p; ssum += p;
                }
                const float inv = 1.f / ssum;
                #pragma unroll
                for (int n = 0; n < NNODE; n++)
                    sSm[1664 + head * 80 + lb * NNODE + n] = ev[n] * inv;
            }
        }
    }
    __syncthreads();

    // ---------- s_b = sum_n attn * emb (both heads; threads split by head) ----------
    {
        const int hh = tid >> 7, t = tid & 127;
        for (int p = t; p < 16 * 64; p += 128) {
            const int lb = p >> 6, k2 = p & 63;
            const float* at = sSm + 1664 + hh * 80 + lb * NNODE;
            float s0 = 0.f, s1 = 0.f;
            #pragma unroll
            for (int n = 0; n < NNODE; n++) {
                const int r = lb * NNODE + n;
                float e0, e1;
                emb_pair(AH[r * S_A + k2], AL[r * S_A + k2], e0, e1);
                s0 = fmaf(at[n], e0, s0);
                s1 = fmaf(at[n], e1, s1);
            }
            u32 hi, lo; split2(s0, s1, hi, lo);
            STH[hh * 16 * S_ST + lb * S_ST + k2] = hi;
            STL[hh * 16 * S_ST + lb * S_ST + k2] = lo;
        }
    }
    __syncthreads();

    // ---------- h' = s @ gat_w[head] (both heads; warps split) -> FT ----------
    {
        const int head = wid >> 2, lw = wid & 3;
        float acc[4][4];
        #pragma unroll
        for (int j = 0; j < 4; j++)
            #pragma unroll
            for (int t = 0; t < 4; t++) acc[j][t] = 0.f;
        gemm16<4>(acc, STH + head * 16 * S_ST, STL + head * 16 * S_ST, S_ST,
                  head ? WF_GAT1 : WF_GAT0, lw * 4, lane, 8);
        const int ar = lane >> 2, ac2 = (lane & 3) << 1;
        #pragma unroll
        for (int j = 0; j < 4; j++) {
            const int c = (lw * 4 + j) * 8 + ac2;
            const int k2f = head * 64 + (c >> 1);
            u32 hi, lo;
            split2(acc[j][0], acc[j][1], hi, lo);
            FTH[ar * S_FT + k2f] = hi;
            FTL[ar * S_FT + k2f] = lo;
            split2(acc[j][2], acc[j][3], hi, lo);
            FTH[(ar + 8) * S_FT + k2f] = hi;
            FTL[(ar + 8) * S_FT + k2f] = lo;
        }
    }
    __syncthreads();

    // ---------- fused value+policy first layers (16x256x128 split-MMA x2) ----------
    {
        const int head = wid >> 2;
        const float* bs = head ? (sSm + 512) : (sSm + 256);
        float* Ho = Hf + head * BT * HD;
        float acc[4][4];
        #pragma unroll
        for (int j = 0; j < 4; j++)
            #pragma unroll
            for (int t = 0; t < 4; t++) acc[j][t] = 0.f;
        gemm16<4>(acc, FTH, FTL, S_FT, head ? WF_POL : WF_VAL, (wid & 3) * 4, lane, 16);
        const int ar = lane >> 2, ac2 = (lane & 3) << 1;
        #pragma unroll
        for (int j = 0; j < 4; j++) {
            const int c = (wid & 3) * 32 + 8 * j + ac2;
            const float b0v = bs[c], b1v = bs[c + 1];
            float2 v;
            v.x = fmaxf(acc[j][0] + b0v, 0.f);
            v.y = fmaxf(acc[j][1] + b1v, 0.f);
            *reinterpret_cast<float2*>(Ho + ar * HD + c) = v;
            v.x = fmaxf(acc[j][2] + b0v, 0.f);
            v.y = fmaxf(acc[j][3] + b1v, 0.f);
            *reinterpret_cast<float2*>(Ho + (ar + 8) * HD + c) = v;
        }
    }
    __syncthreads();

    // ---------- value = hv @ val_w2 + b ----------
    #pragma unroll
    for (int q = 0; q < 2; q++) {
        const int lb = wid * 2 + q;
        float s = 0.f;
        for (int kk = lane; kk < HD; kk += 32)
            s = fmaf(Hf[lb * HD + kk], sSm[384 + kk], s);
        #pragma unroll
        for (int off = 16; off > 0; off >>= 1) s += __shfl_xor_sync(0xffffffffu, s, off);
        if (lane == 0) out[b0 + lb] = s + sSm[1824];
    }

    // ---------- logits = hp @ pol_w2 + b ----------
    if (tid < BT * NACT) {
        const int lb = tid >> 3, a = tid & 7;
        const float* hp = Hf + BT * HD + lb * HD;
        float s = 0.f;
        for (int kk = 0; kk < HD; kk++)
            s = fmaf(hp[kk], sSm[640 + kk * NACT + a], s);
        out[NB + (size_t)(b0 + lb) * NACT + a] = s + sSm[1825 + a];
    }
}

extern "C" void kernel_launch(void* const* d_in, const int* in_sizes, int n_in,
                              void* d_out, int out_size)
{
    (void)in_sizes; (void)n_in; (void)out_size;
    cudaFuncSetAttribute(colight, cudaFuncAttributeMaxDynamicSharedMemorySize, SMEM_BYTES);
    prep_wf<<<(WF_TOTAL + 512 + 255) / 256, 256>>>(
        (const float*)d_in[3], (const float*)d_in[5], (const float*)d_in[7],
        (const float*)d_in[9], (const float*)d_in[13], (const float*)d_in[8]);
    colight<<<NB/BT, NTHREADS, SMEM_BYTES>>>(
        (const float*)d_in[0],  (const float*)d_in[1],  (const int*)d_in[2],
        (const float*)d_in[3],  (const float*)d_in[4],  (const float*)d_in[5],
        (const float*)d_in[6],  (const float*)d_in[7],  (const float*)d_in[8],
        (const float*)d_in[9],  (const float*)d_in[10], (const float*)d_in[11],
        (const float*)d_in[12], (const float*)d_in[13], (const float*)d_in[14],
        (const float*)d_in[15], (const float*)d_in[16],
        (float*)d_out);
}

// round 15
// speedup vs baseline: 3.3355x; 1.0222x over previous
#include <cuda_runtime.h>

typedef unsigned int u32;
typedef unsigned long long u64;

#define NB 16384
#define OBS 64
#define HD 128
#define NNODE 5
#define NACT 8
#define SLOPE 0.2f
#define BT 16
#define NTHREADS 256

#define S_A 68      // u32 stride of 80-row A planes (68%32==4 -> conflict-free)
#define S_ST 68     // u32 stride of 16-row s planes (per head: 16*S_ST)
#define S_FT 132    // u32 stride of 16-row FT planes (132%32==4)

// ---- smem layout (4-byte word offsets) ----
#define OFF_AH  0        // A hi plane u32[80*68]
#define OFF_AL  5440
#define OFF_FTH 10880    // FT hi plane u32[16*132]
#define OFF_FTL 12992
#define OFF_STH 15104    // s hi planes u32[2][16*68]
#define OFF_STL 17280
#define OFF_SM  19456    // small params (2352 floats):
// 0 enc_b1[128],128 enc_b2[128],256 val_b1[128],384 val_w2[128],512 pol_b1[128],
// 640 pol_w2[1024],1664 attn[2][80],1824 val_b2,1825 pol_b2[8],1840 g[512]
#define OFF_ADJ 21808    // 80 ints
#define SMEM_FLOATS 21888
#define SMEM_BYTES (SMEM_FLOATS*4)   // 87552 B -> 2 CTAs/SM

// ---- precomputed weight-fragment buffer (uint4 per (ntile,kstep,lane)) ----
#define WF_ENC1 0        // K=64:  2048
#define WF_ENC2 2048     // K=128: 4096
#define WF_GAT0 6144
#define WF_GAT1 10240
#define WF_VAL  14336    // K=256: 8192
#define WF_POL  22528
#define WF_TOTAL 30720
__device__ uint4 g_wf[WF_TOTAL];
__device__ float g_g[512];   // g[h][v][d] = sum_k gat_w[h][d][k]*gat_a_v[h][k]

// pack two f32 -> bf16x2, first arg in LOW half
#define CVTP(r, a, b) asm("cvt.rn.bf16x2.f32 %0, %1, %2;" : "=r"(r) : "f"(b), "f"(a))

__device__ __forceinline__ void split2(float v0, float v1, u32& hi, u32& lo) {
    CVTP(hi, v0, v1);
    const float r0 = v0 - __uint_as_float(hi << 16);
    const float r1 = v1 - __uint_as_float(hi & 0xffff0000u);
    CVTP(lo, r0, r1);
}

#define MMA(d, a0, a1, a2, a3, b0, b1) \
    asm volatile("mma.sync.aligned.m16n8k16.row.col.f32.bf16.bf16.f32 " \
        "{%0,%1,%2,%3}, {%4,%5,%6,%7}, {%8,%9}, {%0,%1,%2,%3};" \
        : "+f"((d)[0]), "+f"((d)[1]), "+f"((d)[2]), "+f"((d)[3]) \
        : "r"(a0), "r"(a1), "r"(a2), "r"(a3), "r"(b0), "r"(b1))

#define LDSM4(r0, r1, r2, r3, addr) \
    asm volatile("ldmatrix.sync.aligned.m8n8.x4.shared.b16 {%0,%1,%2,%3}, [%4];" \
        : "=r"(r0), "=r"(r1), "=r"(r2), "=r"(r3) : "r"(addr))

__device__ __forceinline__ u32 smem_u32(const void* p) {
    u32 a;
    asm("{ .reg .u64 t; cvta.to.shared.u64 t, %1; cvt.u32.u64 %0, t; }" : "=r"(a) : "l"(p));
    return a;
}

// ---- pre-pass: weight fragments + batch-independent g vectors ----
extern "C" __global__ void __launch_bounds__(256)
prep_wf(const float* __restrict__ enc_w1, const float* __restrict__ enc_w2,
        const float* __restrict__ gat_w,  const float* __restrict__ val_w1,
        const float* __restrict__ pol_w1, const float* __restrict__ gat_a)
{
    const int idx = blockIdx.x * 256 + threadIdx.x;
    if (idx >= WF_TOTAL) {
        const int i2 = idx - WF_TOTAL;
        if (i2 < 512) {
            const int hv = i2 >> 7, d = i2 & 127;
            const int h = hv >> 1, v = hv & 1;
            const float* row = gat_w + (size_t)h * HD * HD + (size_t)d * HD;
            const float* av  = gat_a + h * 256 + v * 128;
            float s = 0.f;
            #pragma unroll 8
            for (int k = 0; k < HD; k++) s = fmaf(__ldg(row + k), __ldg(av + k), s);
            g_g[i2] = s;
        }
        return;
    }
    const float* W; int base;
    if      (idx < WF_ENC2) { W = enc_w1;           base = WF_ENC1; }
    else if (idx < WF_GAT0) { W = enc_w2;           base = WF_ENC2; }
    else if (idx < WF_GAT1) { W = gat_w;            base = WF_GAT0; }
    else if (idx < WF_VAL)  { W = gat_w + HD * HD;  base = WF_GAT1; }
    else if (idx < WF_POL)  { W = val_w1;           base = WF_VAL;  }
    else                    { W = pol_w1;           base = WF_POL;  }
    const int r = idx - base;
    const int lane = r & 31, t = (r >> 5) & 15, s = r >> 9;
    const int ar = lane >> 2, ac = lane & 3;
    const int wn = t * 8 + ar;
    const float* p = W + (size_t)(s * 16 + 2 * ac) * HD + wn;
    u32 h0, l0, h1, l1;
    split2(__ldg(p),          __ldg(p + HD),     h0, l0);
    split2(__ldg(p + 8 * HD), __ldg(p + 9 * HD), h1, l1);
    g_wf[idx] = make_uint4(h0, h1, l0, l1);
}

// Split-bf16 MMA gemm: acc[5 m-tiles][2 n-tiles][4] += A(80xK) @ W(Kx128)
// A fragments via ldmatrix.x4 from hi/lo planes (u32 smem addresses).
__device__ __forceinline__ void run_gemm(float acc[5][2][4],
                                         u32 uAH, u32 uAL,
                                         int wfbase, int lane, int wid, int KS)
{
    const int ln = lane & 15;
    const u32 kh = (u32)((lane >> 4) << 4);     // 0 or 16 bytes (k words +4)
    u32 ah[5], al[5];
    #pragma unroll
    for (int i = 0; i < 5; i++) {
        const u32 off = (u32)((16 * i + ln) * S_A) * 4u + kh;
        ah[i] = uAH + off;
        al[i] = uAL + off;
    }
    for (int s = 0; s < KS; s++) {
        uint4 f[2];
        #pragma unroll
        for (int j = 0; j < 2; j++)
            f[j] = __ldg(&g_wf[wfbase + (s * 16 + 2 * wid + j) * 32 + lane]);
        #pragma unroll
        for (int i = 0; i < 5; i++) {
            u32 a0, a1, a2, a3, l0, l1, l2, l3;
            LDSM4(a0, a1, a2, a3, ah[i] + (u32)s * 32u);
            LDSM4(l0, l1, l2, l3, al[i] + (u32)s * 32u);
            #pragma unroll
            for (int j = 0; j < 2; j++) {
                MMA(acc[i][j], a0, a1, a2, a3, f[j].x, f[j].y);
                MMA(acc[i][j], a0, a1, a2, a3, f[j].z, f[j].w);
                MMA(acc[i][j], l0, l1, l2, l3, f[j].x, f[j].y);
            }
        }
    }
}

// M=16 split-bf16 MMA gemm: acc[NT][4] += A(16xK planes) @ W, frags from g_wf.
template<int NT>
__device__ __forceinline__ void gemm16(float acc[NT][4],
                                       u32 uAH, u32 uAL, int sa,
                                       int wfbase, int nt0, int lane, int KS)
{
    const int ln = lane & 15;
    const u32 kh = (u32)((lane >> 4) << 4);
    const u32 off = (u32)(ln * sa) * 4u + kh;
    const u32 ah = uAH + off, al = uAL + off;
    for (int s = 0; s < KS; s++) {
        uint4 f[NT];
        #pragma unroll
        for (int j = 0; j < NT; j++)
            f[j] = __ldg(&g_wf[wfbase + (s * 16 + nt0 + j) * 32 + lane]);
        u32 a0, a1, a2, a3, l0, l1, l2, l3;
        LDSM4(a0, a1, a2, a3, ah + (u32)s * 32u);
        LDSM4(l0, l1, l2, l3, al + (u32)s * 32u);
        #pragma unroll
        for (int j = 0; j < NT; j++) {
            MMA(acc[j], a0, a1, a2, a3, f[j].x, f[j].y);
            MMA(acc[j], a0, a1, a2, a3, f[j].z, f[j].w);
            MMA(acc[j], l0, l1, l2, l3, f[j].x, f[j].y);
        }
    }
}

// D-frags -> bf16 hi/lo A planes (+bias, optional relu), 5 m-tiles
__device__ __forceinline__ void store_split(const float acc[5][2][4],
                                            u32* __restrict__ AH, u32* __restrict__ AL,
                                            const float* __restrict__ bias, bool relu,
                                            int lane, int n0)
{
    const int ar = lane >> 2, ac2 = (lane & 3) << 1;
    #pragma unroll
    for (int i = 0; i < 5; i++)
        #pragma unroll
        for (int j = 0; j < 2; j++) {
            const int c = n0 + 8 * j + ac2;
            const float b0v = bias[c], b1v = bias[c + 1];
            float v0 = acc[i][j][0] + b0v, v1 = acc[i][j][1] + b1v;
            if (relu) { v0 = fmaxf(v0, 0.f); v1 = fmaxf(v1, 0.f); }
            u32 hi, lo; split2(v0, v1, hi, lo);
            const int r0 = i * 16 + ar;
            AH[r0 * S_A + (c >> 1)] = hi;
            AL[r0 * S_A + (c >> 1)] = lo;
            float v2 = acc[i][j][2] + b0v, v3 = acc[i][j][3] + b1v;
            if (relu) { v2 = fmaxf(v2, 0.f); v3 = fmaxf(v3, 0.f); }
            split2(v2, v3, hi, lo);
            AH[(r0 + 8) * S_A + (c >> 1)] = hi;
            AL[(r0 + 8) * S_A + (c >> 1)] = lo;
        }
}

__device__ __forceinline__ void emb_pair(u32 h, u32 l, float& e0, float& e1) {
    e0 = __uint_as_float(h << 16) + __uint_as_float(l << 16);
    e1 = __uint_as_float(h & 0xffff0000u) + __uint_as_float(l & 0xffff0000u);
}

extern "C" __global__ void __launch_bounds__(NTHREADS, 2)
colight(const float* __restrict__ obs, const float* __restrict__ nobs,
        const int* __restrict__ adj,
        const float* __restrict__ enc_w1, const float* __restrict__ enc_b1,
        const float* __restrict__ enc_w2, const float* __restrict__ enc_b2,
        const float* __restrict__ gat_w, const float* __restrict__ gat_a,
        const float* __restrict__ val_w1, const float* __restrict__ val_b1,
        const float* __restrict__ val_w2, const float* __restrict__ val_b2,
        const float* __restrict__ pol_w1, const float* __restrict__ pol_b1,
        const float* __restrict__ pol_w2, const float* __restrict__ pol_b2,
        float* __restrict__ out)
{
    extern __shared__ float sm[];
    u32*   AH  = reinterpret_cast<u32*>(sm + OFF_AH);
    u32*   AL  = reinterpret_cast<u32*>(sm + OFF_AL);
    u32*   FTH = reinterpret_cast<u32*>(sm + OFF_FTH);
    u32*   FTL = reinterpret_cast<u32*>(sm + OFF_FTL);
    u32*   STH = reinterpret_cast<u32*>(sm + OFF_STH);
    u32*   STL = reinterpret_cast<u32*>(sm + OFF_STL);
    float* sSm = sm + OFF_SM;
    int*   sAdj = reinterpret_cast<int*>(sm + OFF_ADJ);
    float* Hf  = sm + OFF_AH;   // head-MLP output reuses A region (emb dead by then)

    const int tid = threadIdx.x;
    const int b0  = blockIdx.x * BT;
    const int wid = tid >> 5, lane = tid & 31;
    const int n0  = wid * 16;

    const u32 usm  = smem_u32(sm);
    const u32 uAH  = usm + OFF_AH  * 4, uAL  = usm + OFF_AL  * 4;
    const u32 uFTH = usm + OFF_FTH * 4, uFTL = usm + OFF_FTL * 4;
    const u32 uSTH = usm + OFF_STH * 4, uSTL = usm + OFF_STL * 4;

    // ---------- init ----------
    for (int idx = tid; idx < HD; idx += NTHREADS) {
        sSm[idx]        = enc_b1[idx];
        sSm[128 + idx]  = enc_b2[idx];
        sSm[256 + idx]  = val_b1[idx];
        sSm[384 + idx]  = val_w2[idx];
        sSm[512 + idx]  = pol_b1[idx];
    }
    for (int idx = tid; idx < 1024; idx += NTHREADS) sSm[640 + idx]  = pol_w2[idx];
    for (int idx = tid; idx < 512;  idx += NTHREADS) sSm[1840 + idx] = g_g[idx];
    if (tid < BT * NNODE) sAdj[tid] = adj[(size_t)b0 * NNODE + tid];
    if (tid == 0) sSm[1824] = val_b2[0];
    if (tid < NACT) sSm[1825 + tid] = pol_b2[tid];

    for (int p = tid; p < 80 * 32; p += NTHREADS) {
        const int r = p >> 5, k2 = p & 31;
        const int lb = r / NNODE, n = r - lb * NNODE;
        const float* src = (n == 0) ? obs + (size_t)(b0 + lb) * OBS + 2 * k2
                                    : nobs + ((size_t)(b0 + lb) * 4 + (n - 1)) * OBS + 2 * k2;
        const float2 v = __ldg(reinterpret_cast<const float2*>(src));
        u32 hi, lo; split2(v.x, v.y, hi, lo);
        AH[r * S_A + k2] = hi;
        AL[r * S_A + k2] = lo;
    }
    __syncthreads();

    // ---------- encoder layer 1 ----------
    {
        float acc[5][2][4];
        #pragma unroll
        for (int i = 0; i < 5; i++)
            #pragma unroll
            for (int j = 0; j < 2; j++)
                #pragma unroll
                for (int t = 0; t < 4; t++) acc[i][j][t] = 0.f;
        run_gemm(acc, uAH, uAL, WF_ENC1, lane, wid, 4);
        __syncthreads();
        store_split(acc, AH, AL, sSm, true, lane, n0);
    }
    __syncthreads();

    // ---------- encoder layer 2 ----------
    {
        float acc[5][2][4];
        #pragma unroll
        for (int i = 0; i < 5; i++)
            #pragma unroll
            for (int j = 0; j < 2; j++)
                #pragma unroll
                for (int t = 0; t < 4; t++) acc[i][j][t] = 0.f;
        run_gemm(acc, uAH, uAL, WF_ENC2, lane, wid, 8);
        __syncthreads();
        store_split(acc, AH, AL, sSm + 128, false, lane, n0);
    }
    __syncthreads();

    // ---------- GAT: both heads in parallel (warps 0-3 head0, 4-7 head1) ----------
    {
        const int head = wid >> 2;
        const float* g1 = sSm + 1840 + head * 256;
        const float* g2 = g1 + 128;
        #pragma unroll
        for (int q = 0; q < 4; q++) {
            const int lb = (wid & 3) * 4 + q;
            float ei = 0.f, ej[5] = {0.f, 0.f, 0.f, 0.f, 0.f};
            #pragma unroll
            for (int n = 0; n < NNODE; n++) {
                const int r = lb * NNODE + n;
                #pragma unroll
                for (int rep = 0; rep < 2; rep++) {
                    const int k2 = lane + 32 * rep;
                    float e0, e1;
                    emb_pair(AH[r * S_A + k2], AL[r * S_A + k2], e0, e1);
                    const int k = 2 * k2;
                    if (n == 0) { ei = fmaf(e0, g1[k], ei); ei = fmaf(e1, g1[k + 1], ei); }
                    ej[n] = fmaf(e0, g2[k], ej[n]);
                    ej[n] = fmaf(e1, g2[k + 1], ej[n]);
                }
            }
            #pragma unroll
            for (int off = 16; off > 0; off >>= 1) {
                ei += __shfl_xor_sync(0xffffffffu, ei, off);
                #pragma unroll
                for (int n = 0; n < NNODE; n++)
                    ej[n] += __shfl_xor_sync(0xffffffffu, ej[n], off);
            }
            if (lane == 0) {
                float ev[5], mx = -1e30f;
                #pragma unroll
                for (int n = 0; n < NNODE; n++) {
                    if (sAdj[lb * NNODE + n] != 0) {
                        float e = ei + ej[n];
                        e = (e >= 0.f) ? e : SLOPE * e;
                        ev[n] = e; mx = fmaxf(mx, e);
                    } else ev[n] = -1e30f;
                }
                float ssum = 0.f;
                #pragma unroll
                for (int n = 0; n < NNODE; n++) {
                    const float p = (ev[n] > -1e29f) ? __expf(ev[n] - mx) : 0.f;
                    ev[n] = p; ssum += p;
                }
                const float inv = 1.f / ssum;
                #pragma unroll
                for (int n = 0; n < NNODE; n++)
                    sSm[1664 + head * 80 + lb * NNODE + n] = ev[n] * inv;
            }
        }
    }
    __syncthreads();

    // ---------- s_b = sum_n attn * emb (both heads; threads split by head) ----------
    {
        const int hh = tid >> 7, t = tid & 127;
        for (int p = t; p < 16 * 64; p += 128) {
            const int lb = p >> 6, k2 = p & 63;
            const float* at = sSm + 1664 + hh * 80 + lb * NNODE;
            float s0 = 0.f, s1 = 0.f;
            #pragma unroll
            for (int n = 0; n < NNODE; n++) {
                const int r = lb * NNODE + n;
                float e0, e1;
                emb_pair(AH[r * S_A + k2], AL[r * S_A + k2], e0, e1);
                s0 = fmaf(at[n], e0, s0);
                s1 = fmaf(at[n], e1, s1);
            }
            u32 hi, lo; split2(s0, s1, hi, lo);
            STH[hh * 16 * S_ST + lb * S_ST + k2] = hi;
            STL[hh * 16 * S_ST + lb * S_ST + k2] = lo;
        }
    }
    __syncthreads();

    // ---------- h' = s @ gat_w[head] (both heads; warps split) -> FT ----------
    {
        const int head = wid >> 2, lw = wid & 3;
        float acc[4][4];
        #pragma unroll
        for (int j = 0; j < 4; j++)
            #pragma unroll
            for (int t = 0; t < 4; t++) acc[j][t] = 0.f;
        gemm16<4>(acc, uSTH + head * 16 * S_ST * 4, uSTL + head * 16 * S_ST * 4, S_ST,
                  head ? WF_GAT1 : WF_GAT0, lw * 4, lane, 8);
        const int ar = lane >> 2, ac2 = (lane & 3) << 1;
        #pragma unroll
        for (int j = 0; j < 4; j++) {
            const int c = (lw * 4 + j) * 8 + ac2;
            const int k2f = head * 64 + (c >> 1);
            u32 hi, lo;
            split2(acc[j][0], acc[j][1], hi, lo);
            FTH[ar * S_FT + k2f] = hi;
            FTL[ar * S_FT + k2f] = lo;
            split2(acc[j][2], acc[j][3], hi, lo);
            FTH[(ar + 8) * S_FT + k2f] = hi;
            FTL[(ar + 8) * S_FT + k2f] = lo;
        }
    }
    __syncthreads();

    // ---------- fused value+policy first layers (16x256x128 split-MMA x2) ----------
    {
        const int head = wid >> 2;
        const float* bs = head ? (sSm + 512) : (sSm + 256);
        float* Ho = Hf + head * BT * HD;
        float acc[4][4];
        #pragma unroll
        for (int j = 0; j < 4; j++)
            #pragma unroll
            for (int t = 0; t < 4; t++) acc[j][t] = 0.f;
        gemm16<4>(acc, uFTH, uFTL, S_FT, head ? WF_POL : WF_VAL, (wid & 3) * 4, lane, 16);
        const int ar = lane >> 2, ac2 = (lane & 3) << 1;
        #pragma unroll
        for (int j = 0; j < 4; j++) {
            const int c = (wid & 3) * 32 + 8 * j + ac2;
            const float b0v = bs[c], b1v = bs[c + 1];
            float2 v;
            v.x = fmaxf(acc[j][0] + b0v, 0.f);
            v.y = fmaxf(acc[j][1] + b1v, 0.f);
            *reinterpret_cast<float2*>(Ho + ar * HD + c) = v;
            v.x = fmaxf(acc[j][2] + b0v, 0.f);
            v.y = fmaxf(acc[j][3] + b1v, 0.f);
            *reinterpret_cast<float2*>(Ho + (ar + 8) * HD + c) = v;
        }
    }
    __syncthreads();

    // ---------- value = hv @ val_w2 + b ----------
    #pragma unroll
    for (int q = 0; q < 2; q++) {
        const int lb = wid * 2 + q;
        float s = 0.f;
        for (int kk = lane; kk < HD; kk += 32)
            s = fmaf(Hf[lb * HD + kk], sSm[384 + kk], s);
        #pragma unroll
        for (int off = 16; off > 0; off >>= 1) s += __shfl_xor_sync(0xffffffffu, s, off);
        if (lane == 0) out[b0 + lb] = s + sSm[1824];
    }

    // ---------- logits = hp @ pol_w2 + b ----------
    if (tid < BT * NACT) {
        const int lb = tid >> 3, a = tid & 7;
        const float* hp = Hf + BT * HD + lb * HD;
        float s = 0.f;
        for (int kk = 0; kk < HD; kk++)
            s = fmaf(hp[kk], sSm[640 + kk * NACT + a], s);
        out[NB + (size_t)(b0 + lb) * NACT + a] = s + sSm[1825 + a];
    }
}

extern "C" void kernel_launch(void* const* d_in, const int* in_sizes, int n_in,
                              void* d_out, int out_size)
{
    (void)in_sizes; (void)n_in; (void)out_size;
    cudaFuncSetAttribute(colight, cudaFuncAttributeMaxDynamicSharedMemorySize, SMEM_BYTES);
    prep_wf<<<(WF_TOTAL + 512 + 255) / 256, 256>>>(
        (const float*)d_in[3], (const float*)d_in[5], (const float*)d_in[7],
        (const float*)d_in[9], (const float*)d_in[13], (const float*)d_in[8]);
    colight<<<NB/BT, NTHREADS, SMEM_BYTES>>>(
        (const float*)d_in[0],  (const float*)d_in[1],  (const int*)d_in[2],
        (const float*)d_in[3],  (const float*)d_in[4],  (const float*)d_in[5],
        (const float*)d_in[6],  (const float*)d_in[7],  (const float*)d_in[8],
        (const float*)d_in[9],  (const float*)d_in[10], (const float*)d_in[11],
        (const float*)d_in[12], (const float*)d_in[13], (const float*)d_in[14],
        (const float*)d_in[15], (const float*)d_in[16],
        (float*)d_out);
}

// round 16
// speedup vs baseline: 3.4083x; 1.0218x over previous
#include <cuda_runtime.h>

typedef unsigned int u32;
typedef unsigned long long u64;

#define NB 16384
#define OBS 64
#define HD 128
#define NNODE 5
#define NACT 8
#define SLOPE 0.2f
#define BT 16
#define NTHREADS 256

#define S_A 68      // u32 stride of 80-row A planes (68%32==4 -> conflict-free)
#define S_ST 68     // u32 stride of 16-row s planes (per head: 16*S_ST)

// ---- smem layout (4-byte word offsets) ----
#define OFF_AH  0        // A hi plane u32[80*68]
#define OFF_AL  5440
#define OFF_STH 10880    // s hi planes u32[2][16*68]
#define OFF_STL 13056
#define OFF_SM  15232    // small params (2352 floats):
// 0 enc_b1[128],128 enc_b2[128],256 val_b1[128],384 val_w2[128],512 pol_b1[128],
// 640 pol_w2[1024],1664 attn[2][80],1824 val_b2,1825 pol_b2[8],1840 g[512]
#define OFF_ADJ 17584    // 80 ints
#define SMEM_FLOATS 17664
#define SMEM_BYTES (SMEM_FLOATS*4)   // 70656 B -> 2 CTAs/SM (reg-limited anyway)

// ---- precomputed weight-fragment buffer (uint4 per (ntile,kstep,lane)) ----
#define WF_ENC1 0        // K=64:  2048
#define WF_ENC2 2048     // K=128: 4096
#define WF_V0   6144     // GV0 = gat_w0 @ val_w1[:128]   (K=128: 4096)
#define WF_V1   10240    // GV1 = gat_w1 @ val_w1[128:]
#define WF_P0   14336    // GP0 = gat_w0 @ pol_w1[:128]
#define WF_P1   18432    // GP1 = gat_w1 @ pol_w1[128:]
#define WF_TOTAL 22528
__device__ uint4 g_wf[WF_TOTAL];
__device__ float g_g[512];          // g[h][v][d] attention vectors
__device__ float g_gvp[4 * 16384];  // fused GV/GP matrices [m][e][c] fp32

// pack two f32 -> bf16x2, first arg in LOW half
#define CVTP(r, a, b) asm("cvt.rn.bf16x2.f32 %0, %1, %2;" : "=r"(r) : "f"(b), "f"(a))

__device__ __forceinline__ void split2(float v0, float v1, u32& hi, u32& lo) {
    CVTP(hi, v0, v1);
    const float r0 = v0 - __uint_as_float(hi << 16);
    const float r1 = v1 - __uint_as_float(hi & 0xffff0000u);
    CVTP(lo, r0, r1);
}

#define MMA(d, a0, a1, a2, a3, b0, b1) \
    asm volatile("mma.sync.aligned.m16n8k16.row.col.f32.bf16.bf16.f32 " \
        "{%0,%1,%2,%3}, {%4,%5,%6,%7}, {%8,%9}, {%0,%1,%2,%3};" \
        : "+f"((d)[0]), "+f"((d)[1]), "+f"((d)[2]), "+f"((d)[3]) \
        : "r"(a0), "r"(a1), "r"(a2), "r"(a3), "r"(b0), "r"(b1))

#define LDSM4(r0, r1, r2, r3, addr) \
    asm volatile("ldmatrix.sync.aligned.m8n8.x4.shared.b16 {%0,%1,%2,%3}, [%4];" \
        : "=r"(r0), "=r"(r1), "=r"(r2), "=r"(r3) : "r"(addr))

__device__ __forceinline__ u32 smem_u32(const void* p) {
    u32 a;
    asm("{ .reg .u64 t; cvta.to.shared.u64 t, %1; cvt.u32.u64 %0, t; }" : "=r"(a) : "l"(p));
    return a;
}

// ---- prep stage 1: GV/GP = gat_w[h] @ {val,pol}_w1[h*128:] (fp32) ----
extern "C" __global__ void __launch_bounds__(128)
prep_gv(const float* __restrict__ gat_w, const float* __restrict__ val_w1,
        const float* __restrict__ pol_w1)
{
    const int m  = blockIdx.x >> 5;         // 0..3: GV0,GV1,GP0,GP1
    const int e0 = (blockIdx.x & 31) * 4;   // 4 e-rows per block
    const int c  = threadIdx.x;
    const int h  = m & 1;
    const float* Wsrc = ((m < 2) ? val_w1 : pol_w1) + (size_t)h * 128 * HD;
    const float* gr   = gat_w + (size_t)h * HD * HD;
    float a0 = 0.f, a1 = 0.f, a2 = 0.f, a3 = 0.f;
    #pragma unroll 4
    for (int d = 0; d < 128; d++) {
        const float w = __ldg(Wsrc + (size_t)d * HD + c);
        a0 = fmaf(__ldg(gr + (e0 + 0) * HD + d), w, a0);
        a1 = fmaf(__ldg(gr + (e0 + 1) * HD + d), w, a1);
        a2 = fmaf(__ldg(gr + (e0 + 2) * HD + d), w, a2);
        a3 = fmaf(__ldg(gr + (e0 + 3) * HD + d), w, a3);
    }
    float* dst = g_gvp + (size_t)m * 16384 + (size_t)e0 * 128 + c;
    dst[0] = a0; dst[128] = a1; dst[256] = a2; dst[384] = a3;
}

// ---- prep stage 2: weight fragments + attention g vectors ----
extern "C" __global__ void __launch_bounds__(256)
prep_wf(const float* __restrict__ enc_w1, const float* __restrict__ enc_w2,
        const float* __restrict__ gat_w,  const float* __restrict__ gat_a)
{
    const int idx = blockIdx.x * 256 + threadIdx.x;
    if (idx >= WF_TOTAL) {
        const int i2 = idx - WF_TOTAL;
        if (i2 < 512) {
            const int hv = i2 >> 7, d = i2 & 127;
            const int h = hv >> 1, v = hv & 1;
            const float* row = gat_w + (size_t)h * HD * HD + (size_t)d * HD;
            const float* av  = gat_a + h * 256 + v * 128;
            float s = 0.f;
            #pragma unroll 8
            for (int k = 0; k < HD; k++) s = fmaf(__ldg(row + k), __ldg(av + k), s);
            g_g[i2] = s;
        }
        return;
    }
    const float* W; int base;
    if      (idx < WF_ENC2) { W = enc_w1; base = WF_ENC1; }
    else if (idx < WF_V0)   { W = enc_w2; base = WF_ENC2; }
    else {
        const int m = (idx - WF_V0) >> 12;
        W = g_gvp + (size_t)m * 16384;
        base = WF_V0 + m * 4096;
    }
    const int r = idx - base;
    const int lane = r & 31, t = (r >> 5) & 15, s = r >> 9;
    const int ar = lane >> 2, ac = lane & 3;
    const int wn = t * 8 + ar;
    const float* p = W + (size_t)(s * 16 + 2 * ac) * HD + wn;
    u32 h0, l0, h1, l1;
    split2(__ldg(p),          __ldg(p + HD),     h0, l0);
    split2(__ldg(p + 8 * HD), __ldg(p + 9 * HD), h1, l1);
    g_wf[idx] = make_uint4(h0, h1, l0, l1);
}

// Split-bf16 MMA gemm: acc[5 m-tiles][2 n-tiles][4] += A(80xK) @ W(Kx128)
__device__ __forceinline__ void run_gemm(float acc[5][2][4],
                                         u32 uAH, u32 uAL,
                                         int wfbase, int lane, int wid, int KS)
{
    const int ln = lane & 15;
    const u32 kh = (u32)((lane >> 4) << 4);
    u32 ah[5], al[5];
    #pragma unroll
    for (int i = 0; i < 5; i++) {
        const u32 off = (u32)((16 * i + ln) * S_A) * 4u + kh;
        ah[i] = uAH + off;
        al[i] = uAL + off;
    }
    for (int s = 0; s < KS; s++) {
        uint4 f[2];
        #pragma unroll
        for (int j = 0; j < 2; j++)
            f[j] = __ldg(&g_wf[wfbase + (s * 16 + 2 * wid + j) * 32 + lane]);
        #pragma unroll
        for (int i = 0; i < 5; i++) {
            u32 a0, a1, a2, a3, l0, l1, l2, l3;
            LDSM4(a0, a1, a2, a3, ah[i] + (u32)s * 32u);
            LDSM4(l0, l1, l2, l3, al[i] + (u32)s * 32u);
            #pragma unroll
            for (int j = 0; j < 2; j++) {
                MMA(acc[i][j], a0, a1, a2, a3, f[j].x, f[j].y);
                MMA(acc[i][j], a0, a1, a2, a3, f[j].z, f[j].w);
                MMA(acc[i][j], l0, l1, l2, l3, f[j].x, f[j].y);
            }
        }
    }
}

// M=16 split-bf16 MMA gemm: acc[NT][4] += A(16xK planes) @ W, frags from g_wf.
template<int NT>
__device__ __forceinline__ void gemm16(float acc[NT][4],
                                       u32 uAH, u32 uAL, int sa,
                                       int wfbase, int nt0, int lane, int KS)
{
    const int ln = lane & 15;
    const u32 kh = (u32)((lane >> 4) << 4);
    const u32 off = (u32)(ln * sa) * 4u + kh;
    const u32 ah = uAH + off, al = uAL + off;
    for (int s = 0; s < KS; s++) {
        uint4 f[NT];
        #pragma unroll
        for (int j = 0; j < NT; j++)
            f[j] = __ldg(&g_wf[wfbase + (s * 16 + nt0 + j) * 32 + lane]);
        u32 a0, a1, a2, a3, l0, l1, l2, l3;
        LDSM4(a0, a1, a2, a3, ah + (u32)s * 32u);
        LDSM4(l0, l1, l2, l3, al + (u32)s * 32u);
        #pragma unroll
        for (int j = 0; j < NT; j++) {
            MMA(acc[j], a0, a1, a2, a3, f[j].x, f[j].y);
            MMA(acc[j], a0, a1, a2, a3, f[j].z, f[j].w);
            MMA(acc[j], l0, l1, l2, l3, f[j].x, f[j].y);
        }
    }
}

// D-frags -> bf16 hi/lo A planes (+bias, optional relu), 5 m-tiles
__device__ __forceinline__ void store_split(const float acc[5][2][4],
                                            u32* __restrict__ AH, u32* __restrict__ AL,
                                            const float* __restrict__ bias, bool relu,
                                            int lane, int n0)
{
    const int ar = lane >> 2, ac2 = (lane & 3) << 1;
    #pragma unroll
    for (int i = 0; i < 5; i++)
        #pragma unroll
        for (int j = 0; j < 2; j++) {
            const int c = n0 + 8 * j + ac2;
            const float b0v = bias[c], b1v = bias[c + 1];
            float v0 = acc[i][j][0] + b0v, v1 = acc[i][j][1] + b1v;
            if (relu) { v0 = fmaxf(v0, 0.f); v1 = fmaxf(v1, 0.f); }
            u32 hi, lo; split2(v0, v1, hi, lo);
            const int r0 = i * 16 + ar;
            AH[r0 * S_A + (c >> 1)] = hi;
            AL[r0 * S_A + (c >> 1)] = lo;
            float v2 = acc[i][j][2] + b0v, v3 = acc[i][j][3] + b1v;
            if (relu) { v2 = fmaxf(v2, 0.f); v3 = fmaxf(v3, 0.f); }
            split2(v2, v3, hi, lo);
            AH[(r0 + 8) * S_A + (c >> 1)] = hi;
            AL[(r0 + 8) * S_A + (c >> 1)] = lo;
        }
}

__device__ __forceinline__ void emb_pair(u32 h, u32 l, float& e0, float& e1) {
    e0 = __uint_as_float(h << 16) + __uint_as_float(l << 16);
    e1 = __uint_as_float(h & 0xffff0000u) + __uint_as_float(l & 0xffff0000u);
}

extern "C" __global__ void __launch_bounds__(NTHREADS, 2)
colight(const float* __restrict__ obs, const float* __restrict__ nobs,
        const int* __restrict__ adj,
        const float* __restrict__ enc_w1, const float* __restrict__ enc_b1,
        const float* __restrict__ enc_w2, const float* __restrict__ enc_b2,
        const float* __restrict__ gat_w, const float* __restrict__ gat_a,
        const float* __restrict__ val_w1, const float* __restrict__ val_b1,
        const float* __restrict__ val_w2, const float* __restrict__ val_b2,
        const float* __restrict__ pol_w1, const float* __restrict__ pol_b1,
        const float* __restrict__ pol_w2, const float* __restrict__ pol_b2,
        float* __restrict__ out)
{
    extern __shared__ float sm[];
    u32*   AH  = reinterpret_cast<u32*>(sm + OFF_AH);
    u32*   AL  = reinterpret_cast<u32*>(sm + OFF_AL);
    u32*   STH = reinterpret_cast<u32*>(sm + OFF_STH);
    u32*   STL = reinterpret_cast<u32*>(sm + OFF_STL);
    float* sSm = sm + OFF_SM;
    int*   sAdj = reinterpret_cast<int*>(sm + OFF_ADJ);
    float* Hf  = sm + OFF_AH;   // hv/hp output reuses A region (emb dead by then)

    const int tid = threadIdx.x;
    const int b0  = blockIdx.x * BT;
    const int wid = tid >> 5, lane = tid & 31;
    const int n0  = wid * 16;

    const u32 usm  = smem_u32(sm);
    const u32 uAH  = usm + OFF_AH  * 4, uAL  = usm + OFF_AL  * 4;
    const u32 uSTH = usm + OFF_STH * 4, uSTL = usm + OFF_STL * 4;

    // ---------- init ----------
    for (int idx = tid; idx < HD; idx += NTHREADS) {
        sSm[idx]        = enc_b1[idx];
        sSm[128 + idx]  = enc_b2[idx];
        sSm[256 + idx]  = val_b1[idx];
        sSm[384 + idx]  = val_w2[idx];
        sSm[512 + idx]  = pol_b1[idx];
    }
    for (int idx = tid; idx < 1024; idx += NTHREADS) sSm[640 + idx]  = pol_w2[idx];
    for (int idx = tid; idx < 512;  idx += NTHREADS) sSm[1840 + idx] = g_g[idx];
    if (tid < BT * NNODE) sAdj[tid] = adj[(size_t)b0 * NNODE + tid];
    if (tid == 0) sSm[1824] = val_b2[0];
    if (tid < NACT) sSm[1825 + tid] = pol_b2[tid];

    for (int p = tid; p < 80 * 32; p += NTHREADS) {
        const int r = p >> 5, k2 = p & 31;
        const int lb = r / NNODE, n = r - lb * NNODE;
        const float* src = (n == 0) ? obs + (size_t)(b0 + lb) * OBS + 2 * k2
                                    : nobs + ((size_t)(b0 + lb) * 4 + (n - 1)) * OBS + 2 * k2;
        const float2 v = __ldg(reinterpret_cast<const float2*>(src));
        u32 hi, lo; split2(v.x, v.y, hi, lo);
        AH[r * S_A + k2] = hi;
        AL[r * S_A + k2] = lo;
    }
    __syncthreads();

    // ---------- encoder layer 1 ----------
    {
        float acc[5][2][4];
        #pragma unroll
        for (int i = 0; i < 5; i++)
            #pragma unroll
            for (int j = 0; j < 2; j++)
                #pragma unroll
                for (int t = 0; t < 4; t++) acc[i][j][t] = 0.f;
        run_gemm(acc, uAH, uAL, WF_ENC1, lane, wid, 4);
        __syncthreads();
        store_split(acc, AH, AL, sSm, true, lane, n0);
    }
    __syncthreads();

    // ---------- encoder layer 2 ----------
    {
        float acc[5][2][4];
        #pragma unroll
        for (int i = 0; i < 5; i++)
            #pragma unroll
            for (int j = 0; j < 2; j++)
                #pragma unroll
                for (int t = 0; t < 4; t++) acc[i][j][t] = 0.f;
        run_gemm(acc, uAH, uAL, WF_ENC2, lane, wid, 8);
        __syncthreads();
        store_split(acc, AH, AL, sSm + 128, false, lane, n0);
    }
    __syncthreads();

    // ---------- GAT attention: both heads in parallel (warps 0-3 h0, 4-7 h1) ----------
    {
        const int head = wid >> 2;
        const float* g1 = sSm + 1840 + head * 256;
        const float* g2 = g1 + 128;
        #pragma unroll
        for (int q = 0; q < 4; q++) {
            const int lb = (wid & 3) * 4 + q;
            float ei = 0.f, ej[5] = {0.f, 0.f, 0.f, 0.f, 0.f};
            #pragma unroll
            for (int n = 0; n < NNODE; n++) {
                const int r = lb * NNODE + n;
                #pragma unroll
                for (int rep = 0; rep < 2; rep++) {
                    const int k2 = lane + 32 * rep;
                    float e0, e1;
                    emb_pair(AH[r * S_A + k2], AL[r * S_A + k2], e0, e1);
                    const int k = 2 * k2;
                    if (n == 0) { ei = fmaf(e0, g1[k], ei); ei = fmaf(e1, g1[k + 1], ei); }
                    ej[n] = fmaf(e0, g2[k], ej[n]);
                    ej[n] = fmaf(e1, g2[k + 1], ej[n]);
                }
            }
            #pragma unroll
            for (int off = 16; off > 0; off >>= 1) {
                ei += __shfl_xor_sync(0xffffffffu, ei, off);
                #pragma unroll
                for (int n = 0; n < NNODE; n++)
                    ej[n] += __shfl_xor_sync(0xffffffffu, ej[n], off);
            }
            if (lane == 0) {
                float ev[5], mx = -1e30f;
                #pragma unroll
                for (int n = 0; n < NNODE; n++) {
                    if (sAdj[lb * NNODE + n] != 0) {
                        float e = ei + ej[n];
                        e = (e >= 0.f) ? e : SLOPE * e;
                        ev[n] = e; mx = fmaxf(mx, e);
                    } else ev[n] = -1e30f;
                }
                float ssum = 0.f;
                #pragma unroll
                for (int n = 0; n < NNODE; n++) {
                    const float p = (ev[n] > -1e29f) ? __expf(ev[n] - mx) : 0.f;
                    ev[n] = p; ssum += p;
                }
                const float inv = 1.f / ssum;
                #pragma unroll
                for (int n = 0; n < NNODE; n++)
                    sSm[1664 + head * 80 + lb * NNODE + n] = ev[n] * inv;
            }
        }
    }
    __syncthreads();

    // ---------- s_b = sum_n attn * emb (both heads; threads split by head) ----------
    {
        const int hh = tid >> 7, t = tid & 127;
        for (int p = t; p < 16 * 64; p += 128) {
            const int lb = p >> 6, k2 = p & 63;
            const float* at = sSm + 1664 + hh * 80 + lb * NNODE;
            float s0 = 0.f, s1 = 0.f;
            #pragma unroll
            for (int n = 0; n < NNODE; n++) {
                const int r = lb * NNODE + n;
                float e0, e1;
                emb_pair(AH[r * S_A + k2], AL[r * S_A + k2], e0, e1);
                s0 = fmaf(at[n], e0, s0);
                s1 = fmaf(at[n], e1, s1);
            }
            u32 hi, lo; split2(s0, s1, hi, lo);
            STH[hh * 16 * S_ST + lb * S_ST + k2] = hi;
            STL[hh * 16 * S_ST + lb * S_ST + k2] = lo;
        }
    }
    __syncthreads();

    // ---------- fused (h' @ W1) heads: hv = relu(s0@GV0 + s1@GV1 + b), hp likewise ----------
    {
        const int head = wid >> 2;
        const float* bs = head ? (sSm + 512) : (sSm + 256);
        float* Ho = Hf + head * BT * HD;
        float acc[4][4];
        #pragma unroll
        for (int j = 0; j < 4; j++)
            #pragma unroll
            for (int t = 0; t < 4; t++) acc[j][t] = 0.f;
        gemm16<4>(acc, uSTH, uSTL, S_ST,
                  head ? WF_P0 : WF_V0, (wid & 3) * 4, lane, 8);
        gemm16<4>(acc, uSTH + 16 * S_ST * 4, uSTL + 16 * S_ST * 4, S_ST,
                  head ? WF_P1 : WF_V1, (wid & 3) * 4, lane, 8);
        const int ar = lane >> 2, ac2 = (lane & 3) << 1;
        #pragma unroll
        for (int j = 0; j < 4; j++) {
            const int c = (wid & 3) * 32 + 8 * j + ac2;
            const float b0v = bs[c], b1v = bs[c + 1];
            float2 v;
            v.x = fmaxf(acc[j][0] + b0v, 0.f);
            v.y = fmaxf(acc[j][1] + b1v, 0.f);
            *reinterpret_cast<float2*>(Ho + ar * HD + c) = v;
            v.x = fmaxf(acc[j][2] + b0v, 0.f);
            v.y = fmaxf(acc[j][3] + b1v, 0.f);
            *reinterpret_cast<float2*>(Ho + (ar + 8) * HD + c) = v;
        }
    }
    __syncthreads();

    // ---------- value = hv @ val_w2 + b ----------
    #pragma unroll
    for (int q = 0; q < 2; q++) {
        const int lb = wid * 2 + q;
        float s = 0.f;
        for (int kk = lane; kk < HD; kk += 32)
            s = fmaf(Hf[lb * HD + kk], sSm[384 + kk], s);
        #pragma unroll
        for (int off = 16; off > 0; off >>= 1) s += __shfl_xor_sync(0xffffffffu, s, off);
        if (lane == 0) out[b0 + lb] = s + sSm[1824];
    }

    // ---------- logits = hp @ pol_w2 + b ----------
    if (tid < BT * NACT) {
        const int lb = tid >> 3, a = tid & 7;
        const float* hp = Hf + BT * HD + lb * HD;
        float s = 0.f;
        for (int kk = 0; kk < HD; kk++)
            s = fmaf(hp[kk], sSm[640 + kk * NACT + a], s);
        out[NB + (size_t)(b0 + lb) * NACT + a] = s + sSm[1825 + a];
    }
}

extern "C" void kernel_launch(void* const* d_in, const int* in_sizes, int n_in,
                              void* d_out, int out_size)
{
    (void)in_sizes; (void)n_in; (void)out_size;
    cudaFuncSetAttribute(colight, cudaFuncAttributeMaxDynamicSharedMemorySize, SMEM_BYTES);
    prep_gv<<<128, 128>>>(
        (const float*)d_in[7], (const float*)d_in[9], (const float*)d_in[13]);
    prep_wf<<<(WF_TOTAL + 512 + 255) / 256, 256>>>(
        (const float*)d_in[3], (const float*)d_in[5], (const float*)d_in[7],
        (const float*)d_in[8]);
    colight<<<NB/BT, NTHREADS, SMEM_BYTES>>>(
        (const float*)d_in[0],  (const float*)d_in[1],  (const int*)d_in[2],
        (const float*)d_in[3],  (const float*)d_in[4],  (const float*)d_in[5],
        (const float*)d_in[6],  (const float*)d_in[7],  (const float*)d_in[8],
        (const float*)d_in[9],  (const float*)d_in[10], (const float*)d_in[11],
        (const float*)d_in[12], (const float*)d_in[13], (const float*)d_in[14],
        (const float*)d_in[15], (const float*)d_in[16],
        (float*)d_out);
}

// round 17
// speedup vs baseline: 3.6275x; 1.0643x over previous
#include <cuda_runtime.h>

typedef unsigned int u32;
typedef unsigned long long u64;

#define NB 16384
#define OBS 64
#define HD 128
#define NNODE 5
#define NACT 8
#define SLOPE 0.2f
#define BT 16
#define NTHREADS 256

#define S_A 68      // u32 stride of 80-row A planes (68%32==4 -> conflict-free)
#define S_ST 68     // u32 stride of 16-row s planes (per head: 16*S_ST)

// ---- smem layout (4-byte word offsets) ----
#define OFF_AH  0        // A hi plane u32[80*68]
#define OFF_AL  5440
#define OFF_STH 10880    // s hi planes u32[2][16*68]
#define OFF_STL 13056
#define OFF_SM  15232    // small params (2352 floats):
// 0 enc_b1[128],128 enc_b2[128],256 val_b1[128],384 val_w2[128],512 pol_b1[128],
// 640 pol_w2[1024],1664 attn[2][80],1824 val_b2,1825 pol_b2[8],1840 g[512]
#define OFF_ADJ 17584    // 80 ints
#define SMEM_FLOATS 17664
#define SMEM_BYTES (SMEM_FLOATS*4)   // 70656 B

// ---- precomputed weight-fragment buffer (uint4 per (ntile,kstep,lane)) ----
#define WF_ENC1 0        // K=64:  2048
#define WF_ENC2 2048     // K=128: 4096
#define WF_V0   6144     // GV0 = gat_w0 @ val_w1[:128]   (K=128: 4096)
#define WF_V1   10240    // GV1 = gat_w1 @ val_w1[128:]
#define WF_P0   14336    // GP0 = gat_w0 @ pol_w1[:128]
#define WF_P1   18432    // GP1 = gat_w1 @ pol_w1[128:]
#define WF_TOTAL 22528
__device__ uint4 g_wf[WF_TOTAL];
__device__ float g_g[512];          // g[h][v][d] attention vectors
__device__ float g_gvp[4 * 16384];  // fused GV/GP matrices [m][e][c] fp32

// pack two f32 -> bf16x2, first arg in LOW half
#define CVTP(r, a, b) asm("cvt.rn.bf16x2.f32 %0, %1, %2;" : "=r"(r) : "f"(b), "f"(a))

__device__ __forceinline__ void split2(float v0, float v1, u32& hi, u32& lo) {
    CVTP(hi, v0, v1);
    const float r0 = v0 - __uint_as_float(hi << 16);
    const float r1 = v1 - __uint_as_float(hi & 0xffff0000u);
    CVTP(lo, r0, r1);
}

#define MMA(d, a0, a1, a2, a3, b0, b1) \
    asm volatile("mma.sync.aligned.m16n8k16.row.col.f32.bf16.bf16.f32 " \
        "{%0,%1,%2,%3}, {%4,%5,%6,%7}, {%8,%9}, {%0,%1,%2,%3};" \
        : "+f"((d)[0]), "+f"((d)[1]), "+f"((d)[2]), "+f"((d)[3]) \
        : "r"(a0), "r"(a1), "r"(a2), "r"(a3), "r"(b0), "r"(b1))

#define LDSM4(r0, r1, r2, r3, addr) \
    asm volatile("ldmatrix.sync.aligned.m8n8.x4.shared.b16 {%0,%1,%2,%3}, [%4];" \
        : "=r"(r0), "=r"(r1), "=r"(r2), "=r"(r3) : "r"(addr))

__device__ __forceinline__ u32 smem_u32(const void* p) {
    u32 a;
    asm("{ .reg .u64 t; cvta.to.shared.u64 t, %1; cvt.u32.u64 %0, t; }" : "=r"(a) : "l"(p));
    return a;
}

// ---- prep stage 1: GV/GP = gat_w[h] @ {val,pol}_w1[h*128:] (fp32) ----
// 512 blocks: one per (matrix m, output row e). gat_w row staged in smem;
// per-thread K-loop over coalesced W loads (unroll 8 -> 8 LDGs in flight).
// Accumulation order over d identical to previous version (bit-identical output).
extern "C" __global__ void __launch_bounds__(128)
prep_gv(const float* __restrict__ gat_w, const float* __restrict__ val_w1,
        const float* __restrict__ pol_w1)
{
    __shared__ float gsh[128];
    const int m = blockIdx.x >> 7;          // 0..3: GV0,GV1,GP0,GP1
    const int e = blockIdx.x & 127;
    const int c = threadIdx.x;
    const int h = m & 1;
    const float* Wsrc = ((m < 2) ? val_w1 : pol_w1) + (size_t)h * 128 * HD;
    gsh[c] = __ldg(gat_w + (size_t)h * HD * HD + (size_t)e * HD + c);
    __syncthreads();
    float acc = 0.f;
    #pragma unroll 8
    for (int d = 0; d < 128; d++)
        acc = fmaf(gsh[d], __ldg(Wsrc + (size_t)d * HD + c), acc);
    g_gvp[(size_t)m * 16384 + (size_t)e * 128 + c] = acc;
}

// ---- prep stage 2: weight fragments + attention g vectors ----
extern "C" __global__ void __launch_bounds__(256)
prep_wf(const float* __restrict__ enc_w1, const float* __restrict__ enc_w2,
        const float* __restrict__ gat_w,  const float* __restrict__ gat_a)
{
    const int idx = blockIdx.x * 256 + threadIdx.x;
    if (idx >= WF_TOTAL) {
        const int i2 = idx - WF_TOTAL;
        if (i2 < 512) {
            const int hv = i2 >> 7, d = i2 & 127;
            const int h = hv >> 1, v = hv & 1;
            const float* row = gat_w + (size_t)h * HD * HD + (size_t)d * HD;
            const float* av  = gat_a + h * 256 + v * 128;
            float s = 0.f;
            #pragma unroll 8
            for (int k = 0; k < HD; k++) s = fmaf(__ldg(row + k), __ldg(av + k), s);
            g_g[i2] = s;
        }
        return;
    }
    const float* W; int base;
    if      (idx < WF_ENC2) { W = enc_w1; base = WF_ENC1; }
    else if (idx < WF_V0)   { W = enc_w2; base = WF_ENC2; }
    else {
        const int m = (idx - WF_V0) >> 12;
        W = g_gvp + (size_t)m * 16384;
        base = WF_V0 + m * 4096;
    }
    const int r = idx - base;
    const int lane = r & 31, t = (r >> 5) & 15, s = r >> 9;
    const int ar = lane >> 2, ac = lane & 3;
    const int wn = t * 8 + ar;
    const float* p = W + (size_t)(s * 16 + 2 * ac) * HD + wn;
    u32 h0, l0, h1, l1;
    split2(__ldg(p),          __ldg(p + HD),     h0, l0);
    split2(__ldg(p + 8 * HD), __ldg(p + 9 * HD), h1, l1);
    g_wf[idx] = make_uint4(h0, h1, l0, l1);
}

// Split-bf16 MMA gemm: acc[5 m-tiles][2 n-tiles][4] += A(80xK) @ W(Kx128)
__device__ __forceinline__ void run_gemm(float acc[5][2][4],
                                         u32 uAH, u32 uAL,
                                         int wfbase, int lane, int wid, int KS)
{
    const int ln = lane & 15;
    const u32 kh = (u32)((lane >> 4) << 4);
    u32 ah[5], al[5];
    #pragma unroll
    for (int i = 0; i < 5; i++) {
        const u32 off = (u32)((16 * i + ln) * S_A) * 4u + kh;
        ah[i] = uAH + off;
        al[i] = uAL + off;
    }
    for (int s = 0; s < KS; s++) {
        uint4 f[2];
        #pragma unroll
        for (int j = 0; j < 2; j++)
            f[j] = __ldg(&g_wf[wfbase + (s * 16 + 2 * wid + j) * 32 + lane]);
        #pragma unroll
        for (int i = 0; i < 5; i++) {
            u32 a0, a1, a2, a3, l0, l1, l2, l3;
            LDSM4(a0, a1, a2, a3, ah[i] + (u32)s * 32u);
            LDSM4(l0, l1, l2, l3, al[i] + (u32)s * 32u);
            #pragma unroll
            for (int j = 0; j < 2; j++) {
                MMA(acc[i][j], a0, a1, a2, a3, f[j].x, f[j].y);
                MMA(acc[i][j], a0, a1, a2, a3, f[j].z, f[j].w);
                MMA(acc[i][j], l0, l1, l2, l3, f[j].x, f[j].y);
            }
        }
    }
}

// M=16 split-bf16 MMA gemm: acc[NT][4] += A(16xK planes) @ W, frags from g_wf.
template<int NT>
__device__ __forceinline__ void gemm16(float acc[NT][4],
                                       u32 uAH, u32 uAL, int sa,
                                       int wfbase, int nt0, int lane, int KS)
{
    const int ln = lane & 15;
    const u32 kh = (u32)((lane >> 4) << 4);
    const u32 off = (u32)(ln * sa) * 4u + kh;
    const u32 ah = uAH + off, al = uAL + off;
    for (int s = 0; s < KS; s++) {
        uint4 f[NT];
        #pragma unroll
        for (int j = 0; j < NT; j++)
            f[j] = __ldg(&g_wf[wfbase + (s * 16 + nt0 + j) * 32 + lane]);
        u32 a0, a1, a2, a3, l0, l1, l2, l3;
        LDSM4(a0, a1, a2, a3, ah + (u32)s * 32u);
        LDSM4(l0, l1, l2, l3, al + (u32)s * 32u);
        #pragma unroll
        for (int j = 0; j < NT; j++) {
            MMA(acc[j], a0, a1, a2, a3, f[j].x, f[j].y);
            MMA(acc[j], a0, a1, a2, a3, f[j].z, f[j].w);
            MMA(acc[j], l0, l1, l2, l3, f[j].x, f[j].y);
        }
    }
}

// D-frags -> bf16 hi/lo A planes (+bias, optional relu), 5 m-tiles
__device__ __forceinline__ void store_split(const float acc[5][2][4],
                                            u32* __restrict__ AH, u32* __restrict__ AL,
                                            const float* __restrict__ bias, bool relu,
                                            int lane, int n0)
{
    const int ar = lane >> 2, ac2 = (lane & 3) << 1;
    #pragma unroll
    for (int i = 0; i < 5; i++)
        #pragma unroll
        for (int j = 0; j < 2; j++) {
            const int c = n0 + 8 * j + ac2;
            const float b0v = bias[c], b1v = bias[c + 1];
            float v0 = acc[i][j][0] + b0v, v1 = acc[i][j][1] + b1v;
            if (relu) { v0 = fmaxf(v0, 0.f); v1 = fmaxf(v1, 0.f); }
            u32 hi, lo; split2(v0, v1, hi, lo);
            const int r0 = i * 16 + ar;
            AH[r0 * S_A + (c >> 1)] = hi;
            AL[r0 * S_A + (c >> 1)] = lo;
            float v2 = acc[i][j][2] + b0v, v3 = acc[i][j][3] + b1v;
            if (relu) { v2 = fmaxf(v2, 0.f); v3 = fmaxf(v3, 0.f); }
            split2(v2, v3, hi, lo);
            AH[(r0 + 8) * S_A + (c >> 1)] = hi;
            AL[(r0 + 8) * S_A + (c >> 1)] = lo;
        }
}

__device__ __forceinline__ void emb_pair(u32 h, u32 l, float& e0, float& e1) {
    e0 = __uint_as_float(h << 16) + __uint_as_float(l << 16);
    e1 = __uint_as_float(h & 0xffff0000u) + __uint_as_float(l & 0xffff0000u);
}

extern "C" __global__ void __launch_bounds__(NTHREADS, 2)
colight(const float* __restrict__ obs, const float* __restrict__ nobs,
        const int* __restrict__ adj,
        const float* __restrict__ enc_w1, const float* __restrict__ enc_b1,
        const float* __restrict__ enc_w2, const float* __restrict__ enc_b2,
        const float* __restrict__ gat_w, const float* __restrict__ gat_a,
        const float* __restrict__ val_w1, const float* __restrict__ val_b1,
        const float* __restrict__ val_w2, const float* __restrict__ val_b2,
        const float* __restrict__ pol_w1, const float* __restrict__ pol_b1,
        const float* __restrict__ pol_w2, const float* __restrict__ pol_b2,
        float* __restrict__ out)
{
    extern __shared__ float sm[];
    u32*   AH  = reinterpret_cast<u32*>(sm + OFF_AH);
    u32*   AL  = reinterpret_cast<u32*>(sm + OFF_AL);
    u32*   STH = reinterpret_cast<u32*>(sm + OFF_STH);
    u32*   STL = reinterpret_cast<u32*>(sm + OFF_STL);
    float* sSm = sm + OFF_SM;
    int*   sAdj = reinterpret_cast<int*>(sm + OFF_ADJ);
    float* Hf  = sm + OFF_AH;   // hv/hp output reuses A region (emb dead by then)

    const int tid = threadIdx.x;
    const int b0  = blockIdx.x * BT;
    const int wid = tid >> 5, lane = tid & 31;
    const int n0  = wid * 16;

    const u32 usm  = smem_u32(sm);
    const u32 uAH  = usm + OFF_AH  * 4, uAL  = usm + OFF_AL  * 4;
    const u32 uSTH = usm + OFF_STH * 4, uSTL = usm + OFF_STL * 4;

    // ---------- init ----------
    for (int idx = tid; idx < HD; idx += NTHREADS) {
        sSm[idx]        = enc_b1[idx];
        sSm[128 + idx]  = enc_b2[idx];
        sSm[256 + idx]  = val_b1[idx];
        sSm[384 + idx]  = val_w2[idx];
        sSm[512 + idx]  = pol_b1[idx];
    }
    for (int idx = tid; idx < 1024; idx += NTHREADS) sSm[640 + idx]  = pol_w2[idx];
    for (int idx = tid; idx < 512;  idx += NTHREADS) sSm[1840 + idx] = g_g[idx];
    if (tid < BT * NNODE) sAdj[tid] = adj[(size_t)b0 * NNODE + tid];
    if (tid == 0) sSm[1824] = val_b2[0];
    if (tid < NACT) sSm[1825 + tid] = pol_b2[tid];

    for (int p = tid; p < 80 * 32; p += NTHREADS) {
        const int r = p >> 5, k2 = p & 31;
        const int lb = r / NNODE, n = r - lb * NNODE;
        const float* src = (n == 0) ? obs + (size_t)(b0 + lb) * OBS + 2 * k2
                                    : nobs + ((size_t)(b0 + lb) * 4 + (n - 1)) * OBS + 2 * k2;
        const float2 v = __ldg(reinterpret_cast<const float2*>(src));
        u32 hi, lo; split2(v.x, v.y, hi, lo);
        AH[r * S_A + k2] = hi;
        AL[r * S_A + k2] = lo;
    }
    __syncthreads();

    // ---------- encoder layer 1 ----------
    {
        float acc[5][2][4];
        #pragma unroll
        for (int i = 0; i < 5; i++)
            #pragma unroll
            for (int j = 0; j < 2; j++)
                #pragma unroll
                for (int t = 0; t < 4; t++) acc[i][j][t] = 0.f;
        run_gemm(acc, uAH, uAL, WF_ENC1, lane, wid, 4);
        __syncthreads();
        store_split(acc, AH, AL, sSm, true, lane, n0);
    }
    __syncthreads();

    // ---------- encoder layer 2 ----------
    {
        float acc[5][2][4];
        #pragma unroll
        for (int i = 0; i < 5; i++)
            #pragma unroll
            for (int j = 0; j < 2; j++)
                #pragma unroll
                for (int t = 0; t < 4; t++) acc[i][j][t] = 0.f;
        run_gemm(acc, uAH, uAL, WF_ENC2, lane, wid, 8);
        __syncthreads();
        store_split(acc, AH, AL, sSm + 128, false, lane, n0);
    }
    __syncthreads();

    // ---------- GAT attention: both heads in parallel (warps 0-3 h0, 4-7 h1) ----------
    {
        const int head = wid >> 2;
        const float* g1 = sSm + 1840 + head * 256;
        const float* g2 = g1 + 128;
        #pragma unroll
        for (int q = 0; q < 4; q++) {
            const int lb = (wid & 3) * 4 + q;
            float ei = 0.f, ej[5] = {0.f, 0.f, 0.f, 0.f, 0.f};
            #pragma unroll
            for (int n = 0; n < NNODE; n++) {
                const int r = lb * NNODE + n;
                #pragma unroll
                for (int rep = 0; rep < 2; rep++) {
                    const int k2 = lane + 32 * rep;
                    float e0, e1;
                    emb_pair(AH[r * S_A + k2], AL[r * S_A + k2], e0, e1);
                    const int k = 2 * k2;
                    if (n == 0) { ei = fmaf(e0, g1[k], ei); ei = fmaf(e1, g1[k + 1], ei); }
                    ej[n] = fmaf(e0, g2[k], ej[n]);
                    ej[n] = fmaf(e1, g2[k + 1], ej[n]);
                }
            }
            #pragma unroll
            for (int off = 16; off > 0; off >>= 1) {
                ei += __shfl_xor_sync(0xffffffffu, ei, off);
                #pragma unroll
                for (int n = 0; n < NNODE; n++)
                    ej[n] += __shfl_xor_sync(0xffffffffu, ej[n], off);
            }
            if (lane == 0) {
                float ev[5], mx = -1e30f;
                #pragma unroll
                for (int n = 0; n < NNODE; n++) {
                    if (sAdj[lb * NNODE + n] != 0) {
                        float e = ei + ej[n];
                        e = (e >= 0.f) ? e : SLOPE * e;
                        ev[n] = e; mx = fmaxf(mx, e);
                    } else ev[n] = -1e30f;
                }
                float ssum = 0.f;
                #pragma unroll
                for (int n = 0; n < NNODE; n++) {
                    const float p = (ev[n] > -1e29f) ? __expf(ev[n] - mx) : 0.f;
                    ev[n] = p; ssum += p;
                }
                const float inv = 1.f / ssum;
                #pragma unroll
                for (int n = 0; n < NNODE; n++)
                    sSm[1664 + head * 80 + lb * NNODE + n] = ev[n] * inv;
            }
        }
    }
    __syncthreads();

    // ---------- s_b = sum_n attn * emb (both heads; threads split by head) ----------
    {
        const int hh = tid >> 7, t = tid & 127;
        for (int p = t; p < 16 * 64; p += 128) {
            const int lb = p >> 6, k2 = p & 63;
            const float* at = sSm + 1664 + hh * 80 + lb * NNODE;
            float s0 = 0.f, s1 = 0.f;
            #pragma unroll
            for (int n = 0; n < NNODE; n++) {
                const int r = lb * NNODE + n;
                float e0, e1;
                emb_pair(AH[r * S_A + k2], AL[r * S_A + k2], e0, e1);
                s0 = fmaf(at[n], e0, s0);
                s1 = fmaf(at[n], e1, s1);
            }
            u32 hi, lo; split2(s0, s1, hi, lo);
            STH[hh * 16 * S_ST + lb * S_ST + k2] = hi;
            STL[hh * 16 * S_ST + lb * S_ST + k2] = lo;
        }
    }
    __syncthreads();

    // ---------- fused (h' @ W1) heads: hv = relu(s0@GV0 + s1@GV1 + b), hp likewise ----------
    {
        const int head = wid >> 2;
        const float* bs = head ? (sSm + 512) : (sSm + 256);
        float* Ho = Hf + head * BT * HD;
        float acc[4][4];
        #pragma unroll
        for (int j = 0; j < 4; j++)
            #pragma unroll
            for (int t = 0; t < 4; t++) acc[j][t] = 0.f;
        gemm16<4>(acc, uSTH, uSTL, S_ST,
                  head ? WF_P0 : WF_V0, (wid & 3) * 4, lane, 8);
        gemm16<4>(acc, uSTH + 16 * S_ST * 4, uSTL + 16 * S_ST * 4, S_ST,
                  head ? WF_P1 : WF_V1, (wid & 3) * 4, lane, 8);
        const int ar = lane >> 2, ac2 = (lane & 3) << 1;
        #pragma unroll
        for (int j = 0; j < 4; j++) {
            const int c = (wid & 3) * 32 + 8 * j + ac2;
            const float b0v = bs[c], b1v = bs[c + 1];
            float2 v;
            v.x = fmaxf(acc[j][0] + b0v, 0.f);
            v.y = fmaxf(acc[j][1] + b1v, 0.f);
            *reinterpret_cast<float2*>(Ho + ar * HD + c) = v;
            v.x = fmaxf(acc[j][2] + b0v, 0.f);
            v.y = fmaxf(acc[j][3] + b1v, 0.f);
            *reinterpret_cast<float2*>(Ho + (ar + 8) * HD + c) = v;
        }
    }
    __syncthreads();

    // ---------- value = hv @ val_w2 + b ----------
    #pragma unroll
    for (int q = 0; q < 2; q++) {
        const int lb = wid * 2 + q;
        float s = 0.f;
        for (int kk = lane; kk < HD; kk += 32)
            s = fmaf(Hf[lb * HD + kk], sSm[384 + kk], s);
        #pragma unroll
        for (int off = 16; off > 0; off >>= 1) s += __shfl_xor_sync(0xffffffffu, s, off);
        if (lane == 0) out[b0 + lb] = s + sSm[1824];
    }

    // ---------- logits = hp @ pol_w2 + b ----------
    if (tid < BT * NACT) {
        const int lb = tid >> 3, a = tid & 7;
        const float* hp = Hf + BT * HD + lb * HD;
        float s = 0.f;
        for (int kk = 0; kk < HD; kk++)
            s = fmaf(hp[kk], sSm[640 + kk * NACT + a], s);
        out[NB + (size_t)(b0 + lb) * NACT + a] = s + sSm[1825 + a];
    }
}

extern "C" void kernel_launch(void* const* d_in, const int* in_sizes, int n_in,
                              void* d_out, int out_size)
{
    (void)in_sizes; (void)n_in; (void)out_size;
    cudaFuncSetAttribute(colight, cudaFuncAttributeMaxDynamicSharedMemorySize, SMEM_BYTES);
    prep_gv<<<512, 128>>>(
        (const float*)d_in[7], (const float*)d_in[9], (const float*)d_in[13]);
    prep_wf<<<(WF_TOTAL + 512 + 255) / 256, 256>>>(
        (const float*)d_in[3], (const float*)d_in[5], (const float*)d_in[7],
        (const float*)d_in[8]);
    colight<<<NB/BT, NTHREADS, SMEM_BYTES>>>(
        (const float*)d_in[0],  (const float*)d_in[1],  (const int*)d_in[2],
        (const float*)d_in[3],  (const float*)d_in[4],  (const float*)d_in[5],
        (const float*)d_in[6],  (const float*)d_in[7],  (const float*)d_in[8],
        (const float*)d_in[9],  (const float*)d_in[10], (const float*)d_in[11],
        (const float*)d_in[12], (const float*)d_in[13], (const float*)d_in[14],
        (const float*)d_in[15], (const float*)d_in[16],
        (float*)d_out);
}